// round 7
// baseline (speedup 1.0000x reference)
#include <cuda_runtime.h>
#include <cuda_fp16.h>
#include <math.h>
#include <stdint.h>

// ---------------- problem constants ----------------
#define NMAX 50000
#define EMAX 800000
#define CIN  256
#define C1C  128
#define C2C  64

// ---------------- device scratch ----------------
__device__ float g_deg[NMAX];
__device__ float g_dinv[NMAX];
__device__ int   g_cnt[NMAX];
__device__ int   g_fill[NMAX];
__device__ int   g_rowptr[NMAX + 1];
__device__ int   g_bsum[64];
__device__ int   g_src[EMAX];
__device__ float g_norm[EMAX];
__device__ float g_h1[NMAX * C1C];
__device__ float g_agg1[NMAX * C1C];
__device__ float g_skip[NMAX * C2C];
__device__ float g_h2[NMAX * C2C];
__device__ float g_agg2[NMAX * C2C];
__device__ float g_bnsum[C1C + C2C];
__device__ float g_bnsq[C1C + C2C];

// fp16 split operands
__device__ __align__(256) __half g_xh[NMAX * CIN];
__device__ __align__(256) __half g_xl[NMAX * CIN];
__device__ __align__(256) __half g_h1h[NMAX * C1C];
__device__ __align__(256) __half g_h1l[NMAX * C1C];
__device__ __align__(256) __half g_wfh[192 * CIN];   // [W1^T ; Ws^T] fused
__device__ __align__(256) __half g_wfl[192 * CIN];
__device__ __align__(256) __half g_w2th[C2C * C1C];
__device__ __align__(256) __half g_w2tl[C2C * C1C];

__device__ __forceinline__ float gelu_f(float v) {
    return 0.5f * v * (1.0f + erff(v * 0.70710678118654752440f));
}

// ---------------- init ----------------
__global__ void k_init(int n) {
    int i = blockIdx.x * blockDim.x + threadIdx.x;
    if (i < n) { g_cnt[i] = 0; g_fill[i] = 0; g_deg[i] = 1.0f; }
    if (i < C1C + C2C) { g_bnsum[i] = 0.0f; g_bnsq[i] = 0.0f; }
}

// ---------------- histogram ----------------
__global__ void k_hist(const int* __restrict__ col, const float* __restrict__ ew, int e) {
    int i = blockIdx.x * blockDim.x + threadIdx.x;
    if (i < e) {
        int c = col[i];
        atomicAdd(&g_cnt[c], 1);
        atomicAdd(&g_deg[c], ew[i]);
    }
}

// ---------------- scan part (+ fused dinv) ----------------
__global__ void k_scan_part(int n) {
    __shared__ int warp_sums[32];
    int tid = threadIdx.x;
    int lane = tid & 31, wid = tid >> 5;
    int i = blockIdx.x * 1024 + tid;
    int v = (i < n) ? g_cnt[i] : 0;
    int x = v;
    #pragma unroll
    for (int o = 1; o < 32; o <<= 1) {
        int y = __shfl_up_sync(0xFFFFFFFFu, x, o);
        if (lane >= o) x += y;
    }
    if (lane == 31) warp_sums[wid] = x;
    __syncthreads();
    if (wid == 0) {
        int w = warp_sums[lane];
        #pragma unroll
        for (int o = 1; o < 32; o <<= 1) {
            int y = __shfl_up_sync(0xFFFFFFFFu, w, o);
            if (lane >= o) w += y;
        }
        warp_sums[lane] = w;
    }
    __syncthreads();
    int inc = x + (wid > 0 ? warp_sums[wid - 1] : 0);
    if (i < n) {
        g_rowptr[i] = inc - v;
        float d = g_deg[i];
        g_dinv[i] = (d > 0.0f) ? rsqrtf(d) : 0.0f;
    }
    if (tid == 1023) g_bsum[blockIdx.x] = inc;
}

__global__ void k_scan_top(int nblk, int n) {
    int tid = threadIdx.x;
    int lane = tid & 31, wid = tid >> 5;
    __shared__ int w0_total;
    int v = (tid < nblk) ? g_bsum[tid] : 0;
    int x = v;
    #pragma unroll
    for (int o = 1; o < 32; o <<= 1) {
        int y = __shfl_up_sync(0xFFFFFFFFu, x, o);
        if (lane >= o) x += y;
    }
    if (wid == 0 && lane == 31) w0_total = x;
    __syncthreads();
    int incl = x + (wid == 1 ? w0_total : 0);
    if (tid < nblk) g_bsum[tid] = incl - v;
    if (tid == nblk - 1) g_rowptr[n] = incl;
}

__global__ void k_scan_add(int n) {
    int i = blockIdx.x * 1024 + threadIdx.x;
    if (i < n) g_rowptr[i] += g_bsum[blockIdx.x];
}

// ---------------- fill CSR ----------------
__global__ void k_fill(const int* __restrict__ row, const int* __restrict__ col,
                       const float* __restrict__ ew, int e) {
    int i = blockIdx.x * blockDim.x + threadIdx.x;
    if (i < e) {
        int c = col[i], r = row[i];
        int pos = g_rowptr[c] + atomicAdd(&g_fill[c], 1);
        g_src[pos] = r;
        g_norm[pos] = g_dinv[r] * ew[i] * g_dinv[c];
    }
}

// ---------------- split fp32 -> (hi,lo) fp16 ----------------
__global__ void k_split_x(const float* __restrict__ x, __half* __restrict__ xh,
                          __half* __restrict__ xl, int total4) {
    int i = blockIdx.x * blockDim.x + threadIdx.x;
    if (i >= total4) return;
    float4 v = ((const float4*)x)[i];
    __half h0 = __float2half_rn(v.x), h1 = __float2half_rn(v.y);
    __half h2 = __float2half_rn(v.z), h3 = __float2half_rn(v.w);
    __half l0 = __float2half_rn(v.x - __half2float(h0));
    __half l1 = __float2half_rn(v.y - __half2float(h1));
    __half l2 = __float2half_rn(v.z - __half2float(h2));
    __half l3 = __float2half_rn(v.w - __half2float(h3));
    __half2* ph = (__half2*)xh;
    __half2* pl = (__half2*)xl;
    ph[i * 2]     = __half2(h0, h1);
    ph[i * 2 + 1] = __half2(h2, h3);
    pl[i * 2]     = __half2(l0, l1);
    pl[i * 2 + 1] = __half2(l2, l3);
}

// ---------------- fused W1+Ws transpose-split ----------------
__global__ void k_split_wf(const float* __restrict__ W1, const float* __restrict__ Ws,
                           __half* __restrict__ Th, __half* __restrict__ Tl) {
    int i = blockIdx.x * blockDim.x + threadIdx.x;
    if (i >= 192 * CIN) return;
    int nn = i / CIN, k = i % CIN;
    float v = (nn < C1C) ? W1[(size_t)k * C1C + nn] : Ws[(size_t)k * C2C + (nn - C1C)];
    __half h = __float2half_rn(v);
    Th[i] = h;
    Tl[i] = __float2half_rn(v - __half2float(h));
}

// ---------------- split + transpose W2 ----------------
__global__ void k_split_wt(const float* __restrict__ W, __half* __restrict__ Th,
                           __half* __restrict__ Tl, int K, int N) {
    int i = blockIdx.x * blockDim.x + threadIdx.x;
    if (i >= K * N) return;
    int k = i / N, nn = i % N;
    float v = W[i];
    __half h = __float2half_rn(v);
    Th[(size_t)nn * K + k] = h;
    Tl[(size_t)nn * K + k] = __float2half_rn(v - __half2float(h));
}

// ---------------- BN1 apply + GELU + split to fp16 pair ----------------
__global__ void k_split_h1(const float* __restrict__ a, __half* __restrict__ hh,
                           __half* __restrict__ hl,
                           const float* __restrict__ g1, const float* __restrict__ be1,
                           int n) {
    __shared__ float sS[C1C], sB[C1C];
    int tid = threadIdx.x;
    if (tid < C1C) {
        float inv = 1.0f / (float)n;
        float mu = g_bnsum[tid] * inv;
        float var = g_bnsq[tid] * inv - mu * mu;
        float sc = g1[tid] * rsqrtf(var + 1e-5f);
        sS[tid] = sc;
        sB[tid] = be1[tid] - mu * sc;
    }
    __syncthreads();
    int i = blockIdx.x * blockDim.x + tid;
    if (i >= n * C1C) return;
    int c = i & (C1C - 1);
    float v = gelu_f(fmaf(a[i], sS[c], sB[c]));
    __half h = __float2half_rn(v);
    hh[i] = h;
    hl[i] = __float2half_rn(v - __half2float(h));
}

// ---------------- mma.sync GEMM, cp.async double-buffered, BK=32 ----------------
__device__ __forceinline__ void ldsm4(uint32_t* r, uint32_t addr) {
    asm volatile("ldmatrix.sync.aligned.m8n8.x4.shared.b16 {%0,%1,%2,%3}, [%4];"
                 : "=r"(r[0]), "=r"(r[1]), "=r"(r[2]), "=r"(r[3]) : "r"(addr));
}
__device__ __forceinline__ void mma16816(float* d, const uint32_t* a,
                                         uint32_t b0, uint32_t b1) {
    asm volatile(
        "mma.sync.aligned.m16n8k16.row.col.f32.f16.f16.f32 "
        "{%0,%1,%2,%3}, {%4,%5,%6,%7}, {%8,%9}, {%0,%1,%2,%3};"
        : "+f"(d[0]), "+f"(d[1]), "+f"(d[2]), "+f"(d[3])
        : "r"(a[0]), "r"(a[1]), "r"(a[2]), "r"(a[3]), "r"(b0), "r"(b1));
}
__device__ __forceinline__ void cp16(uint32_t dst, const void* src, int srcsize) {
    asm volatile("cp.async.cg.shared.global [%0], [%1], 16, %2;"
                 :: "r"(dst), "l"(src), "r"(srcsize) : "memory");
}
#define CP_COMMIT() asm volatile("cp.async.commit_group;" ::: "memory")
#define CP_WAIT1()  asm volatile("cp.async.wait_group 1;" ::: "memory")
#define CP_WAIT0()  asm volatile("cp.async.wait_group 0;" ::: "memory")

// BM rows per CTA. Warps: WM along M (32 rows each, so BM = 32*WM), WN along N.
// MODE 0: C1[M,BN] (+bias). MODE 1: cols<128 -> C1[M,128]; cols>=128 -> C2+bias.
template<int BM, int BN, int WM, int WN, int MODE>
__global__ __launch_bounds__(32 * WM * WN) void k_gemm_mma(
    const __half* __restrict__ Ah, const __half* __restrict__ Al,
    const __half* __restrict__ Bh, const __half* __restrict__ Bl,
    float* __restrict__ C1, float* __restrict__ C2,
    const float* __restrict__ bias, int M, int K) {
    constexpr int BK = 32;
    constexpr int SA = 40;               // 32 halves + 8 pad (ldsm conflict-free)
    constexpr int THREADS = 32 * WM * WN;
    constexpr int WNW = BN / WN;
    constexpr int NT = WNW / 8;
    constexpr int AHALF = BM * SA;
    constexpr int BHALF = BN * SA;
    constexpr int PERBUF = 2 * AHALF + 2 * BHALF;
    extern __shared__ __half smh[];
    const uint32_t su = (uint32_t)__cvta_generic_to_shared(smh);

    const int tid = threadIdx.x;
    const int w = tid >> 5, lane = tid & 31;
    const int mw = (w % WM) * 32;
    const int nw = (w / WM) * WNW;
    const int m0 = blockIdx.x * BM;
    const int g = lane >> 3, l8 = lane & 7;

    float acc[2][NT][4];
    #pragma unroll
    for (int i = 0; i < 2; i++)
        #pragma unroll
        for (int j = 0; j < NT; j++)
            #pragma unroll
            for (int q = 0; q < 4; q++) acc[i][j][q] = 0.0f;

    auto stage = [&](int chunk, int buf) {
        const int kc = chunk * BK;
        const uint32_t b0 = su + buf * PERBUF * 2;
        // A: 2 parts * BM rows * 4 x 16B
        #pragma unroll
        for (int it = 0; it < (2 * BM * 4 + THREADS - 1) / THREADS; it++) {
            int slot = tid + it * THREADS;
            if (slot < 2 * BM * 4) {
                int part = slot >= BM * 4;
                int idx = part ? slot - BM * 4 : slot;
                int row = idx >> 2, kk = idx & 3;
                int gm = m0 + row;
                const __half* sp = (part ? Al : Ah) +
                                   (size_t)(gm < M ? gm : 0) * K + kc + kk * 8;
                uint32_t dst = b0 + (uint32_t)(part * AHALF + row * SA + kk * 8) * 2;
                cp16(dst, sp, gm < M ? 16 : 0);
            }
        }
        // B: 2 parts * BN rows * 4 x 16B
        #pragma unroll
        for (int it = 0; it < (2 * BN * 4 + THREADS - 1) / THREADS; it++) {
            int slot = tid + it * THREADS;
            if (slot < 2 * BN * 4) {
                int part = slot >= BN * 4;
                int idx = part ? slot - BN * 4 : slot;
                int row = idx >> 2, kk = idx & 3;
                const __half* sp = (part ? Bl : Bh) + (size_t)row * K + kc + kk * 8;
                uint32_t dst = b0 + (uint32_t)(2 * AHALF + part * BHALF +
                                               row * SA + kk * 8) * 2;
                cp16(dst, sp, 16);
            }
        }
        CP_COMMIT();
    };

    const int nchunks = K / BK;
    stage(0, 0);
    for (int c = 0; c < nchunks; c++) {
        const int buf = c & 1;
        if (c + 1 < nchunks) { stage(c + 1, buf ^ 1); CP_WAIT1(); }
        else                 { CP_WAIT0(); }
        __syncthreads();
        const uint32_t b0 = su + buf * PERBUF * 2;
        const uint32_t cAh = b0, cAl = b0 + AHALF * 2;
        const uint32_t cBh = b0 + 2 * AHALF * 2, cBl = cBh + BHALF * 2;
        #pragma unroll
        for (int ks = 0; ks < 2; ks++) {
            const int kb = ks * 16;
            uint32_t ah[2][4], al[2][4];
            #pragma unroll
            for (int mt = 0; mt < 2; mt++) {
                int arow = mw + mt * 16 + l8 + (g & 1) * 8;
                int acol = kb + (g >> 1) * 8;
                uint32_t off = (uint32_t)(arow * SA + acol) * 2;
                ldsm4(ah[mt], cAh + off);
                ldsm4(al[mt], cAl + off);
            }
            #pragma unroll
            for (int p = 0; p < NT / 2; p++) {
                int brow = nw + p * 16 + l8 + (g >> 1) * 8;
                int bcol = kb + (g & 1) * 8;
                uint32_t off = (uint32_t)(brow * SA + bcol) * 2;
                uint32_t bh[4], bl[4];
                ldsm4(bh, cBh + off);
                ldsm4(bl, cBl + off);
                #pragma unroll
                for (int sub = 0; sub < 2; sub++) {
                    int nt = p * 2 + sub;
                    #pragma unroll
                    for (int mt = 0; mt < 2; mt++) {
                        mma16816(acc[mt][nt], ah[mt], bh[2 * sub], bh[2 * sub + 1]);
                        mma16816(acc[mt][nt], ah[mt], bl[2 * sub], bl[2 * sub + 1]);
                        mma16816(acc[mt][nt], al[mt], bh[2 * sub], bh[2 * sub + 1]);
                    }
                }
            }
        }
        __syncthreads();
    }

    // epilogue
    const int gid = lane >> 2, qid = lane & 3;
    #pragma unroll
    for (int mt = 0; mt < 2; mt++) {
        int r0 = m0 + mw + mt * 16 + gid;
        #pragma unroll
        for (int nt = 0; nt < NT; nt++) {
            int col = nw + nt * 8 + qid * 2;
            #pragma unroll
            for (int half = 0; half < 2; half++) {
                int r = r0 + half * 8;
                if (r >= M) continue;
                float v0 = acc[mt][nt][half * 2 + 0];
                float v1 = acc[mt][nt][half * 2 + 1];
                if (MODE == 0) {
                    if (bias) { v0 += bias[col]; v1 += bias[col + 1]; }
                    *(float2*)&C1[(size_t)r * BN + col] = make_float2(v0, v1);
                } else {
                    if (col < 128) {
                        *(float2*)&C1[(size_t)r * 128 + col] = make_float2(v0, v1);
                    } else {
                        int c2 = col - 128;
                        v0 += bias[c2]; v1 += bias[c2 + 1];
                        *(float2*)&C2[(size_t)r * (BN - 128) + c2] = make_float2(v0, v1);
                    }
                }
            }
        }
    }
}

// ---------------- aggregation + fused BN stats ----------------
__global__ void k_agg128(const float* __restrict__ h, float* __restrict__ out, int n) {
    __shared__ float s_sum[C1C], s_sq[C1C];
    int tid = threadIdx.x, lane = tid & 31, wid = tid >> 5;
    if (tid < C1C) { s_sum[tid] = 0.f; s_sq[tid] = 0.f; }
    __syncthreads();
    const float4* hv = (const float4*)h;
    float4 lsum = make_float4(0.f, 0.f, 0.f, 0.f);
    float4 lsq  = make_float4(0.f, 0.f, 0.f, 0.f);
    int base = (blockIdx.x * 8 + wid) * 8;
    #pragma unroll 1
    for (int g = 0; g < 8; g++) {
        int w = base + g;
        if (w >= n) break;
        float di = g_dinv[w];
        float s = di * di;
        float4 a = hv[(size_t)w * 32 + lane];
        float4 acc;
        acc.x = a.x * s; acc.y = a.y * s; acc.z = a.z * s; acc.w = a.w * s;
        int beg = g_rowptr[w], end = g_rowptr[w + 1];
        int e = beg;
        for (; e + 3 < end; e += 4) {
            int s0 = g_src[e], s1 = g_src[e + 1], s2 = g_src[e + 2], s3 = g_src[e + 3];
            float w0 = g_norm[e], w1 = g_norm[e + 1], w2 = g_norm[e + 2], w3 = g_norm[e + 3];
            float4 v0 = hv[(size_t)s0 * 32 + lane];
            float4 v1 = hv[(size_t)s1 * 32 + lane];
            float4 v2 = hv[(size_t)s2 * 32 + lane];
            float4 v3 = hv[(size_t)s3 * 32 + lane];
            acc.x += w0 * v0.x + w1 * v1.x + w2 * v2.x + w3 * v3.x;
            acc.y += w0 * v0.y + w1 * v1.y + w2 * v2.y + w3 * v3.y;
            acc.z += w0 * v0.z + w1 * v1.z + w2 * v2.z + w3 * v3.z;
            acc.w += w0 * v0.w + w1 * v1.w + w2 * v2.w + w3 * v3.w;
        }
        for (; e < end; e++) {
            int src = g_src[e];
            float wt = g_norm[e];
            float4 v = hv[(size_t)src * 32 + lane];
            acc.x += wt * v.x; acc.y += wt * v.y;
            acc.z += wt * v.z; acc.w += wt * v.w;
        }
        ((float4*)out)[(size_t)w * 32 + lane] = acc;
        lsum.x += acc.x; lsum.y += acc.y; lsum.z += acc.z; lsum.w += acc.w;
        lsq.x += acc.x * acc.x; lsq.y += acc.y * acc.y;
        lsq.z += acc.z * acc.z; lsq.w += acc.w * acc.w;
    }
    int c = lane * 4;
    atomicAdd(&s_sum[c + 0], lsum.x); atomicAdd(&s_sum[c + 1], lsum.y);
    atomicAdd(&s_sum[c + 2], lsum.z); atomicAdd(&s_sum[c + 3], lsum.w);
    atomicAdd(&s_sq[c + 0], lsq.x);  atomicAdd(&s_sq[c + 1], lsq.y);
    atomicAdd(&s_sq[c + 2], lsq.z);  atomicAdd(&s_sq[c + 3], lsq.w);
    __syncthreads();
    if (tid < C1C) {
        atomicAdd(&g_bnsum[tid], s_sum[tid]);
        atomicAdd(&g_bnsq[tid], s_sq[tid]);
    }
}

__global__ void k_agg64(const float* __restrict__ h, float* __restrict__ out, int n) {
    __shared__ float s_sum[C2C], s_sq[C2C];
    int tid = threadIdx.x, lane = tid & 31, wid = tid >> 5;
    if (tid < C2C) { s_sum[tid] = 0.f; s_sq[tid] = 0.f; }
    __syncthreads();
    const float2* hv = (const float2*)h;
    float2 lsum = make_float2(0.f, 0.f);
    float2 lsq  = make_float2(0.f, 0.f);
    int base = (blockIdx.x * 8 + wid) * 8;
    #pragma unroll 1
    for (int g = 0; g < 8; g++) {
        int w = base + g;
        if (w >= n) break;
        float di = g_dinv[w];
        float s = di * di;
        float2 a = hv[(size_t)w * 32 + lane];
        float2 acc;
        acc.x = a.x * s; acc.y = a.y * s;
        int beg = g_rowptr[w], end = g_rowptr[w + 1];
        int e = beg;
        for (; e + 3 < end; e += 4) {
            int s0 = g_src[e], s1 = g_src[e + 1], s2 = g_src[e + 2], s3 = g_src[e + 3];
            float w0 = g_norm[e], w1 = g_norm[e + 1], w2 = g_norm[e + 2], w3 = g_norm[e + 3];
            float2 v0 = hv[(size_t)s0 * 32 + lane];
            float2 v1 = hv[(size_t)s1 * 32 + lane];
            float2 v2 = hv[(size_t)s2 * 32 + lane];
            float2 v3 = hv[(size_t)s3 * 32 + lane];
            acc.x += w0 * v0.x + w1 * v1.x + w2 * v2.x + w3 * v3.x;
            acc.y += w0 * v0.y + w1 * v1.y + w2 * v2.y + w3 * v3.y;
        }
        for (; e < end; e++) {
            int src = g_src[e];
            float wt = g_norm[e];
            float2 v = hv[(size_t)src * 32 + lane];
            acc.x += wt * v.x; acc.y += wt * v.y;
        }
        ((float2*)out)[(size_t)w * 32 + lane] = acc;
        lsum.x += acc.x; lsum.y += acc.y;
        lsq.x += acc.x * acc.x; lsq.y += acc.y * acc.y;
    }
    int c = lane * 2;
    atomicAdd(&s_sum[c + 0], lsum.x); atomicAdd(&s_sum[c + 1], lsum.y);
    atomicAdd(&s_sq[c + 0], lsq.x);  atomicAdd(&s_sq[c + 1], lsq.y);
    __syncthreads();
    if (tid < C2C) {
        atomicAdd(&g_bnsum[C1C + tid], s_sum[tid]);
        atomicAdd(&g_bnsq[C1C + tid], s_sq[tid]);
    }
}

// ---------------- final BN2 + skip ----------------
__global__ void k_bn2(const float* __restrict__ a, float* __restrict__ o,
                      const float* __restrict__ gamma, const float* __restrict__ beta,
                      int n, const float* __restrict__ skip) {
    int i = blockIdx.x * blockDim.x + threadIdx.x;
    if (i >= n * C2C) return;
    int c = i & (C2C - 1);
    float inv_n = 1.0f / (float)n;
    float mu = g_bnsum[C1C + c] * inv_n;
    float var = g_bnsq[C1C + c] * inv_n - mu * mu;
    float v = (a[i] - mu) * rsqrtf(var + 1e-5f) * gamma[c] + beta[c];
    o[i] = v + skip[i];
}

// ---------------- launcher ----------------
extern "C" void kernel_launch(void* const* d_in, const int* in_sizes, int n_in,
                              void* d_out, int out_size) {
    const float* x   = (const float*)d_in[0];
    const int*   ei  = (const int*)d_in[1];
    const float* ew  = (const float*)d_in[2];
    const float* W1  = (const float*)d_in[3];
    const float* W2  = (const float*)d_in[5];
    const float* g1  = (const float*)d_in[7];
    const float* be1 = (const float*)d_in[8];
    const float* g2  = (const float*)d_in[9];
    const float* be2 = (const float*)d_in[10];
    const float* Ws  = (const float*)d_in[11];
    const float* bs  = (const float*)d_in[12];
    float* out = (float*)d_out;

    int E = in_sizes[2];
    int n = in_sizes[0] / CIN;
    const int* rowp = ei;
    const int* colp = ei + E;

    float *p_h1, *p_agg1, *p_skip, *p_h2, *p_agg2;
    cudaGetSymbolAddress((void**)&p_h1,   g_h1);
    cudaGetSymbolAddress((void**)&p_agg1, g_agg1);
    cudaGetSymbolAddress((void**)&p_skip, g_skip);
    cudaGetSymbolAddress((void**)&p_h2,   g_h2);
    cudaGetSymbolAddress((void**)&p_agg2, g_agg2);
    __half *p_xh, *p_xl, *p_h1h, *p_h1l, *p_wfh, *p_wfl, *p_w2th, *p_w2tl;
    cudaGetSymbolAddress((void**)&p_xh,   g_xh);
    cudaGetSymbolAddress((void**)&p_xl,   g_xl);
    cudaGetSymbolAddress((void**)&p_h1h,  g_h1h);
    cudaGetSymbolAddress((void**)&p_h1l,  g_h1l);
    cudaGetSymbolAddress((void**)&p_wfh,  g_wfh);
    cudaGetSymbolAddress((void**)&p_wfl,  g_wfl);
    cudaGetSymbolAddress((void**)&p_w2th, g_w2th);
    cudaGetSymbolAddress((void**)&p_w2tl, g_w2tl);

    // smem: 2 stages * 2*(BM+BN) rows * 40 halves * 2B
    const int SMEMF = 2 * 2 * (64 + 192) * 40 * 2;  // 81920
    const int SMEM2 = 2 * 2 * (64 + 64) * 40 * 2;   // 40960
    cudaFuncSetAttribute((const void*)k_gemm_mma<64, 192, 2, 4, 1>,
                         cudaFuncAttributeMaxDynamicSharedMemorySize, SMEMF);
    cudaFuncSetAttribute((const void*)k_gemm_mma<64, 64, 2, 4, 0>,
                         cudaFuncAttributeMaxDynamicSharedMemorySize, SMEM2);

    int nb = (n + 255) / 256;
    int eb = (E + 255) / 256;
    int sblk = (n + 1023) / 1024;
    int mtiles = (n + 63) / 64;

    // 1-3: operand prep (graph-independent)
    k_split_x<<<(n * CIN / 4 + 255) / 256, 256>>>(x, p_xh, p_xl, n * CIN / 4);
    k_split_wf<<<(192 * CIN + 255) / 256, 256>>>(W1, Ws, p_wfh, p_wfl);
    k_init<<<nb, 256>>>(n);

    // 4: fused GEMM1+skip — ncu capture slot
    k_gemm_mma<64, 192, 2, 4, 1><<<mtiles, 256, SMEMF>>>(p_xh, p_xl, p_wfh, p_wfl,
                                                         p_h1, p_skip, bs, n, CIN);

    // 5-9: CSR build
    k_hist<<<eb, 256>>>(colp, ew, E);
    k_scan_part<<<sblk, 1024>>>(n);
    k_scan_top<<<1, 64>>>(sblk, n);
    k_scan_add<<<sblk, 1024>>>(n);
    k_fill<<<eb, 256>>>(rowp, colp, ew, E);

    // 10: conv1 aggregation (+BN1 stats fused)
    int aggb = (n + 63) / 64;
    k_agg128<<<aggb, 256>>>(p_h1, p_agg1, n);

    // 11-13: BN1+GELU+split, then GEMM2
    k_split_wt<<<(C1C * C2C + 255) / 256, 256>>>(W2, p_w2th, p_w2tl, C1C, C2C);
    k_split_h1<<<(n * C1C + 255) / 256, 256>>>(p_agg1, p_h1h, p_h1l, g1, be1, n);
    k_gemm_mma<64, 64, 2, 4, 0><<<mtiles, 256, SMEM2>>>(p_h1h, p_h1l, p_w2th, p_w2tl,
                                                        p_h2, nullptr, nullptr, n, C1C);

    // 14: conv2 aggregation (+BN2 stats fused)
    k_agg64<<<aggb, 256>>>(p_h2, p_agg2, n);

    // 15: BN2 apply + skip add
    k_bn2<<<(n * C2C + 255) / 256, 256>>>(p_agg2, out, g2, be2, n, p_skip);

    (void)n_in; (void)out_size;
}

// round 8
// speedup vs baseline: 1.0001x; 1.0001x over previous
#include <cuda_runtime.h>
#include <cuda_fp16.h>
#include <math.h>
#include <stdint.h>

// ---------------- problem constants ----------------
#define NMAX 50000
#define EMAX 800000
#define CIN  256
#define C1C  128
#define C2C  64

// ---------------- device scratch ----------------
__device__ float g_deg[NMAX];
__device__ float g_dinv[NMAX];
__device__ int   g_cnt[NMAX];
__device__ int   g_fill[NMAX];
__device__ int   g_rowptr[NMAX + 1];
__device__ int   g_bsum[64];
__device__ int   g_src[EMAX];
__device__ float g_norm[EMAX];
__device__ float g_h1[NMAX * C1C];
__device__ float g_agg1[NMAX * C1C];
__device__ float g_skip[NMAX * C2C];
__device__ float g_h2[NMAX * C2C];
__device__ float g_agg2[NMAX * C2C];
__device__ float g_bnsum[C1C + C2C];
__device__ float g_bnsq[C1C + C2C];

// fp16 split operands
__device__ __align__(256) __half g_xh[NMAX * CIN];
__device__ __align__(256) __half g_xl[NMAX * CIN];
__device__ __align__(256) __half g_h1h[NMAX * C1C];
__device__ __align__(256) __half g_h1l[NMAX * C1C];
__device__ __align__(256) __half g_wfh[192 * CIN];   // [W1^T ; Ws^T] fused
__device__ __align__(256) __half g_wfl[192 * CIN];
__device__ __align__(256) __half g_w2th[C2C * C1C];
__device__ __align__(256) __half g_w2tl[C2C * C1C];

__device__ __forceinline__ float gelu_f(float v) {
    return 0.5f * v * (1.0f + erff(v * 0.70710678118654752440f));
}

// ---------------- init ----------------
__global__ void k_init(int n) {
    int i = blockIdx.x * blockDim.x + threadIdx.x;
    if (i < n) { g_cnt[i] = 0; g_fill[i] = 0; g_deg[i] = 1.0f; }
    if (i < C1C + C2C) { g_bnsum[i] = 0.0f; g_bnsq[i] = 0.0f; }
}

// ---------------- histogram ----------------
__global__ void k_hist(const int* __restrict__ col, const float* __restrict__ ew, int e) {
    int i = blockIdx.x * blockDim.x + threadIdx.x;
    if (i < e) {
        int c = col[i];
        atomicAdd(&g_cnt[c], 1);
        atomicAdd(&g_deg[c], ew[i]);
    }
}

// ---------------- scan part (+ fused dinv) ----------------
__global__ void k_scan_part(int n) {
    __shared__ int warp_sums[32];
    int tid = threadIdx.x;
    int lane = tid & 31, wid = tid >> 5;
    int i = blockIdx.x * 1024 + tid;
    int v = (i < n) ? g_cnt[i] : 0;
    int x = v;
    #pragma unroll
    for (int o = 1; o < 32; o <<= 1) {
        int y = __shfl_up_sync(0xFFFFFFFFu, x, o);
        if (lane >= o) x += y;
    }
    if (lane == 31) warp_sums[wid] = x;
    __syncthreads();
    if (wid == 0) {
        int w = warp_sums[lane];
        #pragma unroll
        for (int o = 1; o < 32; o <<= 1) {
            int y = __shfl_up_sync(0xFFFFFFFFu, w, o);
            if (lane >= o) w += y;
        }
        warp_sums[lane] = w;
    }
    __syncthreads();
    int inc = x + (wid > 0 ? warp_sums[wid - 1] : 0);
    if (i < n) {
        g_rowptr[i] = inc - v;
        float d = g_deg[i];
        g_dinv[i] = (d > 0.0f) ? rsqrtf(d) : 0.0f;
    }
    if (tid == 1023) g_bsum[blockIdx.x] = inc;
}

__global__ void k_scan_top(int nblk, int n) {
    int tid = threadIdx.x;
    int lane = tid & 31, wid = tid >> 5;
    __shared__ int w0_total;
    int v = (tid < nblk) ? g_bsum[tid] : 0;
    int x = v;
    #pragma unroll
    for (int o = 1; o < 32; o <<= 1) {
        int y = __shfl_up_sync(0xFFFFFFFFu, x, o);
        if (lane >= o) x += y;
    }
    if (wid == 0 && lane == 31) w0_total = x;
    __syncthreads();
    int incl = x + (wid == 1 ? w0_total : 0);
    if (tid < nblk) g_bsum[tid] = incl - v;
    if (tid == nblk - 1) g_rowptr[n] = incl;
}

__global__ void k_scan_add(int n) {
    int i = blockIdx.x * 1024 + threadIdx.x;
    if (i < n) g_rowptr[i] += g_bsum[blockIdx.x];
}

// ---------------- fill CSR ----------------
__global__ void k_fill(const int* __restrict__ row, const int* __restrict__ col,
                       const float* __restrict__ ew, int e) {
    int i = blockIdx.x * blockDim.x + threadIdx.x;
    if (i < e) {
        int c = col[i], r = row[i];
        int pos = g_rowptr[c] + atomicAdd(&g_fill[c], 1);
        g_src[pos] = r;
        g_norm[pos] = g_dinv[r] * ew[i] * g_dinv[c];
    }
}

// ---------------- split fp32 -> (hi,lo) fp16 ----------------
__global__ void k_split_x(const float* __restrict__ x, __half* __restrict__ xh,
                          __half* __restrict__ xl, int total4) {
    int i = blockIdx.x * blockDim.x + threadIdx.x;
    if (i >= total4) return;
    float4 v = ((const float4*)x)[i];
    __half h0 = __float2half_rn(v.x), h1 = __float2half_rn(v.y);
    __half h2 = __float2half_rn(v.z), h3 = __float2half_rn(v.w);
    __half l0 = __float2half_rn(v.x - __half2float(h0));
    __half l1 = __float2half_rn(v.y - __half2float(h1));
    __half l2 = __float2half_rn(v.z - __half2float(h2));
    __half l3 = __float2half_rn(v.w - __half2float(h3));
    __half2* ph = (__half2*)xh;
    __half2* pl = (__half2*)xl;
    ph[i * 2]     = __half2(h0, h1);
    ph[i * 2 + 1] = __half2(h2, h3);
    pl[i * 2]     = __half2(l0, l1);
    pl[i * 2 + 1] = __half2(l2, l3);
}

// ---------------- fused W1+Ws transpose-split ----------------
__global__ void k_split_wf(const float* __restrict__ W1, const float* __restrict__ Ws,
                           __half* __restrict__ Th, __half* __restrict__ Tl) {
    int i = blockIdx.x * blockDim.x + threadIdx.x;
    if (i >= 192 * CIN) return;
    int nn = i / CIN, k = i % CIN;
    float v = (nn < C1C) ? W1[(size_t)k * C1C + nn] : Ws[(size_t)k * C2C + (nn - C1C)];
    __half h = __float2half_rn(v);
    Th[i] = h;
    Tl[i] = __float2half_rn(v - __half2float(h));
}

// ---------------- split + transpose W2 ----------------
__global__ void k_split_wt(const float* __restrict__ W, __half* __restrict__ Th,
                           __half* __restrict__ Tl, int K, int N) {
    int i = blockIdx.x * blockDim.x + threadIdx.x;
    if (i >= K * N) return;
    int k = i / N, nn = i % N;
    float v = W[i];
    __half h = __float2half_rn(v);
    Th[(size_t)nn * K + k] = h;
    Tl[(size_t)nn * K + k] = __float2half_rn(v - __half2float(h));
}

// ---------------- BN1 apply + GELU + split to fp16 pair ----------------
__global__ void k_split_h1(const float* __restrict__ a, __half* __restrict__ hh,
                           __half* __restrict__ hl,
                           const float* __restrict__ g1, const float* __restrict__ be1,
                           int n) {
    __shared__ float sS[C1C], sB[C1C];
    int tid = threadIdx.x;
    if (tid < C1C) {
        float inv = 1.0f / (float)n;
        float mu = g_bnsum[tid] * inv;
        float var = g_bnsq[tid] * inv - mu * mu;
        float sc = g1[tid] * rsqrtf(var + 1e-5f);
        sS[tid] = sc;
        sB[tid] = be1[tid] - mu * sc;
    }
    __syncthreads();
    int i = blockIdx.x * blockDim.x + tid;
    if (i >= n * C1C) return;
    int c = i & (C1C - 1);
    float v = gelu_f(fmaf(a[i], sS[c], sB[c]));
    __half h = __float2half_rn(v);
    hh[i] = h;
    hl[i] = __float2half_rn(v - __half2float(h));
}

// ---------------- mma.sync GEMM, cp.async double-buffered, BK=32 ----------------
// Term-outer MMA scheduling: all fragments preloaded, then 3 sweeps
// (AhBh, AhBl, AlBh) across all accumulators — reuse distance 2*NT MMAs.
__device__ __forceinline__ void ldsm4(uint32_t* r, uint32_t addr) {
    asm volatile("ldmatrix.sync.aligned.m8n8.x4.shared.b16 {%0,%1,%2,%3}, [%4];"
                 : "=r"(r[0]), "=r"(r[1]), "=r"(r[2]), "=r"(r[3]) : "r"(addr));
}
__device__ __forceinline__ void mma16816(float* d, const uint32_t* a,
                                         uint32_t b0, uint32_t b1) {
    asm volatile(
        "mma.sync.aligned.m16n8k16.row.col.f32.f16.f16.f32 "
        "{%0,%1,%2,%3}, {%4,%5,%6,%7}, {%8,%9}, {%0,%1,%2,%3};"
        : "+f"(d[0]), "+f"(d[1]), "+f"(d[2]), "+f"(d[3])
        : "r"(a[0]), "r"(a[1]), "r"(a[2]), "r"(a[3]), "r"(b0), "r"(b1));
}
__device__ __forceinline__ void cp16(uint32_t dst, const void* src, int srcsize) {
    asm volatile("cp.async.cg.shared.global [%0], [%1], 16, %2;"
                 :: "r"(dst), "l"(src), "r"(srcsize) : "memory");
}
#define CP_COMMIT() asm volatile("cp.async.commit_group;" ::: "memory")
#define CP_WAIT1()  asm volatile("cp.async.wait_group 1;" ::: "memory")
#define CP_WAIT0()  asm volatile("cp.async.wait_group 0;" ::: "memory")

// BM rows per CTA. Warps: WM along M (32 rows each), WN along N.
// MODE 0: C1[M,BN] (+bias). MODE 1: cols<128 -> C1[M,128]; cols>=128 -> C2+bias.
template<int BM, int BN, int WM, int WN, int MODE>
__global__ __launch_bounds__(32 * WM * WN) void k_gemm_mma(
    const __half* __restrict__ Ah, const __half* __restrict__ Al,
    const __half* __restrict__ Bh, const __half* __restrict__ Bl,
    float* __restrict__ C1, float* __restrict__ C2,
    const float* __restrict__ bias, int M, int K) {
    constexpr int BK = 32;
    constexpr int SA = 40;               // 32 halves + 8 pad (ldsm conflict-free)
    constexpr int THREADS = 32 * WM * WN;
    constexpr int WNW = BN / WN;
    constexpr int NT = WNW / 8;
    constexpr int NP = NT / 2;           // 16-wide b-fragment groups
    constexpr int AHALF = BM * SA;
    constexpr int BHALF = BN * SA;
    constexpr int PERBUF = 2 * AHALF + 2 * BHALF;
    extern __shared__ __half smh[];
    const uint32_t su = (uint32_t)__cvta_generic_to_shared(smh);

    const int tid = threadIdx.x;
    const int w = tid >> 5, lane = tid & 31;
    const int mw = (w % WM) * 32;
    const int nw = (w / WM) * WNW;
    const int m0 = blockIdx.x * BM;
    const int g = lane >> 3, l8 = lane & 7;

    float acc[2][NT][4];
    #pragma unroll
    for (int i = 0; i < 2; i++)
        #pragma unroll
        for (int j = 0; j < NT; j++)
            #pragma unroll
            for (int q = 0; q < 4; q++) acc[i][j][q] = 0.0f;

    auto stage = [&](int chunk, int buf) {
        const int kc = chunk * BK;
        const uint32_t b0 = su + buf * PERBUF * 2;
        #pragma unroll
        for (int it = 0; it < (2 * BM * 4 + THREADS - 1) / THREADS; it++) {
            int slot = tid + it * THREADS;
            if (slot < 2 * BM * 4) {
                int part = slot >= BM * 4;
                int idx = part ? slot - BM * 4 : slot;
                int row = idx >> 2, kk = idx & 3;
                int gm = m0 + row;
                const __half* sp = (part ? Al : Ah) +
                                   (size_t)(gm < M ? gm : 0) * K + kc + kk * 8;
                uint32_t dst = b0 + (uint32_t)(part * AHALF + row * SA + kk * 8) * 2;
                cp16(dst, sp, gm < M ? 16 : 0);
            }
        }
        #pragma unroll
        for (int it = 0; it < (2 * BN * 4 + THREADS - 1) / THREADS; it++) {
            int slot = tid + it * THREADS;
            if (slot < 2 * BN * 4) {
                int part = slot >= BN * 4;
                int idx = part ? slot - BN * 4 : slot;
                int row = idx >> 2, kk = idx & 3;
                const __half* sp = (part ? Bl : Bh) + (size_t)row * K + kc + kk * 8;
                uint32_t dst = b0 + (uint32_t)(2 * AHALF + part * BHALF +
                                               row * SA + kk * 8) * 2;
                cp16(dst, sp, 16);
            }
        }
        CP_COMMIT();
    };

    const int nchunks = K / BK;
    stage(0, 0);
    for (int c = 0; c < nchunks; c++) {
        const int buf = c & 1;
        if (c + 1 < nchunks) { stage(c + 1, buf ^ 1); CP_WAIT1(); }
        else                 { CP_WAIT0(); }
        __syncthreads();
        const uint32_t b0 = su + buf * PERBUF * 2;
        const uint32_t cAh = b0, cAl = b0 + AHALF * 2;
        const uint32_t cBh = b0 + 2 * AHALF * 2, cBl = cBh + BHALF * 2;
        #pragma unroll
        for (int ks = 0; ks < 2; ks++) {
            const int kb = ks * 16;
            // preload ALL fragments for this ks
            uint32_t ah[2][4], al[2][4];
            #pragma unroll
            for (int mt = 0; mt < 2; mt++) {
                int arow = mw + mt * 16 + l8 + (g & 1) * 8;
                int acol = kb + (g >> 1) * 8;
                uint32_t off = (uint32_t)(arow * SA + acol) * 2;
                ldsm4(ah[mt], cAh + off);
                ldsm4(al[mt], cAl + off);
            }
            uint32_t bh[NP][4], bl[NP][4];
            #pragma unroll
            for (int p = 0; p < NP; p++) {
                int brow = nw + p * 16 + l8 + (g >> 1) * 8;
                int bcol = kb + (g & 1) * 8;
                uint32_t off = (uint32_t)(brow * SA + bcol) * 2;
                ldsm4(bh[p], cBh + off);
                ldsm4(bl[p], cBl + off);
            }
            // term sweep 1: Ah * Bh — all accumulators independent
            #pragma unroll
            for (int p = 0; p < NP; p++)
                #pragma unroll
                for (int sub = 0; sub < 2; sub++)
                    #pragma unroll
                    for (int mt = 0; mt < 2; mt++)
                        mma16816(acc[mt][p * 2 + sub], ah[mt],
                                 bh[p][2 * sub], bh[p][2 * sub + 1]);
            // term sweep 2: Ah * Bl
            #pragma unroll
            for (int p = 0; p < NP; p++)
                #pragma unroll
                for (int sub = 0; sub < 2; sub++)
                    #pragma unroll
                    for (int mt = 0; mt < 2; mt++)
                        mma16816(acc[mt][p * 2 + sub], ah[mt],
                                 bl[p][2 * sub], bl[p][2 * sub + 1]);
            // term sweep 3: Al * Bh
            #pragma unroll
            for (int p = 0; p < NP; p++)
                #pragma unroll
                for (int sub = 0; sub < 2; sub++)
                    #pragma unroll
                    for (int mt = 0; mt < 2; mt++)
                        mma16816(acc[mt][p * 2 + sub], al[mt],
                                 bh[p][2 * sub], bh[p][2 * sub + 1]);
        }
        __syncthreads();
    }

    // epilogue
    const int gid = lane >> 2, qid = lane & 3;
    #pragma unroll
    for (int mt = 0; mt < 2; mt++) {
        int r0 = m0 + mw + mt * 16 + gid;
        #pragma unroll
        for (int nt = 0; nt < NT; nt++) {
            int col = nw + nt * 8 + qid * 2;
            #pragma unroll
            for (int half = 0; half < 2; half++) {
                int r = r0 + half * 8;
                if (r >= M) continue;
                float v0 = acc[mt][nt][half * 2 + 0];
                float v1 = acc[mt][nt][half * 2 + 1];
                if (MODE == 0) {
                    if (bias) { v0 += bias[col]; v1 += bias[col + 1]; }
                    *(float2*)&C1[(size_t)r * BN + col] = make_float2(v0, v1);
                } else {
                    if (col < 128) {
                        *(float2*)&C1[(size_t)r * 128 + col] = make_float2(v0, v1);
                    } else {
                        int c2 = col - 128;
                        v0 += bias[c2]; v1 += bias[c2 + 1];
                        *(float2*)&C2[(size_t)r * (BN - 128) + c2] = make_float2(v0, v1);
                    }
                }
            }
        }
    }
}

// ---------------- aggregation + fused BN stats ----------------
__global__ void k_agg128(const float* __restrict__ h, float* __restrict__ out, int n) {
    __shared__ float s_sum[C1C], s_sq[C1C];
    int tid = threadIdx.x, lane = tid & 31, wid = tid >> 5;
    if (tid < C1C) { s_sum[tid] = 0.f; s_sq[tid] = 0.f; }
    __syncthreads();
    const float4* hv = (const float4*)h;
    float4 lsum = make_float4(0.f, 0.f, 0.f, 0.f);
    float4 lsq  = make_float4(0.f, 0.f, 0.f, 0.f);
    int base = (blockIdx.x * 8 + wid) * 8;
    #pragma unroll 1
    for (int g = 0; g < 8; g++) {
        int w = base + g;
        if (w >= n) break;
        float di = g_dinv[w];
        float s = di * di;
        float4 a = hv[(size_t)w * 32 + lane];
        float4 acc;
        acc.x = a.x * s; acc.y = a.y * s; acc.z = a.z * s; acc.w = a.w * s;
        int beg = g_rowptr[w], end = g_rowptr[w + 1];
        int e = beg;
        for (; e + 3 < end; e += 4) {
            int s0 = g_src[e], s1 = g_src[e + 1], s2 = g_src[e + 2], s3 = g_src[e + 3];
            float w0 = g_norm[e], w1 = g_norm[e + 1], w2 = g_norm[e + 2], w3 = g_norm[e + 3];
            float4 v0 = hv[(size_t)s0 * 32 + lane];
            float4 v1 = hv[(size_t)s1 * 32 + lane];
            float4 v2 = hv[(size_t)s2 * 32 + lane];
            float4 v3 = hv[(size_t)s3 * 32 + lane];
            acc.x += w0 * v0.x + w1 * v1.x + w2 * v2.x + w3 * v3.x;
            acc.y += w0 * v0.y + w1 * v1.y + w2 * v2.y + w3 * v3.y;
            acc.z += w0 * v0.z + w1 * v1.z + w2 * v2.z + w3 * v3.z;
            acc.w += w0 * v0.w + w1 * v1.w + w2 * v2.w + w3 * v3.w;
        }
        for (; e < end; e++) {
            int src = g_src[e];
            float wt = g_norm[e];
            float4 v = hv[(size_t)src * 32 + lane];
            acc.x += wt * v.x; acc.y += wt * v.y;
            acc.z += wt * v.z; acc.w += wt * v.w;
        }
        ((float4*)out)[(size_t)w * 32 + lane] = acc;
        lsum.x += acc.x; lsum.y += acc.y; lsum.z += acc.z; lsum.w += acc.w;
        lsq.x += acc.x * acc.x; lsq.y += acc.y * acc.y;
        lsq.z += acc.z * acc.z; lsq.w += acc.w * acc.w;
    }
    int c = lane * 4;
    atomicAdd(&s_sum[c + 0], lsum.x); atomicAdd(&s_sum[c + 1], lsum.y);
    atomicAdd(&s_sum[c + 2], lsum.z); atomicAdd(&s_sum[c + 3], lsum.w);
    atomicAdd(&s_sq[c + 0], lsq.x);  atomicAdd(&s_sq[c + 1], lsq.y);
    atomicAdd(&s_sq[c + 2], lsq.z);  atomicAdd(&s_sq[c + 3], lsq.w);
    __syncthreads();
    if (tid < C1C) {
        atomicAdd(&g_bnsum[tid], s_sum[tid]);
        atomicAdd(&g_bnsq[tid], s_sq[tid]);
    }
}

__global__ void k_agg64(const float* __restrict__ h, float* __restrict__ out, int n) {
    __shared__ float s_sum[C2C], s_sq[C2C];
    int tid = threadIdx.x, lane = tid & 31, wid = tid >> 5;
    if (tid < C2C) { s_sum[tid] = 0.f; s_sq[tid] = 0.f; }
    __syncthreads();
    const float2* hv = (const float2*)h;
    float2 lsum = make_float2(0.f, 0.f);
    float2 lsq  = make_float2(0.f, 0.f);
    int base = (blockIdx.x * 8 + wid) * 8;
    #pragma unroll 1
    for (int g = 0; g < 8; g++) {
        int w = base + g;
        if (w >= n) break;
        float di = g_dinv[w];
        float s = di * di;
        float2 a = hv[(size_t)w * 32 + lane];
        float2 acc;
        acc.x = a.x * s; acc.y = a.y * s;
        int beg = g_rowptr[w], end = g_rowptr[w + 1];
        int e = beg;
        for (; e + 3 < end; e += 4) {
            int s0 = g_src[e], s1 = g_src[e + 1], s2 = g_src[e + 2], s3 = g_src[e + 3];
            float w0 = g_norm[e], w1 = g_norm[e + 1], w2 = g_norm[e + 2], w3 = g_norm[e + 3];
            float2 v0 = hv[(size_t)s0 * 32 + lane];
            float2 v1 = hv[(size_t)s1 * 32 + lane];
            float2 v2 = hv[(size_t)s2 * 32 + lane];
            float2 v3 = hv[(size_t)s3 * 32 + lane];
            acc.x += w0 * v0.x + w1 * v1.x + w2 * v2.x + w3 * v3.x;
            acc.y += w0 * v0.y + w1 * v1.y + w2 * v2.y + w3 * v3.y;
        }
        for (; e < end; e++) {
            int src = g_src[e];
            float wt = g_norm[e];
            float2 v = hv[(size_t)src * 32 + lane];
            acc.x += wt * v.x; acc.y += wt * v.y;
        }
        ((float2*)out)[(size_t)w * 32 + lane] = acc;
        lsum.x += acc.x; lsum.y += acc.y;
        lsq.x += acc.x * acc.x; lsq.y += acc.y * acc.y;
    }
    int c = lane * 2;
    atomicAdd(&s_sum[c + 0], lsum.x); atomicAdd(&s_sum[c + 1], lsum.y);
    atomicAdd(&s_sq[c + 0], lsq.x);  atomicAdd(&s_sq[c + 1], lsq.y);
    __syncthreads();
    if (tid < C2C) {
        atomicAdd(&g_bnsum[C1C + tid], s_sum[tid]);
        atomicAdd(&g_bnsq[C1C + tid], s_sq[tid]);
    }
}

// ---------------- final BN2 + skip ----------------
__global__ void k_bn2(const float* __restrict__ a, float* __restrict__ o,
                      const float* __restrict__ gamma, const float* __restrict__ beta,
                      int n, const float* __restrict__ skip) {
    int i = blockIdx.x * blockDim.x + threadIdx.x;
    if (i >= n * C2C) return;
    int c = i & (C2C - 1);
    float inv_n = 1.0f / (float)n;
    float mu = g_bnsum[C1C + c] * inv_n;
    float var = g_bnsq[C1C + c] * inv_n - mu * mu;
    float v = (a[i] - mu) * rsqrtf(var + 1e-5f) * gamma[c] + beta[c];
    o[i] = v + skip[i];
}

// ---------------- launcher ----------------
extern "C" void kernel_launch(void* const* d_in, const int* in_sizes, int n_in,
                              void* d_out, int out_size) {
    const float* x   = (const float*)d_in[0];
    const int*   ei  = (const int*)d_in[1];
    const float* ew  = (const float*)d_in[2];
    const float* W1  = (const float*)d_in[3];
    const float* W2  = (const float*)d_in[5];
    const float* g1  = (const float*)d_in[7];
    const float* be1 = (const float*)d_in[8];
    const float* g2  = (const float*)d_in[9];
    const float* be2 = (const float*)d_in[10];
    const float* Ws  = (const float*)d_in[11];
    const float* bs  = (const float*)d_in[12];
    float* out = (float*)d_out;

    int E = in_sizes[2];
    int n = in_sizes[0] / CIN;
    const int* rowp = ei;
    const int* colp = ei + E;

    float *p_h1, *p_agg1, *p_skip, *p_h2, *p_agg2;
    cudaGetSymbolAddress((void**)&p_h1,   g_h1);
    cudaGetSymbolAddress((void**)&p_agg1, g_agg1);
    cudaGetSymbolAddress((void**)&p_skip, g_skip);
    cudaGetSymbolAddress((void**)&p_h2,   g_h2);
    cudaGetSymbolAddress((void**)&p_agg2, g_agg2);
    __half *p_xh, *p_xl, *p_h1h, *p_h1l, *p_wfh, *p_wfl, *p_w2th, *p_w2tl;
    cudaGetSymbolAddress((void**)&p_xh,   g_xh);
    cudaGetSymbolAddress((void**)&p_xl,   g_xl);
    cudaGetSymbolAddress((void**)&p_h1h,  g_h1h);
    cudaGetSymbolAddress((void**)&p_h1l,  g_h1l);
    cudaGetSymbolAddress((void**)&p_wfh,  g_wfh);
    cudaGetSymbolAddress((void**)&p_wfl,  g_wfl);
    cudaGetSymbolAddress((void**)&p_w2th, g_w2th);
    cudaGetSymbolAddress((void**)&p_w2tl, g_w2tl);

    const int SMEMF = 2 * 2 * (64 + 192) * 40 * 2;  // 81920
    const int SMEM2 = 2 * 2 * (64 + 64) * 40 * 2;   // 40960
    cudaFuncSetAttribute((const void*)k_gemm_mma<64, 192, 2, 4, 1>,
                         cudaFuncAttributeMaxDynamicSharedMemorySize, SMEMF);
    cudaFuncSetAttribute((const void*)k_gemm_mma<64, 64, 2, 4, 0>,
                         cudaFuncAttributeMaxDynamicSharedMemorySize, SMEM2);

    int nb = (n + 255) / 256;
    int eb = (E + 255) / 256;
    int sblk = (n + 1023) / 1024;
    int mtiles = (n + 63) / 64;

    // 1-3: operand prep (graph-independent)
    k_split_x<<<(n * CIN / 4 + 255) / 256, 256>>>(x, p_xh, p_xl, n * CIN / 4);
    k_split_wf<<<(192 * CIN + 255) / 256, 256>>>(W1, Ws, p_wfh, p_wfl);
    k_init<<<nb, 256>>>(n);

    // 4: fused GEMM1+skip — ncu capture slot
    k_gemm_mma<64, 192, 2, 4, 1><<<mtiles, 256, SMEMF>>>(p_xh, p_xl, p_wfh, p_wfl,
                                                         p_h1, p_skip, bs, n, CIN);

    // 5-9: CSR build
    k_hist<<<eb, 256>>>(colp, ew, E);
    k_scan_part<<<sblk, 1024>>>(n);
    k_scan_top<<<1, 64>>>(sblk, n);
    k_scan_add<<<sblk, 1024>>>(n);
    k_fill<<<eb, 256>>>(rowp, colp, ew, E);

    // 10: conv1 aggregation (+BN1 stats fused)
    int aggb = (n + 63) / 64;
    k_agg128<<<aggb, 256>>>(p_h1, p_agg1, n);

    // 11-13: BN1+GELU+split, then GEMM2
    k_split_wt<<<(C1C * C2C + 255) / 256, 256>>>(W2, p_w2th, p_w2tl, C1C, C2C);
    k_split_h1<<<(n * C1C + 255) / 256, 256>>>(p_agg1, p_h1h, p_h1l, g1, be1, n);
    k_gemm_mma<64, 64, 2, 4, 0><<<mtiles, 256, SMEM2>>>(p_h1h, p_h1l, p_w2th, p_w2tl,
                                                        p_h2, nullptr, nullptr, n, C1C);

    // 14: conv2 aggregation (+BN2 stats fused)
    k_agg64<<<aggb, 256>>>(p_h2, p_agg2, n);

    // 15: BN2 apply + skip add
    k_bn2<<<(n * C2C + 255) / 256, 256>>>(p_agg2, out, g2, be2, n, p_skip);

    (void)n_in; (void)out_size;
}

// round 9
// speedup vs baseline: 1.0602x; 1.0600x over previous
#include <cuda_runtime.h>
#include <cuda_fp16.h>
#include <math.h>
#include <stdint.h>

// ---------------- problem constants ----------------
#define NMAX 50000
#define EMAX 800000
#define CIN  256
#define C1C  128
#define C2C  64

// ---------------- device scratch ----------------
__device__ float g_deg[NMAX];
__device__ float g_dinv[NMAX];
__device__ int   g_cnt[NMAX];
__device__ int   g_fill[NMAX];
__device__ int   g_rowptr[NMAX + 1];
__device__ int   g_bsum[64];
__device__ int   g_src[EMAX];
__device__ float g_norm[EMAX];
__device__ float g_h1[NMAX * C1C];
__device__ float g_agg1[NMAX * C1C];
__device__ float g_skip[NMAX * C2C];
__device__ float g_h2[NMAX * C2C];
__device__ float g_agg2[NMAX * C2C];
__device__ float g_bnsum[C1C + C2C];
__device__ float g_bnsq[C1C + C2C];

// fp16 split operands
__device__ __align__(256) __half g_xh[NMAX * CIN];
__device__ __align__(256) __half g_xl[NMAX * CIN];
__device__ __align__(256) __half g_h1h[NMAX * C1C];
__device__ __align__(256) __half g_h1l[NMAX * C1C];
__device__ __align__(256) __half g_wfh[192 * CIN];   // [W1^T ; Ws^T] fused
__device__ __align__(256) __half g_wfl[192 * CIN];
__device__ __align__(256) __half g_w2th[C2C * C1C];
__device__ __align__(256) __half g_w2tl[C2C * C1C];

__device__ __forceinline__ float gelu_f(float v) {
    return 0.5f * v * (1.0f + erff(v * 0.70710678118654752440f));
}

// ---------------- init ----------------
__global__ void k_init(int n) {
    int i = blockIdx.x * blockDim.x + threadIdx.x;
    if (i < n) { g_cnt[i] = 0; g_fill[i] = 0; g_deg[i] = 1.0f; }
    if (i < C1C + C2C) { g_bnsum[i] = 0.0f; g_bnsq[i] = 0.0f; }
}

// ---------------- histogram ----------------
__global__ void k_hist(const int* __restrict__ col, const float* __restrict__ ew, int e) {
    int i = blockIdx.x * blockDim.x + threadIdx.x;
    if (i < e) {
        int c = col[i];
        atomicAdd(&g_cnt[c], 1);
        atomicAdd(&g_deg[c], ew[i]);
    }
}

// ---------------- scan part (+ fused dinv) ----------------
__global__ void k_scan_part(int n) {
    __shared__ int warp_sums[32];
    int tid = threadIdx.x;
    int lane = tid & 31, wid = tid >> 5;
    int i = blockIdx.x * 1024 + tid;
    int v = (i < n) ? g_cnt[i] : 0;
    int x = v;
    #pragma unroll
    for (int o = 1; o < 32; o <<= 1) {
        int y = __shfl_up_sync(0xFFFFFFFFu, x, o);
        if (lane >= o) x += y;
    }
    if (lane == 31) warp_sums[wid] = x;
    __syncthreads();
    if (wid == 0) {
        int w = warp_sums[lane];
        #pragma unroll
        for (int o = 1; o < 32; o <<= 1) {
            int y = __shfl_up_sync(0xFFFFFFFFu, w, o);
            if (lane >= o) w += y;
        }
        warp_sums[lane] = w;
    }
    __syncthreads();
    int inc = x + (wid > 0 ? warp_sums[wid - 1] : 0);
    if (i < n) {
        g_rowptr[i] = inc - v;
        float d = g_deg[i];
        g_dinv[i] = (d > 0.0f) ? rsqrtf(d) : 0.0f;
    }
    if (tid == 1023) g_bsum[blockIdx.x] = inc;
}

__global__ void k_scan_top(int nblk, int n) {
    int tid = threadIdx.x;
    int lane = tid & 31, wid = tid >> 5;
    __shared__ int w0_total;
    int v = (tid < nblk) ? g_bsum[tid] : 0;
    int x = v;
    #pragma unroll
    for (int o = 1; o < 32; o <<= 1) {
        int y = __shfl_up_sync(0xFFFFFFFFu, x, o);
        if (lane >= o) x += y;
    }
    if (wid == 0 && lane == 31) w0_total = x;
    __syncthreads();
    int incl = x + (wid == 1 ? w0_total : 0);
    if (tid < nblk) g_bsum[tid] = incl - v;
    if (tid == nblk - 1) g_rowptr[n] = incl;
}

__global__ void k_scan_add(int n) {
    int i = blockIdx.x * 1024 + threadIdx.x;
    if (i < n) g_rowptr[i] += g_bsum[blockIdx.x];
}

// ---------------- fill CSR ----------------
__global__ void k_fill(const int* __restrict__ row, const int* __restrict__ col,
                       const float* __restrict__ ew, int e) {
    int i = blockIdx.x * blockDim.x + threadIdx.x;
    if (i < e) {
        int c = col[i], r = row[i];
        int pos = g_rowptr[c] + atomicAdd(&g_fill[c], 1);
        g_src[pos] = r;
        g_norm[pos] = g_dinv[r] * ew[i] * g_dinv[c];
    }
}

// ---------------- split fp32 -> (hi,lo) fp16 ----------------
__global__ void k_split_x(const float* __restrict__ x, __half* __restrict__ xh,
                          __half* __restrict__ xl, int total4) {
    int i = blockIdx.x * blockDim.x + threadIdx.x;
    if (i >= total4) return;
    float4 v = ((const float4*)x)[i];
    __half h0 = __float2half_rn(v.x), h1 = __float2half_rn(v.y);
    __half h2 = __float2half_rn(v.z), h3 = __float2half_rn(v.w);
    __half l0 = __float2half_rn(v.x - __half2float(h0));
    __half l1 = __float2half_rn(v.y - __half2float(h1));
    __half l2 = __float2half_rn(v.z - __half2float(h2));
    __half l3 = __float2half_rn(v.w - __half2float(h3));
    __half2* ph = (__half2*)xh;
    __half2* pl = (__half2*)xl;
    ph[i * 2]     = __half2(h0, h1);
    ph[i * 2 + 1] = __half2(h2, h3);
    pl[i * 2]     = __half2(l0, l1);
    pl[i * 2 + 1] = __half2(l2, l3);
}

// ---------------- fused W1+Ws transpose-split ----------------
__global__ void k_split_wf(const float* __restrict__ W1, const float* __restrict__ Ws,
                           __half* __restrict__ Th, __half* __restrict__ Tl) {
    int i = blockIdx.x * blockDim.x + threadIdx.x;
    if (i >= 192 * CIN) return;
    int nn = i / CIN, k = i % CIN;
    float v = (nn < C1C) ? W1[(size_t)k * C1C + nn] : Ws[(size_t)k * C2C + (nn - C1C)];
    __half h = __float2half_rn(v);
    Th[i] = h;
    Tl[i] = __float2half_rn(v - __half2float(h));
}

// ---------------- split + transpose W2 ----------------
__global__ void k_split_wt(const float* __restrict__ W, __half* __restrict__ Th,
                           __half* __restrict__ Tl, int K, int N) {
    int i = blockIdx.x * blockDim.x + threadIdx.x;
    if (i >= K * N) return;
    int k = i / N, nn = i % N;
    float v = W[i];
    __half h = __float2half_rn(v);
    Th[(size_t)nn * K + k] = h;
    Tl[(size_t)nn * K + k] = __float2half_rn(v - __half2float(h));
}

// ---------------- BN1 apply + GELU + split to fp16 pair ----------------
__global__ void k_split_h1(const float* __restrict__ a, __half* __restrict__ hh,
                           __half* __restrict__ hl,
                           const float* __restrict__ g1, const float* __restrict__ be1,
                           int n) {
    __shared__ float sS[C1C], sB[C1C];
    int tid = threadIdx.x;
    if (tid < C1C) {
        float inv = 1.0f / (float)n;
        float mu = g_bnsum[tid] * inv;
        float var = g_bnsq[tid] * inv - mu * mu;
        float sc = g1[tid] * rsqrtf(var + 1e-5f);
        sS[tid] = sc;
        sB[tid] = be1[tid] - mu * sc;
    }
    __syncthreads();
    int i = blockIdx.x * blockDim.x + tid;
    if (i >= n * C1C) return;
    int c = i & (C1C - 1);
    float v = gelu_f(fmaf(a[i], sS[c], sB[c]));
    __half h = __float2half_rn(v);
    hh[i] = h;
    hl[i] = __float2half_rn(v - __half2float(h));
}

// ---------------- mma.sync GEMM, cp.async double-buffered, BK=32 ----------------
__device__ __forceinline__ void ldsm4(uint32_t* r, uint32_t addr) {
    asm volatile("ldmatrix.sync.aligned.m8n8.x4.shared.b16 {%0,%1,%2,%3}, [%4];"
                 : "=r"(r[0]), "=r"(r[1]), "=r"(r[2]), "=r"(r[3]) : "r"(addr));
}
__device__ __forceinline__ void mma16816(float* d, const uint32_t* a,
                                         uint32_t b0, uint32_t b1) {
    asm volatile(
        "mma.sync.aligned.m16n8k16.row.col.f32.f16.f16.f32 "
        "{%0,%1,%2,%3}, {%4,%5,%6,%7}, {%8,%9}, {%0,%1,%2,%3};"
        : "+f"(d[0]), "+f"(d[1]), "+f"(d[2]), "+f"(d[3])
        : "r"(a[0]), "r"(a[1]), "r"(a[2]), "r"(a[3]), "r"(b0), "r"(b1));
}
__device__ __forceinline__ void cp16(uint32_t dst, const void* src, int srcsize) {
    asm volatile("cp.async.cg.shared.global [%0], [%1], 16, %2;"
                 :: "r"(dst), "l"(src), "r"(srcsize) : "memory");
}
#define CP_COMMIT() asm volatile("cp.async.commit_group;" ::: "memory")
#define CP_WAIT1()  asm volatile("cp.async.wait_group 1;" ::: "memory")
#define CP_WAIT0()  asm volatile("cp.async.wait_group 0;" ::: "memory")

template<int BM, int BN, int WM, int WN, int MODE>
__global__ __launch_bounds__(32 * WM * WN) void k_gemm_mma(
    const __half* __restrict__ Ah, const __half* __restrict__ Al,
    const __half* __restrict__ Bh, const __half* __restrict__ Bl,
    float* __restrict__ C1, float* __restrict__ C2,
    const float* __restrict__ bias, int M, int K) {
    constexpr int BK = 32;
    constexpr int SA = 40;
    constexpr int THREADS = 32 * WM * WN;
    constexpr int WNW = BN / WN;
    constexpr int NT = WNW / 8;
    constexpr int NP = NT / 2;
    constexpr int AHALF = BM * SA;
    constexpr int BHALF = BN * SA;
    constexpr int PERBUF = 2 * AHALF + 2 * BHALF;
    extern __shared__ __half smh[];
    const uint32_t su = (uint32_t)__cvta_generic_to_shared(smh);

    const int tid = threadIdx.x;
    const int w = tid >> 5, lane = tid & 31;
    const int mw = (w % WM) * 32;
    const int nw = (w / WM) * WNW;
    const int m0 = blockIdx.x * BM;
    const int g = lane >> 3, l8 = lane & 7;

    float acc[2][NT][4];
    #pragma unroll
    for (int i = 0; i < 2; i++)
        #pragma unroll
        for (int j = 0; j < NT; j++)
            #pragma unroll
            for (int q = 0; q < 4; q++) acc[i][j][q] = 0.0f;

    auto stage = [&](int chunk, int buf) {
        const int kc = chunk * BK;
        const uint32_t b0 = su + buf * PERBUF * 2;
        #pragma unroll
        for (int it = 0; it < (2 * BM * 4 + THREADS - 1) / THREADS; it++) {
            int slot = tid + it * THREADS;
            if (slot < 2 * BM * 4) {
                int part = slot >= BM * 4;
                int idx = part ? slot - BM * 4 : slot;
                int row = idx >> 2, kk = idx & 3;
                int gm = m0 + row;
                const __half* sp = (part ? Al : Ah) +
                                   (size_t)(gm < M ? gm : 0) * K + kc + kk * 8;
                uint32_t dst = b0 + (uint32_t)(part * AHALF + row * SA + kk * 8) * 2;
                cp16(dst, sp, gm < M ? 16 : 0);
            }
        }
        #pragma unroll
        for (int it = 0; it < (2 * BN * 4 + THREADS - 1) / THREADS; it++) {
            int slot = tid + it * THREADS;
            if (slot < 2 * BN * 4) {
                int part = slot >= BN * 4;
                int idx = part ? slot - BN * 4 : slot;
                int row = idx >> 2, kk = idx & 3;
                const __half* sp = (part ? Bl : Bh) + (size_t)row * K + kc + kk * 8;
                uint32_t dst = b0 + (uint32_t)(2 * AHALF + part * BHALF +
                                               row * SA + kk * 8) * 2;
                cp16(dst, sp, 16);
            }
        }
        CP_COMMIT();
    };

    const int nchunks = K / BK;
    stage(0, 0);
    for (int c = 0; c < nchunks; c++) {
        const int buf = c & 1;
        if (c + 1 < nchunks) { stage(c + 1, buf ^ 1); CP_WAIT1(); }
        else                 { CP_WAIT0(); }
        __syncthreads();
        const uint32_t b0 = su + buf * PERBUF * 2;
        const uint32_t cAh = b0, cAl = b0 + AHALF * 2;
        const uint32_t cBh = b0 + 2 * AHALF * 2, cBl = cBh + BHALF * 2;
        #pragma unroll
        for (int ks = 0; ks < 2; ks++) {
            const int kb = ks * 16;
            uint32_t ah[2][4], al[2][4];
            #pragma unroll
            for (int mt = 0; mt < 2; mt++) {
                int arow = mw + mt * 16 + l8 + (g & 1) * 8;
                int acol = kb + (g >> 1) * 8;
                uint32_t off = (uint32_t)(arow * SA + acol) * 2;
                ldsm4(ah[mt], cAh + off);
                ldsm4(al[mt], cAl + off);
            }
            uint32_t bh[NP][4], bl[NP][4];
            #pragma unroll
            for (int p = 0; p < NP; p++) {
                int brow = nw + p * 16 + l8 + (g >> 1) * 8;
                int bcol = kb + (g & 1) * 8;
                uint32_t off = (uint32_t)(brow * SA + bcol) * 2;
                ldsm4(bh[p], cBh + off);
                ldsm4(bl[p], cBl + off);
            }
            #pragma unroll
            for (int p = 0; p < NP; p++)
                #pragma unroll
                for (int sub = 0; sub < 2; sub++)
                    #pragma unroll
                    for (int mt = 0; mt < 2; mt++)
                        mma16816(acc[mt][p * 2 + sub], ah[mt],
                                 bh[p][2 * sub], bh[p][2 * sub + 1]);
            #pragma unroll
            for (int p = 0; p < NP; p++)
                #pragma unroll
                for (int sub = 0; sub < 2; sub++)
                    #pragma unroll
                    for (int mt = 0; mt < 2; mt++)
                        mma16816(acc[mt][p * 2 + sub], ah[mt],
                                 bl[p][2 * sub], bl[p][2 * sub + 1]);
            #pragma unroll
            for (int p = 0; p < NP; p++)
                #pragma unroll
                for (int sub = 0; sub < 2; sub++)
                    #pragma unroll
                    for (int mt = 0; mt < 2; mt++)
                        mma16816(acc[mt][p * 2 + sub], al[mt],
                                 bh[p][2 * sub], bh[p][2 * sub + 1]);
        }
        __syncthreads();
    }

    const int gid = lane >> 2, qid = lane & 3;
    #pragma unroll
    for (int mt = 0; mt < 2; mt++) {
        int r0 = m0 + mw + mt * 16 + gid;
        #pragma unroll
        for (int nt = 0; nt < NT; nt++) {
            int col = nw + nt * 8 + qid * 2;
            #pragma unroll
            for (int half = 0; half < 2; half++) {
                int r = r0 + half * 8;
                if (r >= M) continue;
                float v0 = acc[mt][nt][half * 2 + 0];
                float v1 = acc[mt][nt][half * 2 + 1];
                if (MODE == 0) {
                    if (bias) { v0 += bias[col]; v1 += bias[col + 1]; }
                    *(float2*)&C1[(size_t)r * BN + col] = make_float2(v0, v1);
                } else {
                    if (col < 128) {
                        *(float2*)&C1[(size_t)r * 128 + col] = make_float2(v0, v1);
                    } else {
                        int c2 = col - 128;
                        v0 += bias[c2]; v1 += bias[c2 + 1];
                        *(float2*)&C2[(size_t)r * (BN - 128) + c2] = make_float2(v0, v1);
                    }
                }
            }
        }
    }
}

// ---------------- aggregation + fused BN stats ----------------
__global__ void k_agg128(const float* __restrict__ h, float* __restrict__ out, int n) {
    __shared__ float s_sum[C1C], s_sq[C1C];
    int tid = threadIdx.x, lane = tid & 31, wid = tid >> 5;
    if (tid < C1C) { s_sum[tid] = 0.f; s_sq[tid] = 0.f; }
    __syncthreads();
    const float4* hv = (const float4*)h;
    float4 lsum = make_float4(0.f, 0.f, 0.f, 0.f);
    float4 lsq  = make_float4(0.f, 0.f, 0.f, 0.f);
    int base = (blockIdx.x * 8 + wid) * 8;
    #pragma unroll 1
    for (int g = 0; g < 8; g++) {
        int w = base + g;
        if (w >= n) break;
        float di = g_dinv[w];
        float s = di * di;
        float4 a = hv[(size_t)w * 32 + lane];
        float4 acc;
        acc.x = a.x * s; acc.y = a.y * s; acc.z = a.z * s; acc.w = a.w * s;
        int beg = g_rowptr[w], end = g_rowptr[w + 1];
        int e = beg;
        for (; e + 3 < end; e += 4) {
            int s0 = g_src[e], s1 = g_src[e + 1], s2 = g_src[e + 2], s3 = g_src[e + 3];
            float w0 = g_norm[e], w1 = g_norm[e + 1], w2 = g_norm[e + 2], w3 = g_norm[e + 3];
            float4 v0 = hv[(size_t)s0 * 32 + lane];
            float4 v1 = hv[(size_t)s1 * 32 + lane];
            float4 v2 = hv[(size_t)s2 * 32 + lane];
            float4 v3 = hv[(size_t)s3 * 32 + lane];
            acc.x += w0 * v0.x + w1 * v1.x + w2 * v2.x + w3 * v3.x;
            acc.y += w0 * v0.y + w1 * v1.y + w2 * v2.y + w3 * v3.y;
            acc.z += w0 * v0.z + w1 * v1.z + w2 * v2.z + w3 * v3.z;
            acc.w += w0 * v0.w + w1 * v1.w + w2 * v2.w + w3 * v3.w;
        }
        for (; e < end; e++) {
            int src = g_src[e];
            float wt = g_norm[e];
            float4 v = hv[(size_t)src * 32 + lane];
            acc.x += wt * v.x; acc.y += wt * v.y;
            acc.z += wt * v.z; acc.w += wt * v.w;
        }
        ((float4*)out)[(size_t)w * 32 + lane] = acc;
        lsum.x += acc.x; lsum.y += acc.y; lsum.z += acc.z; lsum.w += acc.w;
        lsq.x += acc.x * acc.x; lsq.y += acc.y * acc.y;
        lsq.z += acc.z * acc.z; lsq.w += acc.w * acc.w;
    }
    int c = lane * 4;
    atomicAdd(&s_sum[c + 0], lsum.x); atomicAdd(&s_sum[c + 1], lsum.y);
    atomicAdd(&s_sum[c + 2], lsum.z); atomicAdd(&s_sum[c + 3], lsum.w);
    atomicAdd(&s_sq[c + 0], lsq.x);  atomicAdd(&s_sq[c + 1], lsq.y);
    atomicAdd(&s_sq[c + 2], lsq.z);  atomicAdd(&s_sq[c + 3], lsq.w);
    __syncthreads();
    if (tid < C1C) {
        atomicAdd(&g_bnsum[tid], s_sum[tid]);
        atomicAdd(&g_bnsq[tid], s_sq[tid]);
    }
}

__global__ void k_agg64(const float* __restrict__ h, float* __restrict__ out, int n) {
    __shared__ float s_sum[C2C], s_sq[C2C];
    int tid = threadIdx.x, lane = tid & 31, wid = tid >> 5;
    if (tid < C2C) { s_sum[tid] = 0.f; s_sq[tid] = 0.f; }
    __syncthreads();
    const float2* hv = (const float2*)h;
    float2 lsum = make_float2(0.f, 0.f);
    float2 lsq  = make_float2(0.f, 0.f);
    int base = (blockIdx.x * 8 + wid) * 8;
    #pragma unroll 1
    for (int g = 0; g < 8; g++) {
        int w = base + g;
        if (w >= n) break;
        float di = g_dinv[w];
        float s = di * di;
        float2 a = hv[(size_t)w * 32 + lane];
        float2 acc;
        acc.x = a.x * s; acc.y = a.y * s;
        int beg = g_rowptr[w], end = g_rowptr[w + 1];
        int e = beg;
        for (; e + 3 < end; e += 4) {
            int s0 = g_src[e], s1 = g_src[e + 1], s2 = g_src[e + 2], s3 = g_src[e + 3];
            float w0 = g_norm[e], w1 = g_norm[e + 1], w2 = g_norm[e + 2], w3 = g_norm[e + 3];
            float2 v0 = hv[(size_t)s0 * 32 + lane];
            float2 v1 = hv[(size_t)s1 * 32 + lane];
            float2 v2 = hv[(size_t)s2 * 32 + lane];
            float2 v3 = hv[(size_t)s3 * 32 + lane];
            acc.x += w0 * v0.x + w1 * v1.x + w2 * v2.x + w3 * v3.x;
            acc.y += w0 * v0.y + w1 * v1.y + w2 * v2.y + w3 * v3.y;
        }
        for (; e < end; e++) {
            int src = g_src[e];
            float wt = g_norm[e];
            float2 v = hv[(size_t)src * 32 + lane];
            acc.x += wt * v.x; acc.y += wt * v.y;
        }
        ((float2*)out)[(size_t)w * 32 + lane] = acc;
        lsum.x += acc.x; lsum.y += acc.y;
        lsq.x += acc.x * acc.x; lsq.y += acc.y * acc.y;
    }
    int c = lane * 2;
    atomicAdd(&s_sum[c + 0], lsum.x); atomicAdd(&s_sum[c + 1], lsum.y);
    atomicAdd(&s_sq[c + 0], lsq.x);  atomicAdd(&s_sq[c + 1], lsq.y);
    __syncthreads();
    if (tid < C2C) {
        atomicAdd(&g_bnsum[C1C + tid], s_sum[tid]);
        atomicAdd(&g_bnsq[C1C + tid], s_sq[tid]);
    }
}

// ---------------- final BN2 + skip ----------------
__global__ void k_bn2(const float* __restrict__ a, float* __restrict__ o,
                      const float* __restrict__ gamma, const float* __restrict__ beta,
                      int n, const float* __restrict__ skip) {
    int i = blockIdx.x * blockDim.x + threadIdx.x;
    if (i >= n * C2C) return;
    int c = i & (C2C - 1);
    float inv_n = 1.0f / (float)n;
    float mu = g_bnsum[C1C + c] * inv_n;
    float var = g_bnsq[C1C + c] * inv_n - mu * mu;
    float v = (a[i] - mu) * rsqrtf(var + 1e-5f) * gamma[c] + beta[c];
    o[i] = v + skip[i];
}

// ---------------- launcher: fork CSR build onto a side stream ----------------
extern "C" void kernel_launch(void* const* d_in, const int* in_sizes, int n_in,
                              void* d_out, int out_size) {
    const float* x   = (const float*)d_in[0];
    const int*   ei  = (const int*)d_in[1];
    const float* ew  = (const float*)d_in[2];
    const float* W1  = (const float*)d_in[3];
    const float* W2  = (const float*)d_in[5];
    const float* g1  = (const float*)d_in[7];
    const float* be1 = (const float*)d_in[8];
    const float* g2  = (const float*)d_in[9];
    const float* be2 = (const float*)d_in[10];
    const float* Ws  = (const float*)d_in[11];
    const float* bs  = (const float*)d_in[12];
    float* out = (float*)d_out;

    int E = in_sizes[2];
    int n = in_sizes[0] / CIN;
    const int* rowp = ei;
    const int* colp = ei + E;

    float *p_h1, *p_agg1, *p_skip, *p_h2, *p_agg2;
    cudaGetSymbolAddress((void**)&p_h1,   g_h1);
    cudaGetSymbolAddress((void**)&p_agg1, g_agg1);
    cudaGetSymbolAddress((void**)&p_skip, g_skip);
    cudaGetSymbolAddress((void**)&p_h2,   g_h2);
    cudaGetSymbolAddress((void**)&p_agg2, g_agg2);
    __half *p_xh, *p_xl, *p_h1h, *p_h1l, *p_wfh, *p_wfl, *p_w2th, *p_w2tl;
    cudaGetSymbolAddress((void**)&p_xh,   g_xh);
    cudaGetSymbolAddress((void**)&p_xl,   g_xl);
    cudaGetSymbolAddress((void**)&p_h1h,  g_h1h);
    cudaGetSymbolAddress((void**)&p_h1l,  g_h1l);
    cudaGetSymbolAddress((void**)&p_wfh,  g_wfh);
    cudaGetSymbolAddress((void**)&p_wfl,  g_wfl);
    cudaGetSymbolAddress((void**)&p_w2th, g_w2th);
    cudaGetSymbolAddress((void**)&p_w2tl, g_w2tl);

    const int SMEMF = 2 * 2 * (64 + 192) * 40 * 2;  // 81920
    const int SMEM2 = 2 * 2 * (64 + 64) * 40 * 2;   // 40960
    cudaFuncSetAttribute((const void*)k_gemm_mma<64, 192, 2, 4, 1>,
                         cudaFuncAttributeMaxDynamicSharedMemorySize, SMEMF);
    cudaFuncSetAttribute((const void*)k_gemm_mma<64, 64, 2, 4, 0>,
                         cudaFuncAttributeMaxDynamicSharedMemorySize, SMEM2);

    int nb = (n + 255) / 256;
    int eb = (E + 255) / 256;
    int sblk = (n + 1023) / 1024;
    int mtiles = (n + 63) / 64;
    int aggb = (n + 63) / 64;

    // Side stream + fork/join events. Created fresh each call (kernel_launch
    // runs only a handful of times: correctness + capture). Never destroyed —
    // the captured graph retains the DAG; no device memory is allocated.
    cudaStream_t sB;
    cudaStreamCreate(&sB);
    cudaEvent_t eFork, eJoin;
    cudaEventCreateWithFlags(&eFork, cudaEventDisableTiming);
    cudaEventCreateWithFlags(&eJoin, cudaEventDisableTiming);

    // main stream: operand prep for the fused GEMM
    k_split_x<<<(n * CIN / 4 + 255) / 256, 256>>>(x, p_xh, p_xl, n * CIN / 4);
    k_split_wf<<<(192 * CIN + 255) / 256, 256>>>(W1, Ws, p_wfh, p_wfl);

    // fork: side stream builds the CSR while the GEMM runs
    cudaEventRecord(eFork, 0);
    cudaStreamWaitEvent(sB, eFork, 0);

    k_init<<<nb, 256, 0, sB>>>(n);

    // main stream: fused GEMM1+skip (tensor-bound, ~60us) — overlaps side stream
    k_gemm_mma<64, 192, 2, 4, 1><<<mtiles, 256, SMEMF>>>(p_xh, p_xl, p_wfh, p_wfl,
                                                         p_h1, p_skip, bs, n, CIN);

    // side stream: CSR chain + W2 split (memory/atomic-bound, ~25us)
    k_hist<<<eb, 256, 0, sB>>>(colp, ew, E);
    k_scan_part<<<sblk, 1024, 0, sB>>>(n);
    k_scan_top<<<1, 64, 0, sB>>>(sblk, n);
    k_scan_add<<<sblk, 1024, 0, sB>>>(n);
    k_fill<<<eb, 256, 0, sB>>>(rowp, colp, ew, E);
    k_split_wt<<<(C1C * C2C + 255) / 256, 256, 0, sB>>>(W2, p_w2th, p_w2tl, C1C, C2C);

    // join: main stream waits for CSR before aggregation
    cudaEventRecord(eJoin, sB);
    cudaStreamWaitEvent(0, eJoin, 0);

    // serial tail on main stream
    k_agg128<<<aggb, 256>>>(p_h1, p_agg1, n);
    k_split_h1<<<(n * C1C + 255) / 256, 256>>>(p_agg1, p_h1h, p_h1l, g1, be1, n);
    k_gemm_mma<64, 64, 2, 4, 0><<<mtiles, 256, SMEM2>>>(p_h1h, p_h1l, p_w2th, p_w2tl,
                                                        p_h2, nullptr, nullptr, n, C1C);
    k_agg64<<<aggb, 256>>>(p_h2, p_agg2, n);
    k_bn2<<<(n * C2C + 255) / 256, 256>>>(p_agg2, out, g2, be2, n, p_skip);

    (void)n_in; (void)out_size;
}

// round 11
// speedup vs baseline: 1.2301x; 1.1603x over previous
#include <cuda_runtime.h>
#include <cuda_fp16.h>
#include <math.h>
#include <stdint.h>

// ---------------- problem constants ----------------
#define NMAX 50000
#define EMAX 800000
#define CIN  256
#define C1C  128
#define C2C  64

// ---------------- device scratch ----------------
__device__ float g_deg[NMAX];
__device__ float g_dinv[NMAX];
__device__ int   g_cnt[NMAX];
__device__ int   g_fill[NMAX];
__device__ int   g_rowptr[NMAX + 1];
__device__ int   g_bsum[64];
__device__ int   g_src[EMAX];
__device__ float g_norm[EMAX];
__device__ float g_h1[NMAX * C1C];
__device__ float g_agg1[NMAX * C1C];
__device__ float g_skip[NMAX * C2C];
__device__ float g_h2[NMAX * C2C];
__device__ float g_agg2[NMAX * C2C];
__device__ float g_bnsum[C1C + C2C];
__device__ float g_bnsq[C1C + C2C];

// fp16 split weights
__device__ __align__(256) __half g_wfh[192 * CIN];   // [W1^T ; Ws^T] fused
__device__ __align__(256) __half g_wfl[192 * CIN];
__device__ __align__(256) __half g_w2th[C2C * C1C];
__device__ __align__(256) __half g_w2tl[C2C * C1C];

__device__ __forceinline__ float gelu_f(float v) {
    return 0.5f * v * (1.0f + erff(v * 0.70710678118654752440f));
}

// ---------------- init ----------------
__global__ void k_init(int n) {
    int i = blockIdx.x * blockDim.x + threadIdx.x;
    if (i < n) { g_cnt[i] = 0; g_fill[i] = 0; g_deg[i] = 1.0f; }
    if (i < C1C + C2C) { g_bnsum[i] = 0.0f; g_bnsq[i] = 0.0f; }
}

// ---------------- histogram ----------------
__global__ void k_hist(const int* __restrict__ col, const float* __restrict__ ew, int e) {
    int i = blockIdx.x * blockDim.x + threadIdx.x;
    if (i < e) {
        int c = col[i];
        atomicAdd(&g_cnt[c], 1);
        atomicAdd(&g_deg[c], ew[i]);
    }
}

// ---------------- scan part (+ fused dinv) ----------------
__global__ void k_scan_part(int n) {
    __shared__ int warp_sums[32];
    int tid = threadIdx.x;
    int lane = tid & 31, wid = tid >> 5;
    int i = blockIdx.x * 1024 + tid;
    int v = (i < n) ? g_cnt[i] : 0;
    int x = v;
    #pragma unroll
    for (int o = 1; o < 32; o <<= 1) {
        int y = __shfl_up_sync(0xFFFFFFFFu, x, o);
        if (lane >= o) x += y;
    }
    if (lane == 31) warp_sums[wid] = x;
    __syncthreads();
    if (wid == 0) {
        int w = warp_sums[lane];
        #pragma unroll
        for (int o = 1; o < 32; o <<= 1) {
            int y = __shfl_up_sync(0xFFFFFFFFu, w, o);
            if (lane >= o) w += y;
        }
        warp_sums[lane] = w;
    }
    __syncthreads();
    int inc = x + (wid > 0 ? warp_sums[wid - 1] : 0);
    if (i < n) {
        g_rowptr[i] = inc - v;
        float d = g_deg[i];
        g_dinv[i] = (d > 0.0f) ? rsqrtf(d) : 0.0f;
    }
    if (tid == 1023) g_bsum[blockIdx.x] = inc;
}

__global__ void k_scan_top(int nblk, int n) {
    int tid = threadIdx.x;
    int lane = tid & 31, wid = tid >> 5;
    __shared__ int w0_total;
    int v = (tid < nblk) ? g_bsum[tid] : 0;
    int x = v;
    #pragma unroll
    for (int o = 1; o < 32; o <<= 1) {
        int y = __shfl_up_sync(0xFFFFFFFFu, x, o);
        if (lane >= o) x += y;
    }
    if (wid == 0 && lane == 31) w0_total = x;
    __syncthreads();
    int incl = x + (wid == 1 ? w0_total : 0);
    if (tid < nblk) g_bsum[tid] = incl - v;
    if (tid == nblk - 1) g_rowptr[n] = incl;
}

__global__ void k_scan_add(int n) {
    int i = blockIdx.x * 1024 + threadIdx.x;
    if (i < n) g_rowptr[i] += g_bsum[blockIdx.x];
}

// ---------------- fill CSR ----------------
__global__ void k_fill(const int* __restrict__ row, const int* __restrict__ col,
                       const float* __restrict__ ew, int e) {
    int i = blockIdx.x * blockDim.x + threadIdx.x;
    if (i < e) {
        int c = col[i], r = row[i];
        int pos = g_rowptr[c] + atomicAdd(&g_fill[c], 1);
        g_src[pos] = r;
        g_norm[pos] = g_dinv[r] * ew[i] * g_dinv[c];
    }
}

// ---------------- fused W1+Ws transpose-split ----------------
__global__ void k_split_wf(const float* __restrict__ W1, const float* __restrict__ Ws,
                           __half* __restrict__ Th, __half* __restrict__ Tl) {
    int i = blockIdx.x * blockDim.x + threadIdx.x;
    if (i >= 192 * CIN) return;
    int nn = i / CIN, k = i % CIN;
    float v = (nn < C1C) ? W1[(size_t)k * C1C + nn] : Ws[(size_t)k * C2C + (nn - C1C)];
    __half h = __float2half_rn(v);
    Th[i] = h;
    Tl[i] = __float2half_rn(v - __half2float(h));
}

// ---------------- split + transpose W2 ----------------
__global__ void k_split_wt(const float* __restrict__ W, __half* __restrict__ Th,
                           __half* __restrict__ Tl, int K, int N) {
    int i = blockIdx.x * blockDim.x + threadIdx.x;
    if (i >= K * N) return;
    int k = i / N, nn = i % N;
    float v = W[i];
    __half h = __float2half_rn(v);
    Th[(size_t)nn * K + k] = h;
    Tl[(size_t)nn * K + k] = __float2half_rn(v - __half2float(h));
}

// ---------------- mma.sync GEMM: fp32 A split in-kernel, cp.async B ----------------
__device__ __forceinline__ void ldsm4(uint32_t* r, uint32_t addr) {
    asm volatile("ldmatrix.sync.aligned.m8n8.x4.shared.b16 {%0,%1,%2,%3}, [%4];"
                 : "=r"(r[0]), "=r"(r[1]), "=r"(r[2]), "=r"(r[3]) : "r"(addr));
}
__device__ __forceinline__ void mma16816(float* d, const uint32_t* a,
                                         uint32_t b0, uint32_t b1) {
    asm volatile(
        "mma.sync.aligned.m16n8k16.row.col.f32.f16.f16.f32 "
        "{%0,%1,%2,%3}, {%4,%5,%6,%7}, {%8,%9}, {%0,%1,%2,%3};"
        : "+f"(d[0]), "+f"(d[1]), "+f"(d[2]), "+f"(d[3])
        : "r"(a[0]), "r"(a[1]), "r"(a[2]), "r"(a[3]), "r"(b0), "r"(b1));
}
__device__ __forceinline__ void cp16(uint32_t dst, const void* src, int srcsize) {
    asm volatile("cp.async.cg.shared.global [%0], [%1], 16, %2;"
                 :: "r"(dst), "l"(src), "r"(srcsize) : "memory");
}
#define CP_COMMIT() asm volatile("cp.async.commit_group;" ::: "memory")
#define CP_WAIT0()  asm volatile("cp.async.wait_group 0;" ::: "memory")

__device__ __forceinline__ uint32_t hpack(__half a, __half b) {
    return (uint32_t)__half_as_ushort(a) | ((uint32_t)__half_as_ushort(b) << 16);
}

// A is fp32 [M,K]; split to hi/lo fp16 in-kernel during staging.
// AFP 1: plain split. AFP 2: BN(scale/shift from g_bnsum/g_bnsq[0..K)) + GELU, then split.
// MODE 0: C1[M,BN] (+bias). MODE 1: cols<128 -> C1[M,128]; cols>=128 -> C2+bias.
// BM=64, 256 threads (WM=2 x WN=4 warps).
// Race-free single-barrier pipeline:
//   CP_WAIT0 -> __syncthreads -> issue ldgA/cpB for c+1 -> compute(buf) -> stsA(buf^1)
// (cp.async into buf^1 issued only AFTER the barrier proves all readers of buf^1 done.)
template<int BN, int MODE, int AFP>
__global__ __launch_bounds__(256) void k_gemm_mma(
    const float* __restrict__ A,
    const __half* __restrict__ Bh_, const __half* __restrict__ Bl_,
    float* __restrict__ C1, float* __restrict__ C2,
    const float* __restrict__ bias,
    const float* __restrict__ bnG, const float* __restrict__ bnB,
    int M, int K) {
    constexpr int BM = 64;
    constexpr int BK = 32;
    constexpr int SA = 40;
    constexpr int THREADS = 256;
    constexpr int WM = 2, WN = 4;
    constexpr int WNW = BN / WN;
    constexpr int NT = WNW / 8;
    constexpr int NP = NT / 2;
    constexpr int AHALF = BM * SA;
    constexpr int BHALF = BN * SA;
    constexpr int PERBUF = 2 * AHALF + 2 * BHALF;
    extern __shared__ __half smh[];
    const uint32_t su = (uint32_t)__cvta_generic_to_shared(smh);
    __shared__ float sS[C1C], sBsh[C1C];

    const int tid = threadIdx.x;
    const int w = tid >> 5, lane = tid & 31;
    const int mw = (w % WM) * 32;
    const int nw = (w / WM) * WNW;
    const int m0 = blockIdx.x * BM;
    const int g = lane >> 3, l8 = lane & 7;

    if (AFP == 2) {
        if (tid < K) {
            float inv = 1.0f / (float)M;
            float mu = g_bnsum[tid] * inv;
            float var = g_bnsq[tid] * inv - mu * mu;
            float sc = bnG[tid] * rsqrtf(var + 1e-5f);
            sS[tid] = sc;
            sBsh[tid] = bnB[tid] - mu * sc;
        }
        __syncthreads();
    }

    float acc[2][NT][4];
    #pragma unroll
    for (int i = 0; i < 2; i++)
        #pragma unroll
        for (int j = 0; j < NT; j++)
            #pragma unroll
            for (int q = 0; q < 4; q++) acc[i][j][q] = 0.0f;

    // A staging: one thread = one (row, 8-wide k-group). 64 rows * 4 groups = 256.
    const int arow = tid >> 2;
    const int akk = (tid & 3) * 8;
    const int agm = m0 + arow;
    const float* abase = A + (size_t)(agm < M ? agm : 0) * K + akk;
    float4 ra0, ra1;

    auto ldgA = [&](int chunk) {
        const float* s = abase + chunk * BK;
        ra0 = *(const float4*)s;
        ra1 = *(const float4*)(s + 4);
    };
    auto stsA = [&](int buf, int kc) {
        float v[8] = {ra0.x, ra0.y, ra0.z, ra0.w, ra1.x, ra1.y, ra1.z, ra1.w};
        if (AFP == 2) {
            #pragma unroll
            for (int i = 0; i < 8; i++) {
                int kcol = kc + akk + i;
                v[i] = gelu_f(fmaf(v[i], sS[kcol], sBsh[kcol]));
            }
        }
        __half hh[8], hl[8];
        #pragma unroll
        for (int i = 0; i < 8; i++) {
            hh[i] = __float2half_rn(v[i]);
            hl[i] = __float2half_rn(v[i] - __half2float(hh[i]));
        }
        uint4 uh, ul;
        uh.x = hpack(hh[0], hh[1]); uh.y = hpack(hh[2], hh[3]);
        uh.z = hpack(hh[4], hh[5]); uh.w = hpack(hh[6], hh[7]);
        ul.x = hpack(hl[0], hl[1]); ul.y = hpack(hl[2], hl[3]);
        ul.z = hpack(hl[4], hl[5]); ul.w = hpack(hl[6], hl[7]);
        __half* dst = smh + buf * PERBUF + arow * SA + akk;
        *(uint4*)dst = uh;
        *(uint4*)(dst + AHALF) = ul;
    };
    auto cpB = [&](int chunk, int buf) {
        const int kc = chunk * BK;
        const uint32_t b0 = su + buf * PERBUF * 2;
        #pragma unroll
        for (int it = 0; it < (2 * BN * 4 + THREADS - 1) / THREADS; it++) {
            int slot = tid + it * THREADS;
            if (slot < 2 * BN * 4) {
                int part = slot >= BN * 4;
                int idx = part ? slot - BN * 4 : slot;
                int row = idx >> 2, kk = idx & 3;
                const __half* sp = (part ? Bl_ : Bh_) + (size_t)row * K + kc + kk * 8;
                uint32_t dst = b0 + (uint32_t)(2 * AHALF + part * BHALF +
                                               row * SA + kk * 8) * 2;
                cp16(dst, sp, 16);
            }
        }
        CP_COMMIT();
    };

    const int nchunks = K / BK;
    ldgA(0);
    stsA(0, 0);
    cpB(0, 0);
    for (int c = 0; c < nchunks; c++) {
        const int buf = c & 1;
        const bool more = (c + 1 < nchunks);
        CP_WAIT0();          // B for buf landed (group issued last iteration)
        __syncthreads();     // publishes stsA(buf); all readers of buf^1 done
        if (more) { ldgA(c + 1); cpB(c + 1, buf ^ 1); }  // safe: after barrier
        const uint32_t b0 = su + buf * PERBUF * 2;
        const uint32_t cAh = b0, cAl = b0 + AHALF * 2;
        const uint32_t cBh = b0 + 2 * AHALF * 2, cBl = cBh + BHALF * 2;
        #pragma unroll
        for (int ks = 0; ks < 2; ks++) {
            const int kb = ks * 16;
            uint32_t ah[2][4], al[2][4];
            #pragma unroll
            for (int mt = 0; mt < 2; mt++) {
                int r = mw + mt * 16 + l8 + (g & 1) * 8;
                int col = kb + (g >> 1) * 8;
                uint32_t off = (uint32_t)(r * SA + col) * 2;
                ldsm4(ah[mt], cAh + off);
                ldsm4(al[mt], cAl + off);
            }
            uint32_t bh[NP][4], bl[NP][4];
            #pragma unroll
            for (int p = 0; p < NP; p++) {
                int r = nw + p * 16 + l8 + (g >> 1) * 8;
                int col = kb + (g & 1) * 8;
                uint32_t off = (uint32_t)(r * SA + col) * 2;
                ldsm4(bh[p], cBh + off);
                ldsm4(bl[p], cBl + off);
            }
            #pragma unroll
            for (int p = 0; p < NP; p++)
                #pragma unroll
                for (int sub = 0; sub < 2; sub++)
                    #pragma unroll
                    for (int mt = 0; mt < 2; mt++)
                        mma16816(acc[mt][p * 2 + sub], ah[mt],
                                 bh[p][2 * sub], bh[p][2 * sub + 1]);
            #pragma unroll
            for (int p = 0; p < NP; p++)
                #pragma unroll
                for (int sub = 0; sub < 2; sub++)
                    #pragma unroll
                    for (int mt = 0; mt < 2; mt++)
                        mma16816(acc[mt][p * 2 + sub], ah[mt],
                                 bl[p][2 * sub], bl[p][2 * sub + 1]);
            #pragma unroll
            for (int p = 0; p < NP; p++)
                #pragma unroll
                for (int sub = 0; sub < 2; sub++)
                    #pragma unroll
                    for (int mt = 0; mt < 2; mt++)
                        mma16816(acc[mt][p * 2 + sub], al[mt],
                                 bh[p][2 * sub], bh[p][2 * sub + 1]);
        }
        if (more) stsA(buf ^ 1, (c + 1) * BK);  // published by next top barrier
    }

    const int gid = lane >> 2, qid = lane & 3;
    #pragma unroll
    for (int mt = 0; mt < 2; mt++) {
        int r0 = m0 + mw + mt * 16 + gid;
        #pragma unroll
        for (int nt = 0; nt < NT; nt++) {
            int col = nw + nt * 8 + qid * 2;
            #pragma unroll
            for (int half = 0; half < 2; half++) {
                int r = r0 + half * 8;
                if (r >= M) continue;
                float v0 = acc[mt][nt][half * 2 + 0];
                float v1 = acc[mt][nt][half * 2 + 1];
                if (MODE == 0) {
                    if (bias) { v0 += bias[col]; v1 += bias[col + 1]; }
                    *(float2*)&C1[(size_t)r * BN + col] = make_float2(v0, v1);
                } else {
                    if (col < 128) {
                        *(float2*)&C1[(size_t)r * 128 + col] = make_float2(v0, v1);
                    } else {
                        int c2 = col - 128;
                        v0 += bias[c2]; v1 += bias[c2 + 1];
                        *(float2*)&C2[(size_t)r * (BN - 128) + c2] = make_float2(v0, v1);
                    }
                }
            }
        }
    }
}

// ---------------- aggregation + fused BN stats ----------------
__global__ void k_agg128(const float* __restrict__ h, float* __restrict__ out, int n) {
    __shared__ float s_sum[C1C], s_sq[C1C];
    int tid = threadIdx.x, lane = tid & 31, wid = tid >> 5;
    if (tid < C1C) { s_sum[tid] = 0.f; s_sq[tid] = 0.f; }
    __syncthreads();
    const float4* hv = (const float4*)h;
    float4 lsum = make_float4(0.f, 0.f, 0.f, 0.f);
    float4 lsq  = make_float4(0.f, 0.f, 0.f, 0.f);
    int base = (blockIdx.x * 8 + wid) * 8;
    #pragma unroll 1
    for (int g = 0; g < 8; g++) {
        int w = base + g;
        if (w >= n) break;
        float di = g_dinv[w];
        float s = di * di;
        float4 a = hv[(size_t)w * 32 + lane];
        float4 acc;
        acc.x = a.x * s; acc.y = a.y * s; acc.z = a.z * s; acc.w = a.w * s;
        int beg = g_rowptr[w], end = g_rowptr[w + 1];
        int e = beg;
        for (; e + 3 < end; e += 4) {
            int s0 = g_src[e], s1 = g_src[e + 1], s2 = g_src[e + 2], s3 = g_src[e + 3];
            float w0 = g_norm[e], w1 = g_norm[e + 1], w2 = g_norm[e + 2], w3 = g_norm[e + 3];
            float4 v0 = hv[(size_t)s0 * 32 + lane];
            float4 v1 = hv[(size_t)s1 * 32 + lane];
            float4 v2 = hv[(size_t)s2 * 32 + lane];
            float4 v3 = hv[(size_t)s3 * 32 + lane];
            acc.x += w0 * v0.x + w1 * v1.x + w2 * v2.x + w3 * v3.x;
            acc.y += w0 * v0.y + w1 * v1.y + w2 * v2.y + w3 * v3.y;
            acc.z += w0 * v0.z + w1 * v1.z + w2 * v2.z + w3 * v3.z;
            acc.w += w0 * v0.w + w1 * v1.w + w2 * v2.w + w3 * v3.w;
        }
        for (; e < end; e++) {
            int src = g_src[e];
            float wt = g_norm[e];
            float4 v = hv[(size_t)src * 32 + lane];
            acc.x += wt * v.x; acc.y += wt * v.y;
            acc.z += wt * v.z; acc.w += wt * v.w;
        }
        ((float4*)out)[(size_t)w * 32 + lane] = acc;
        lsum.x += acc.x; lsum.y += acc.y; lsum.z += acc.z; lsum.w += acc.w;
        lsq.x += acc.x * acc.x; lsq.y += acc.y * acc.y;
        lsq.z += acc.z * acc.z; lsq.w += acc.w * acc.w;
    }
    int c = lane * 4;
    atomicAdd(&s_sum[c + 0], lsum.x); atomicAdd(&s_sum[c + 1], lsum.y);
    atomicAdd(&s_sum[c + 2], lsum.z); atomicAdd(&s_sum[c + 3], lsum.w);
    atomicAdd(&s_sq[c + 0], lsq.x);  atomicAdd(&s_sq[c + 1], lsq.y);
    atomicAdd(&s_sq[c + 2], lsq.z);  atomicAdd(&s_sq[c + 3], lsq.w);
    __syncthreads();
    if (tid < C1C) {
        atomicAdd(&g_bnsum[tid], s_sum[tid]);
        atomicAdd(&g_bnsq[tid], s_sq[tid]);
    }
}

__global__ void k_agg64(const float* __restrict__ h, float* __restrict__ out, int n) {
    __shared__ float s_sum[C2C], s_sq[C2C];
    int tid = threadIdx.x, lane = tid & 31, wid = tid >> 5;
    if (tid < C2C) { s_sum[tid] = 0.f; s_sq[tid] = 0.f; }
    __syncthreads();
    const float2* hv = (const float2*)h;
    float2 lsum = make_float2(0.f, 0.f);
    float2 lsq  = make_float2(0.f, 0.f);
    int base = (blockIdx.x * 8 + wid) * 8;
    #pragma unroll 1
    for (int g = 0; g < 8; g++) {
        int w = base + g;
        if (w >= n) break;
        float di = g_dinv[w];
        float s = di * di;
        float2 a = hv[(size_t)w * 32 + lane];
        float2 acc;
        acc.x = a.x * s; acc.y = a.y * s;
        int beg = g_rowptr[w], end = g_rowptr[w + 1];
        int e = beg;
        for (; e + 3 < end; e += 4) {
            int s0 = g_src[e], s1 = g_src[e + 1], s2 = g_src[e + 2], s3 = g_src[e + 3];
            float w0 = g_norm[e], w1 = g_norm[e + 1], w2 = g_norm[e + 2], w3 = g_norm[e + 3];
            float2 v0 = hv[(size_t)s0 * 32 + lane];
            float2 v1 = hv[(size_t)s1 * 32 + lane];
            float2 v2 = hv[(size_t)s2 * 32 + lane];
            float2 v3 = hv[(size_t)s3 * 32 + lane];
            acc.x += w0 * v0.x + w1 * v1.x + w2 * v2.x + w3 * v3.x;
            acc.y += w0 * v0.y + w1 * v1.y + w2 * v2.y + w3 * v3.y;
        }
        for (; e < end; e++) {
            int src = g_src[e];
            float wt = g_norm[e];
            float2 v = hv[(size_t)src * 32 + lane];
            acc.x += wt * v.x; acc.y += wt * v.y;
        }
        ((float2*)out)[(size_t)w * 32 + lane] = acc;
        lsum.x += acc.x; lsum.y += acc.y;
        lsq.x += acc.x * acc.x; lsq.y += acc.y * acc.y;
    }
    int c = lane * 2;
    atomicAdd(&s_sum[c + 0], lsum.x); atomicAdd(&s_sum[c + 1], lsum.y);
    atomicAdd(&s_sq[c + 0], lsq.x);  atomicAdd(&s_sq[c + 1], lsq.y);
    __syncthreads();
    if (tid < C2C) {
        atomicAdd(&g_bnsum[C1C + tid], s_sum[tid]);
        atomicAdd(&g_bnsq[C1C + tid], s_sq[tid]);
    }
}

// ---------------- final BN2 + skip ----------------
__global__ void k_bn2(const float* __restrict__ a, float* __restrict__ o,
                      const float* __restrict__ gamma, const float* __restrict__ beta,
                      int n, const float* __restrict__ skip) {
    int i = blockIdx.x * blockDim.x + threadIdx.x;
    if (i >= n * C2C) return;
    int c = i & (C2C - 1);
    float inv_n = 1.0f / (float)n;
    float mu = g_bnsum[C1C + c] * inv_n;
    float var = g_bnsq[C1C + c] * inv_n - mu * mu;
    float v = (a[i] - mu) * rsqrtf(var + 1e-5f) * gamma[c] + beta[c];
    o[i] = v + skip[i];
}

// ---------------- launcher ----------------
extern "C" void kernel_launch(void* const* d_in, const int* in_sizes, int n_in,
                              void* d_out, int out_size) {
    const float* x   = (const float*)d_in[0];
    const int*   ei  = (const int*)d_in[1];
    const float* ew  = (const float*)d_in[2];
    const float* W1  = (const float*)d_in[3];
    const float* W2  = (const float*)d_in[5];
    const float* g1  = (const float*)d_in[7];
    const float* be1 = (const float*)d_in[8];
    const float* g2  = (const float*)d_in[9];
    const float* be2 = (const float*)d_in[10];
    const float* Ws  = (const float*)d_in[11];
    const float* bs  = (const float*)d_in[12];
    float* out = (float*)d_out;

    int E = in_sizes[2];
    int n = in_sizes[0] / CIN;
    const int* rowp = ei;
    const int* colp = ei + E;

    float *p_h1, *p_agg1, *p_skip, *p_h2, *p_agg2;
    cudaGetSymbolAddress((void**)&p_h1,   g_h1);
    cudaGetSymbolAddress((void**)&p_agg1, g_agg1);
    cudaGetSymbolAddress((void**)&p_skip, g_skip);
    cudaGetSymbolAddress((void**)&p_h2,   g_h2);
    cudaGetSymbolAddress((void**)&p_agg2, g_agg2);
    __half *p_wfh, *p_wfl, *p_w2th, *p_w2tl;
    cudaGetSymbolAddress((void**)&p_wfh,  g_wfh);
    cudaGetSymbolAddress((void**)&p_wfl,  g_wfl);
    cudaGetSymbolAddress((void**)&p_w2th, g_w2th);
    cudaGetSymbolAddress((void**)&p_w2tl, g_w2tl);

    const int SMEMF = 2 * 2 * (64 + 192) * 40 * 2;  // 81920
    const int SMEM2 = 2 * 2 * (64 + 64) * 40 * 2;   // 40960
    cudaFuncSetAttribute((const void*)k_gemm_mma<192, 1, 1>,
                         cudaFuncAttributeMaxDynamicSharedMemorySize, SMEMF);
    cudaFuncSetAttribute((const void*)k_gemm_mma<64, 0, 2>,
                         cudaFuncAttributeMaxDynamicSharedMemorySize, SMEM2);

    int nb = (n + 255) / 256;
    int eb = (E + 255) / 256;
    int sblk = (n + 1023) / 1024;
    int mtiles = (n + 63) / 64;
    int aggb = (n + 63) / 64;

    // Side stream + fork/join (created fresh per call; never destroyed —
    // kernel_launch runs only a handful of times; no device memory involved).
    cudaStream_t sB;
    cudaStreamCreate(&sB);
    cudaEvent_t eFork, eJoin;
    cudaEventCreateWithFlags(&eFork, cudaEventDisableTiming);
    cudaEventCreateWithFlags(&eJoin, cudaEventDisableTiming);

    // fork immediately: side stream is input-only until the join
    cudaEventRecord(eFork, 0);
    cudaStreamWaitEvent(sB, eFork, 0);

    // 1: main weight prep; 2-3: side CSR start
    k_split_wf<<<(192 * CIN + 255) / 256, 256>>>(W1, Ws, p_wfh, p_wfl);
    k_init<<<nb, 256, 0, sB>>>(n);
    k_hist<<<eb, 256, 0, sB>>>(colp, ew, E);

    // 4: fused GEMM1+skip, x split in-kernel — ncu capture slot
    k_gemm_mma<192, 1, 1><<<mtiles, 256, SMEMF>>>(x, p_wfh, p_wfl,
                                                  p_h1, p_skip, bs,
                                                  nullptr, nullptr, n, CIN);

    // side: finish CSR + W2 split (overlaps GEMM)
    k_scan_part<<<sblk, 1024, 0, sB>>>(n);
    k_scan_top<<<1, 64, 0, sB>>>(sblk, n);
    k_scan_add<<<sblk, 1024, 0, sB>>>(n);
    k_fill<<<eb, 256, 0, sB>>>(rowp, colp, ew, E);
    k_split_wt<<<(C1C * C2C + 255) / 256, 256, 0, sB>>>(W2, p_w2th, p_w2tl, C1C, C2C);

    // join before aggregation
    cudaEventRecord(eJoin, sB);
    cudaStreamWaitEvent(0, eJoin, 0);

    // serial tail
    k_agg128<<<aggb, 256>>>(p_h1, p_agg1, n);
    k_gemm_mma<64, 0, 2><<<mtiles, 256, SMEM2>>>(p_agg1, p_w2th, p_w2tl,
                                                 p_h2, nullptr, nullptr,
                                                 g1, be1, n, C1C);
    k_agg64<<<aggb, 256>>>(p_h2, p_agg2, n);
    k_bn2<<<(n * C2C + 255) / 256, 256>>>(p_agg2, out, g2, be2, n, p_skip);

    (void)n_in; (void)out_size;
}

// round 12
// speedup vs baseline: 1.3111x; 1.0659x over previous
#include <cuda_runtime.h>
#include <cuda_fp16.h>
#include <math.h>
#include <stdint.h>

// ---------------- problem constants ----------------
#define NMAX 50000
#define EMAX 800000
#define CIN  256
#define C1C  128
#define C2C  64

// ---------------- device scratch ----------------
__device__ float g_deg[NMAX];
__device__ float g_dinv[NMAX];
__device__ int   g_cnt[NMAX];
__device__ int   g_fill[NMAX];
__device__ int   g_rowptr[NMAX + 1];
__device__ int   g_bsum[64];
__device__ int   g_src[EMAX];
__device__ float g_norm[EMAX];
__device__ float g_agg1[NMAX * C1C];
__device__ float g_skip[NMAX * C2C];
__device__ float g_agg2[NMAX * C2C];
__device__ float g_bnsum[C1C + C2C];
__device__ float g_bnsq[C1C + C2C];

// fp16 intermediates (GEMM outputs gathered by aggregation)
__device__ __align__(256) __half g_h1f[NMAX * C1C];
__device__ __align__(256) __half g_h2f[NMAX * C2C];
// fp16 split weights
__device__ __align__(256) __half g_wfh[192 * CIN];   // [W1^T ; Ws^T] fused
__device__ __align__(256) __half g_wfl[192 * CIN];
__device__ __align__(256) __half g_w2th[C2C * C1C];
__device__ __align__(256) __half g_w2tl[C2C * C1C];

__device__ __forceinline__ float gelu_f(float v) {
    return 0.5f * v * (1.0f + erff(v * 0.70710678118654752440f));
}

// ---------------- init ----------------
__global__ void k_init(int n) {
    int i = blockIdx.x * blockDim.x + threadIdx.x;
    if (i < n) { g_cnt[i] = 0; g_fill[i] = 0; g_deg[i] = 1.0f; }
    if (i < C1C + C2C) { g_bnsum[i] = 0.0f; g_bnsq[i] = 0.0f; }
}

// ---------------- histogram ----------------
__global__ void k_hist(const int* __restrict__ col, const float* __restrict__ ew, int e) {
    int i = blockIdx.x * blockDim.x + threadIdx.x;
    if (i < e) {
        int c = col[i];
        atomicAdd(&g_cnt[c], 1);
        atomicAdd(&g_deg[c], ew[i]);
    }
}

// ---------------- scan part (+ fused dinv) ----------------
__global__ void k_scan_part(int n) {
    __shared__ int warp_sums[32];
    int tid = threadIdx.x;
    int lane = tid & 31, wid = tid >> 5;
    int i = blockIdx.x * 1024 + tid;
    int v = (i < n) ? g_cnt[i] : 0;
    int x = v;
    #pragma unroll
    for (int o = 1; o < 32; o <<= 1) {
        int y = __shfl_up_sync(0xFFFFFFFFu, x, o);
        if (lane >= o) x += y;
    }
    if (lane == 31) warp_sums[wid] = x;
    __syncthreads();
    if (wid == 0) {
        int w = warp_sums[lane];
        #pragma unroll
        for (int o = 1; o < 32; o <<= 1) {
            int y = __shfl_up_sync(0xFFFFFFFFu, w, o);
            if (lane >= o) w += y;
        }
        warp_sums[lane] = w;
    }
    __syncthreads();
    int inc = x + (wid > 0 ? warp_sums[wid - 1] : 0);
    if (i < n) {
        g_rowptr[i] = inc - v;
        float d = g_deg[i];
        g_dinv[i] = (d > 0.0f) ? rsqrtf(d) : 0.0f;
    }
    if (tid == 1023) g_bsum[blockIdx.x] = inc;
}

__global__ void k_scan_top(int nblk, int n) {
    int tid = threadIdx.x;
    int lane = tid & 31, wid = tid >> 5;
    __shared__ int w0_total;
    int v = (tid < nblk) ? g_bsum[tid] : 0;
    int x = v;
    #pragma unroll
    for (int o = 1; o < 32; o <<= 1) {
        int y = __shfl_up_sync(0xFFFFFFFFu, x, o);
        if (lane >= o) x += y;
    }
    if (wid == 0 && lane == 31) w0_total = x;
    __syncthreads();
    int incl = x + (wid == 1 ? w0_total : 0);
    if (tid < nblk) g_bsum[tid] = incl - v;
    if (tid == nblk - 1) g_rowptr[n] = incl;
}

__global__ void k_scan_add(int n) {
    int i = blockIdx.x * 1024 + threadIdx.x;
    if (i < n) g_rowptr[i] += g_bsum[blockIdx.x];
}

// ---------------- fill CSR ----------------
__global__ void k_fill(const int* __restrict__ row, const int* __restrict__ col,
                       const float* __restrict__ ew, int e) {
    int i = blockIdx.x * blockDim.x + threadIdx.x;
    if (i < e) {
        int c = col[i], r = row[i];
        int pos = g_rowptr[c] + atomicAdd(&g_fill[c], 1);
        g_src[pos] = r;
        g_norm[pos] = g_dinv[r] * ew[i] * g_dinv[c];
    }
}

// ---------------- fused W1+Ws transpose-split ----------------
__global__ void k_split_wf(const float* __restrict__ W1, const float* __restrict__ Ws,
                           __half* __restrict__ Th, __half* __restrict__ Tl) {
    int i = blockIdx.x * blockDim.x + threadIdx.x;
    if (i >= 192 * CIN) return;
    int nn = i / CIN, k = i % CIN;
    float v = (nn < C1C) ? W1[(size_t)k * C1C + nn] : Ws[(size_t)k * C2C + (nn - C1C)];
    __half h = __float2half_rn(v);
    Th[i] = h;
    Tl[i] = __float2half_rn(v - __half2float(h));
}

// ---------------- split + transpose W2 ----------------
__global__ void k_split_wt(const float* __restrict__ W, __half* __restrict__ Th,
                           __half* __restrict__ Tl, int K, int N) {
    int i = blockIdx.x * blockDim.x + threadIdx.x;
    if (i >= K * N) return;
    int k = i / N, nn = i % N;
    float v = W[i];
    __half h = __float2half_rn(v);
    Th[(size_t)nn * K + k] = h;
    Tl[(size_t)nn * K + k] = __float2half_rn(v - __half2float(h));
}

// ---------------- mma.sync GEMM: fp32 A split in-kernel, fp16 C1 out ----------------
__device__ __forceinline__ void ldsm4(uint32_t* r, uint32_t addr) {
    asm volatile("ldmatrix.sync.aligned.m8n8.x4.shared.b16 {%0,%1,%2,%3}, [%4];"
                 : "=r"(r[0]), "=r"(r[1]), "=r"(r[2]), "=r"(r[3]) : "r"(addr));
}
__device__ __forceinline__ void mma16816(float* d, const uint32_t* a,
                                         uint32_t b0, uint32_t b1) {
    asm volatile(
        "mma.sync.aligned.m16n8k16.row.col.f32.f16.f16.f32 "
        "{%0,%1,%2,%3}, {%4,%5,%6,%7}, {%8,%9}, {%0,%1,%2,%3};"
        : "+f"(d[0]), "+f"(d[1]), "+f"(d[2]), "+f"(d[3])
        : "r"(a[0]), "r"(a[1]), "r"(a[2]), "r"(a[3]), "r"(b0), "r"(b1));
}
__device__ __forceinline__ void cp16(uint32_t dst, const void* src, int srcsize) {
    asm volatile("cp.async.cg.shared.global [%0], [%1], 16, %2;"
                 :: "r"(dst), "l"(src), "r"(srcsize) : "memory");
}
#define CP_COMMIT() asm volatile("cp.async.commit_group;" ::: "memory")
#define CP_WAIT0()  asm volatile("cp.async.wait_group 0;" ::: "memory")

__device__ __forceinline__ uint32_t hpack(__half a, __half b) {
    return (uint32_t)__half_as_ushort(a) | ((uint32_t)__half_as_ushort(b) << 16);
}

// A fp32 [M,K]; split hi/lo fp16 in-kernel.
// AFP 1: plain split. AFP 2: BN(g_bnsum/g_bnsq[0..K)) + GELU, then split.
// MODE 0: all cols -> C1h (fp16). MODE 1: cols<128 -> C1h (fp16, stride 128);
//         cols>=128 -> C2 (fp32) + bias.
// Race-free single-barrier pipeline (see R10 post-mortem).
template<int BN, int MODE, int AFP>
__global__ __launch_bounds__(256) void k_gemm_mma(
    const float* __restrict__ A,
    const __half* __restrict__ Bh_, const __half* __restrict__ Bl_,
    __half* __restrict__ C1h, float* __restrict__ C2,
    const float* __restrict__ bias,
    const float* __restrict__ bnG, const float* __restrict__ bnB,
    int M, int K) {
    constexpr int BM = 64;
    constexpr int BK = 32;
    constexpr int SA = 40;
    constexpr int THREADS = 256;
    constexpr int WM = 2, WN = 4;
    constexpr int WNW = BN / WN;
    constexpr int NT = WNW / 8;
    constexpr int NP = NT / 2;
    constexpr int AHALF = BM * SA;
    constexpr int BHALF = BN * SA;
    constexpr int PERBUF = 2 * AHALF + 2 * BHALF;
    extern __shared__ __half smh[];
    const uint32_t su = (uint32_t)__cvta_generic_to_shared(smh);
    __shared__ float sS[C1C], sBsh[C1C];

    const int tid = threadIdx.x;
    const int w = tid >> 5, lane = tid & 31;
    const int mw = (w % WM) * 32;
    const int nw = (w / WM) * WNW;
    const int m0 = blockIdx.x * BM;
    const int g = lane >> 3, l8 = lane & 7;

    if (AFP == 2) {
        if (tid < K) {
            float inv = 1.0f / (float)M;
            float mu = g_bnsum[tid] * inv;
            float var = g_bnsq[tid] * inv - mu * mu;
            float sc = bnG[tid] * rsqrtf(var + 1e-5f);
            sS[tid] = sc;
            sBsh[tid] = bnB[tid] - mu * sc;
        }
        __syncthreads();
    }

    float acc[2][NT][4];
    #pragma unroll
    for (int i = 0; i < 2; i++)
        #pragma unroll
        for (int j = 0; j < NT; j++)
            #pragma unroll
            for (int q = 0; q < 4; q++) acc[i][j][q] = 0.0f;

    const int arow = tid >> 2;
    const int akk = (tid & 3) * 8;
    const int agm = m0 + arow;
    const float* abase = A + (size_t)(agm < M ? agm : 0) * K + akk;
    float4 ra0, ra1;

    auto ldgA = [&](int chunk) {
        const float* s = abase + chunk * BK;
        ra0 = *(const float4*)s;
        ra1 = *(const float4*)(s + 4);
    };
    auto stsA = [&](int buf, int kc) {
        float v[8] = {ra0.x, ra0.y, ra0.z, ra0.w, ra1.x, ra1.y, ra1.z, ra1.w};
        if (AFP == 2) {
            #pragma unroll
            for (int i = 0; i < 8; i++) {
                int kcol = kc + akk + i;
                v[i] = gelu_f(fmaf(v[i], sS[kcol], sBsh[kcol]));
            }
        }
        __half hh[8], hl[8];
        #pragma unroll
        for (int i = 0; i < 8; i++) {
            hh[i] = __float2half_rn(v[i]);
            hl[i] = __float2half_rn(v[i] - __half2float(hh[i]));
        }
        uint4 uh, ul;
        uh.x = hpack(hh[0], hh[1]); uh.y = hpack(hh[2], hh[3]);
        uh.z = hpack(hh[4], hh[5]); uh.w = hpack(hh[6], hh[7]);
        ul.x = hpack(hl[0], hl[1]); ul.y = hpack(hl[2], hl[3]);
        ul.z = hpack(hl[4], hl[5]); ul.w = hpack(hl[6], hl[7]);
        __half* dst = smh + buf * PERBUF + arow * SA + akk;
        *(uint4*)dst = uh;
        *(uint4*)(dst + AHALF) = ul;
    };
    auto cpB = [&](int chunk, int buf) {
        const int kc = chunk * BK;
        const uint32_t b0 = su + buf * PERBUF * 2;
        #pragma unroll
        for (int it = 0; it < (2 * BN * 4 + THREADS - 1) / THREADS; it++) {
            int slot = tid + it * THREADS;
            if (slot < 2 * BN * 4) {
                int part = slot >= BN * 4;
                int idx = part ? slot - BN * 4 : slot;
                int row = idx >> 2, kk = idx & 3;
                const __half* sp = (part ? Bl_ : Bh_) + (size_t)row * K + kc + kk * 8;
                uint32_t dst = b0 + (uint32_t)(2 * AHALF + part * BHALF +
                                               row * SA + kk * 8) * 2;
                cp16(dst, sp, 16);
            }
        }
        CP_COMMIT();
    };

    const int nchunks = K / BK;
    ldgA(0);
    stsA(0, 0);
    cpB(0, 0);
    for (int c = 0; c < nchunks; c++) {
        const int buf = c & 1;
        const bool more = (c + 1 < nchunks);
        CP_WAIT0();
        __syncthreads();
        if (more) { ldgA(c + 1); cpB(c + 1, buf ^ 1); }
        const uint32_t b0 = su + buf * PERBUF * 2;
        const uint32_t cAh = b0, cAl = b0 + AHALF * 2;
        const uint32_t cBh = b0 + 2 * AHALF * 2, cBl = cBh + BHALF * 2;
        #pragma unroll
        for (int ks = 0; ks < 2; ks++) {
            const int kb = ks * 16;
            uint32_t ah[2][4], al[2][4];
            #pragma unroll
            for (int mt = 0; mt < 2; mt++) {
                int r = mw + mt * 16 + l8 + (g & 1) * 8;
                int col = kb + (g >> 1) * 8;
                uint32_t off = (uint32_t)(r * SA + col) * 2;
                ldsm4(ah[mt], cAh + off);
                ldsm4(al[mt], cAl + off);
            }
            uint32_t bh[NP][4], bl[NP][4];
            #pragma unroll
            for (int p = 0; p < NP; p++) {
                int r = nw + p * 16 + l8 + (g >> 1) * 8;
                int col = kb + (g & 1) * 8;
                uint32_t off = (uint32_t)(r * SA + col) * 2;
                ldsm4(bh[p], cBh + off);
                ldsm4(bl[p], cBl + off);
            }
            #pragma unroll
            for (int p = 0; p < NP; p++)
                #pragma unroll
                for (int sub = 0; sub < 2; sub++)
                    #pragma unroll
                    for (int mt = 0; mt < 2; mt++)
                        mma16816(acc[mt][p * 2 + sub], ah[mt],
                                 bh[p][2 * sub], bh[p][2 * sub + 1]);
            #pragma unroll
            for (int p = 0; p < NP; p++)
                #pragma unroll
                for (int sub = 0; sub < 2; sub++)
                    #pragma unroll
                    for (int mt = 0; mt < 2; mt++)
                        mma16816(acc[mt][p * 2 + sub], ah[mt],
                                 bl[p][2 * sub], bl[p][2 * sub + 1]);
            #pragma unroll
            for (int p = 0; p < NP; p++)
                #pragma unroll
                for (int sub = 0; sub < 2; sub++)
                    #pragma unroll
                    for (int mt = 0; mt < 2; mt++)
                        mma16816(acc[mt][p * 2 + sub], al[mt],
                                 bh[p][2 * sub], bh[p][2 * sub + 1]);
        }
        if (more) stsA(buf ^ 1, (c + 1) * BK);
    }

    const int gid = lane >> 2, qid = lane & 3;
    #pragma unroll
    for (int mt = 0; mt < 2; mt++) {
        int r0 = m0 + mw + mt * 16 + gid;
        #pragma unroll
        for (int nt = 0; nt < NT; nt++) {
            int col = nw + nt * 8 + qid * 2;
            #pragma unroll
            for (int half = 0; half < 2; half++) {
                int r = r0 + half * 8;
                if (r >= M) continue;
                float v0 = acc[mt][nt][half * 2 + 0];
                float v1 = acc[mt][nt][half * 2 + 1];
                if (MODE == 0) {
                    *(__half2*)&C1h[(size_t)r * BN + col] = __floats2half2_rn(v0, v1);
                } else {
                    if (col < 128) {
                        *(__half2*)&C1h[(size_t)r * 128 + col] = __floats2half2_rn(v0, v1);
                    } else {
                        int c2 = col - 128;
                        v0 += bias[c2]; v1 += bias[c2 + 1];
                        *(float2*)&C2[(size_t)r * (BN - 128) + c2] = make_float2(v0, v1);
                    }
                }
            }
        }
    }
}

// ---------------- aggregation (fp16 gather, fp32 accumulate) + BN stats ----------------
__global__ void k_agg128(const __half* __restrict__ h, float* __restrict__ out, int n) {
    __shared__ float s_sum[C1C], s_sq[C1C];
    int tid = threadIdx.x, lane = tid & 31, wid = tid >> 5;
    if (tid < C1C) { s_sum[tid] = 0.f; s_sq[tid] = 0.f; }
    __syncthreads();
    const uint2* hv = (const uint2*)h;   // 4 halves per lane (128ch/32 lanes)
    float4 lsum = make_float4(0.f, 0.f, 0.f, 0.f);
    float4 lsq  = make_float4(0.f, 0.f, 0.f, 0.f);
    int base = (blockIdx.x * 8 + wid) * 8;
    #pragma unroll 1
    for (int g = 0; g < 8; g++) {
        int w = base + g;
        if (w >= n) break;
        float di = g_dinv[w];
        float s = di * di;
        uint2 raw = hv[(size_t)w * 32 + lane];
        __half2 p0 = *(__half2*)&raw.x;
        __half2 p1 = *(__half2*)&raw.y;
        float4 acc;
        acc.x = __low2float(p0) * s;  acc.y = __high2float(p0) * s;
        acc.z = __low2float(p1) * s;  acc.w = __high2float(p1) * s;
        int beg = g_rowptr[w], end = g_rowptr[w + 1];
        int e = beg;
        for (; e + 3 < end; e += 4) {
            int s0 = g_src[e], s1 = g_src[e + 1], s2 = g_src[e + 2], s3 = g_src[e + 3];
            float w0 = g_norm[e], w1 = g_norm[e + 1], w2 = g_norm[e + 2], w3 = g_norm[e + 3];
            uint2 r0 = hv[(size_t)s0 * 32 + lane];
            uint2 r1 = hv[(size_t)s1 * 32 + lane];
            uint2 r2 = hv[(size_t)s2 * 32 + lane];
            uint2 r3 = hv[(size_t)s3 * 32 + lane];
            __half2 a0 = *(__half2*)&r0.x, b0 = *(__half2*)&r0.y;
            __half2 a1 = *(__half2*)&r1.x, b1 = *(__half2*)&r1.y;
            __half2 a2 = *(__half2*)&r2.x, b2 = *(__half2*)&r2.y;
            __half2 a3 = *(__half2*)&r3.x, b3 = *(__half2*)&r3.y;
            acc.x += w0 * __low2float(a0) + w1 * __low2float(a1)
                   + w2 * __low2float(a2) + w3 * __low2float(a3);
            acc.y += w0 * __high2float(a0) + w1 * __high2float(a1)
                   + w2 * __high2float(a2) + w3 * __high2float(a3);
            acc.z += w0 * __low2float(b0) + w1 * __low2float(b1)
                   + w2 * __low2float(b2) + w3 * __low2float(b3);
            acc.w += w0 * __high2float(b0) + w1 * __high2float(b1)
                   + w2 * __high2float(b2) + w3 * __high2float(b3);
        }
        for (; e < end; e++) {
            int src = g_src[e];
            float wt = g_norm[e];
            uint2 r0 = hv[(size_t)src * 32 + lane];
            __half2 a0 = *(__half2*)&r0.x, b0 = *(__half2*)&r0.y;
            acc.x += wt * __low2float(a0);  acc.y += wt * __high2float(a0);
            acc.z += wt * __low2float(b0);  acc.w += wt * __high2float(b0);
        }
        ((float4*)out)[(size_t)w * 32 + lane] = acc;
        lsum.x += acc.x; lsum.y += acc.y; lsum.z += acc.z; lsum.w += acc.w;
        lsq.x += acc.x * acc.x; lsq.y += acc.y * acc.y;
        lsq.z += acc.z * acc.z; lsq.w += acc.w * acc.w;
    }
    int c = lane * 4;
    atomicAdd(&s_sum[c + 0], lsum.x); atomicAdd(&s_sum[c + 1], lsum.y);
    atomicAdd(&s_sum[c + 2], lsum.z); atomicAdd(&s_sum[c + 3], lsum.w);
    atomicAdd(&s_sq[c + 0], lsq.x);  atomicAdd(&s_sq[c + 1], lsq.y);
    atomicAdd(&s_sq[c + 2], lsq.z);  atomicAdd(&s_sq[c + 3], lsq.w);
    __syncthreads();
    if (tid < C1C) {
        atomicAdd(&g_bnsum[tid], s_sum[tid]);
        atomicAdd(&g_bnsq[tid], s_sq[tid]);
    }
}

__global__ void k_agg64(const __half* __restrict__ h, float* __restrict__ out, int n) {
    __shared__ float s_sum[C2C], s_sq[C2C];
    int tid = threadIdx.x, lane = tid & 31, wid = tid >> 5;
    if (tid < C2C) { s_sum[tid] = 0.f; s_sq[tid] = 0.f; }
    __syncthreads();
    const __half2* hv = (const __half2*)h;  // 2 halves per lane (64ch/32 lanes)
    float2 lsum = make_float2(0.f, 0.f);
    float2 lsq  = make_float2(0.f, 0.f);
    int base = (blockIdx.x * 8 + wid) * 8;
    #pragma unroll 1
    for (int g = 0; g < 8; g++) {
        int w = base + g;
        if (w >= n) break;
        float di = g_dinv[w];
        float s = di * di;
        __half2 a = hv[(size_t)w * 32 + lane];
        float2 acc;
        acc.x = __low2float(a) * s; acc.y = __high2float(a) * s;
        int beg = g_rowptr[w], end = g_rowptr[w + 1];
        int e = beg;
        for (; e + 3 < end; e += 4) {
            int s0 = g_src[e], s1 = g_src[e + 1], s2 = g_src[e + 2], s3 = g_src[e + 3];
            float w0 = g_norm[e], w1 = g_norm[e + 1], w2 = g_norm[e + 2], w3 = g_norm[e + 3];
            __half2 v0 = hv[(size_t)s0 * 32 + lane];
            __half2 v1 = hv[(size_t)s1 * 32 + lane];
            __half2 v2 = hv[(size_t)s2 * 32 + lane];
            __half2 v3 = hv[(size_t)s3 * 32 + lane];
            acc.x += w0 * __low2float(v0) + w1 * __low2float(v1)
                   + w2 * __low2float(v2) + w3 * __low2float(v3);
            acc.y += w0 * __high2float(v0) + w1 * __high2float(v1)
                   + w2 * __high2float(v2) + w3 * __high2float(v3);
        }
        for (; e < end; e++) {
            int src = g_src[e];
            float wt = g_norm[e];
            __half2 v = hv[(size_t)src * 32 + lane];
            acc.x += wt * __low2float(v); acc.y += wt * __high2float(v);
        }
        ((float2*)out)[(size_t)w * 32 + lane] = acc;
        lsum.x += acc.x; lsum.y += acc.y;
        lsq.x += acc.x * acc.x; lsq.y += acc.y * acc.y;
    }
    int c = lane * 2;
    atomicAdd(&s_sum[c + 0], lsum.x); atomicAdd(&s_sum[c + 1], lsum.y);
    atomicAdd(&s_sq[c + 0], lsq.x);  atomicAdd(&s_sq[c + 1], lsq.y);
    __syncthreads();
    if (tid < C2C) {
        atomicAdd(&g_bnsum[C1C + tid], s_sum[tid]);
        atomicAdd(&g_bnsq[C1C + tid], s_sq[tid]);
    }
}

// ---------------- final BN2 + skip ----------------
__global__ void k_bn2(const float* __restrict__ a, float* __restrict__ o,
                      const float* __restrict__ gamma, const float* __restrict__ beta,
                      int n, const float* __restrict__ skip) {
    int i = blockIdx.x * blockDim.x + threadIdx.x;
    if (i >= n * C2C) return;
    int c = i & (C2C - 1);
    float inv_n = 1.0f / (float)n;
    float mu = g_bnsum[C1C + c] * inv_n;
    float var = g_bnsq[C1C + c] * inv_n - mu * mu;
    float v = (a[i] - mu) * rsqrtf(var + 1e-5f) * gamma[c] + beta[c];
    o[i] = v + skip[i];
}

// ---------------- launcher ----------------
extern "C" void kernel_launch(void* const* d_in, const int* in_sizes, int n_in,
                              void* d_out, int out_size) {
    const float* x   = (const float*)d_in[0];
    const int*   ei  = (const int*)d_in[1];
    const float* ew  = (const float*)d_in[2];
    const float* W1  = (const float*)d_in[3];
    const float* W2  = (const float*)d_in[5];
    const float* g1  = (const float*)d_in[7];
    const float* be1 = (const float*)d_in[8];
    const float* g2  = (const float*)d_in[9];
    const float* be2 = (const float*)d_in[10];
    const float* Ws  = (const float*)d_in[11];
    const float* bs  = (const float*)d_in[12];
    float* out = (float*)d_out;

    int E = in_sizes[2];
    int n = in_sizes[0] / CIN;
    const int* rowp = ei;
    const int* colp = ei + E;

    float *p_agg1, *p_skip, *p_agg2;
    cudaGetSymbolAddress((void**)&p_agg1, g_agg1);
    cudaGetSymbolAddress((void**)&p_skip, g_skip);
    cudaGetSymbolAddress((void**)&p_agg2, g_agg2);
    __half *p_h1f, *p_h2f, *p_wfh, *p_wfl, *p_w2th, *p_w2tl;
    cudaGetSymbolAddress((void**)&p_h1f,  g_h1f);
    cudaGetSymbolAddress((void**)&p_h2f,  g_h2f);
    cudaGetSymbolAddress((void**)&p_wfh,  g_wfh);
    cudaGetSymbolAddress((void**)&p_wfl,  g_wfl);
    cudaGetSymbolAddress((void**)&p_w2th, g_w2th);
    cudaGetSymbolAddress((void**)&p_w2tl, g_w2tl);

    const int SMEMF = 2 * 2 * (64 + 192) * 40 * 2;  // 81920
    const int SMEM2 = 2 * 2 * (64 + 64) * 40 * 2;   // 40960
    cudaFuncSetAttribute((const void*)k_gemm_mma<192, 1, 1>,
                         cudaFuncAttributeMaxDynamicSharedMemorySize, SMEMF);
    cudaFuncSetAttribute((const void*)k_gemm_mma<64, 0, 2>,
                         cudaFuncAttributeMaxDynamicSharedMemorySize, SMEM2);

    int nb = (n + 255) / 256;
    int eb = (E + 255) / 256;
    int sblk = (n + 1023) / 1024;
    int mtiles = (n + 63) / 64;
    int aggb = (n + 63) / 64;

    // Side stream + fork/join (created fresh per call; never destroyed —
    // kernel_launch runs only a handful of times; no device memory involved).
    cudaStream_t sB;
    cudaStreamCreate(&sB);
    cudaEvent_t eFork, eJoin;
    cudaEventCreateWithFlags(&eFork, cudaEventDisableTiming);
    cudaEventCreateWithFlags(&eJoin, cudaEventDisableTiming);

    cudaEventRecord(eFork, 0);
    cudaStreamWaitEvent(sB, eFork, 0);

    // 1: main weight prep; 2-3: side CSR start
    k_split_wf<<<(192 * CIN + 255) / 256, 256>>>(W1, Ws, p_wfh, p_wfl);
    k_init<<<nb, 256, 0, sB>>>(n);
    k_hist<<<eb, 256, 0, sB>>>(colp, ew, E);

    // 4: fused GEMM1+skip, x split in-kernel, fp16 h1 out — ncu capture slot
    k_gemm_mma<192, 1, 1><<<mtiles, 256, SMEMF>>>(x, p_wfh, p_wfl,
                                                  p_h1f, p_skip, bs,
                                                  nullptr, nullptr, n, CIN);

    // side: finish CSR + W2 split (overlaps GEMM)
    k_scan_part<<<sblk, 1024, 0, sB>>>(n);
    k_scan_top<<<1, 64, 0, sB>>>(sblk, n);
    k_scan_add<<<sblk, 1024, 0, sB>>>(n);
    k_fill<<<eb, 256, 0, sB>>>(rowp, colp, ew, E);
    k_split_wt<<<(C1C * C2C + 255) / 256, 256, 0, sB>>>(W2, p_w2th, p_w2tl, C1C, C2C);

    // join before aggregation
    cudaEventRecord(eJoin, sB);
    cudaStreamWaitEvent(0, eJoin, 0);

    // serial tail
    k_agg128<<<aggb, 256>>>(p_h1f, p_agg1, n);
    k_gemm_mma<64, 0, 2><<<mtiles, 256, SMEM2>>>(p_agg1, p_w2th, p_w2tl,
                                                 p_h2f, nullptr, nullptr,
                                                 g1, be1, n, C1C);
    k_agg64<<<aggb, 256>>>(p_h2f, p_agg2, n);
    k_bn2<<<(n * C2C + 255) / 256, 256>>>(p_agg2, out, g2, be2, n, p_skip);

    (void)n_in; (void)out_size;
}

// round 13
// speedup vs baseline: 1.4421x; 1.0999x over previous
#include <cuda_runtime.h>
#include <cuda_fp16.h>
#include <math.h>
#include <stdint.h>

// ---------------- problem constants ----------------
#define NMAX 50000
#define EMAX 800000
#define CIN  256
#define C1C  128
#define C2C  64

// ---------------- device scratch ----------------
__device__ float g_deg[NMAX];
__device__ float g_dinv[NMAX];
__device__ int   g_cnt[NMAX];
__device__ int   g_fill[NMAX];
__device__ int   g_rowptr[NMAX + 1];
__device__ int   g_bsum[64];
__device__ int   g_src[EMAX];
__device__ float g_norm[EMAX];
__device__ float g_agg1[NMAX * C1C];
__device__ float g_skip[NMAX * C2C];
__device__ float g_agg2[NMAX * C2C];
__device__ float g_bnsum[C1C + C2C];
__device__ float g_bnsq[C1C + C2C];

// fp16 intermediates (GEMM outputs gathered by aggregation)
__device__ __align__(256) __half g_h1f[NMAX * C1C];
__device__ __align__(256) __half g_h2f[NMAX * C2C];
// fp16 weights (plain rn — 2-term split keeps only the x-lo correction)
__device__ __align__(256) __half g_wfh[192 * CIN];   // [W1^T ; Ws^T] fused
__device__ __align__(256) __half g_w2th[C2C * C1C];

__device__ __forceinline__ float gelu_f(float v) {
    return 0.5f * v * (1.0f + erff(v * 0.70710678118654752440f));
}

// ---------------- init ----------------
__global__ void k_init(int n) {
    int i = blockIdx.x * blockDim.x + threadIdx.x;
    if (i < n) { g_cnt[i] = 0; g_fill[i] = 0; g_deg[i] = 1.0f; }
    if (i < C1C + C2C) { g_bnsum[i] = 0.0f; g_bnsq[i] = 0.0f; }
}

// ---------------- histogram ----------------
__global__ void k_hist(const int* __restrict__ col, const float* __restrict__ ew, int e) {
    int i = blockIdx.x * blockDim.x + threadIdx.x;
    if (i < e) {
        int c = col[i];
        atomicAdd(&g_cnt[c], 1);
        atomicAdd(&g_deg[c], ew[i]);
    }
}

// ---------------- scan part (+ fused dinv) ----------------
__global__ void k_scan_part(int n) {
    __shared__ int warp_sums[32];
    int tid = threadIdx.x;
    int lane = tid & 31, wid = tid >> 5;
    int i = blockIdx.x * 1024 + tid;
    int v = (i < n) ? g_cnt[i] : 0;
    int x = v;
    #pragma unroll
    for (int o = 1; o < 32; o <<= 1) {
        int y = __shfl_up_sync(0xFFFFFFFFu, x, o);
        if (lane >= o) x += y;
    }
    if (lane == 31) warp_sums[wid] = x;
    __syncthreads();
    if (wid == 0) {
        int w = warp_sums[lane];
        #pragma unroll
        for (int o = 1; o < 32; o <<= 1) {
            int y = __shfl_up_sync(0xFFFFFFFFu, w, o);
            if (lane >= o) w += y;
        }
        warp_sums[lane] = w;
    }
    __syncthreads();
    int inc = x + (wid > 0 ? warp_sums[wid - 1] : 0);
    if (i < n) {
        g_rowptr[i] = inc - v;
        float d = g_deg[i];
        g_dinv[i] = (d > 0.0f) ? rsqrtf(d) : 0.0f;
    }
    if (tid == 1023) g_bsum[blockIdx.x] = inc;
}

__global__ void k_scan_top(int nblk, int n) {
    int tid = threadIdx.x;
    int lane = tid & 31, wid = tid >> 5;
    __shared__ int w0_total;
    int v = (tid < nblk) ? g_bsum[tid] : 0;
    int x = v;
    #pragma unroll
    for (int o = 1; o < 32; o <<= 1) {
        int y = __shfl_up_sync(0xFFFFFFFFu, x, o);
        if (lane >= o) x += y;
    }
    if (wid == 0 && lane == 31) w0_total = x;
    __syncthreads();
    int incl = x + (wid == 1 ? w0_total : 0);
    if (tid < nblk) g_bsum[tid] = incl - v;
    if (tid == nblk - 1) g_rowptr[n] = incl;
}

__global__ void k_scan_add(int n) {
    int i = blockIdx.x * 1024 + threadIdx.x;
    if (i < n) g_rowptr[i] += g_bsum[blockIdx.x];
}

// ---------------- fill CSR ----------------
__global__ void k_fill(const int* __restrict__ row, const int* __restrict__ col,
                       const float* __restrict__ ew, int e) {
    int i = blockIdx.x * blockDim.x + threadIdx.x;
    if (i < e) {
        int c = col[i], r = row[i];
        int pos = g_rowptr[c] + atomicAdd(&g_fill[c], 1);
        g_src[pos] = r;
        g_norm[pos] = g_dinv[r] * ew[i] * g_dinv[c];
    }
}

// ---------------- fused W1+Ws transpose (fp16 rn) ----------------
__global__ void k_split_wf(const float* __restrict__ W1, const float* __restrict__ Ws,
                           __half* __restrict__ Th) {
    int i = blockIdx.x * blockDim.x + threadIdx.x;
    if (i >= 192 * CIN) return;
    int nn = i / CIN, k = i % CIN;
    float v = (nn < C1C) ? W1[(size_t)k * C1C + nn] : Ws[(size_t)k * C2C + (nn - C1C)];
    Th[i] = __float2half_rn(v);
}

// ---------------- transpose W2 (fp16 rn) ----------------
__global__ void k_split_wt(const float* __restrict__ W, __half* __restrict__ Th,
                           int K, int N) {
    int i = blockIdx.x * blockDim.x + threadIdx.x;
    if (i >= K * N) return;
    int k = i / N, nn = i % N;
    Th[(size_t)nn * K + k] = __float2half_rn(W[i]);
}

// ---------------- mma.sync GEMM: fp32 A split in-kernel, fp16 B, 2-term ----------------
__device__ __forceinline__ void ldsm4(uint32_t* r, uint32_t addr) {
    asm volatile("ldmatrix.sync.aligned.m8n8.x4.shared.b16 {%0,%1,%2,%3}, [%4];"
                 : "=r"(r[0]), "=r"(r[1]), "=r"(r[2]), "=r"(r[3]) : "r"(addr));
}
__device__ __forceinline__ void mma16816(float* d, const uint32_t* a,
                                         uint32_t b0, uint32_t b1) {
    asm volatile(
        "mma.sync.aligned.m16n8k16.row.col.f32.f16.f16.f32 "
        "{%0,%1,%2,%3}, {%4,%5,%6,%7}, {%8,%9}, {%0,%1,%2,%3};"
        : "+f"(d[0]), "+f"(d[1]), "+f"(d[2]), "+f"(d[3])
        : "r"(a[0]), "r"(a[1]), "r"(a[2]), "r"(a[3]), "r"(b0), "r"(b1));
}
__device__ __forceinline__ void cp16(uint32_t dst, const void* src, int srcsize) {
    asm volatile("cp.async.cg.shared.global [%0], [%1], 16, %2;"
                 :: "r"(dst), "l"(src), "r"(srcsize) : "memory");
}
#define CP_COMMIT() asm volatile("cp.async.commit_group;" ::: "memory")
#define CP_WAIT0()  asm volatile("cp.async.wait_group 0;" ::: "memory")

__device__ __forceinline__ uint32_t hpack(__half a, __half b) {
    return (uint32_t)__half_as_ushort(a) | ((uint32_t)__half_as_ushort(b) << 16);
}

// A fp32 [M,K]; split hi/lo fp16 in-kernel. B fp16 [BN,K] (single precision level).
// D = Ah*B + Al*B  (2-term split: exact x, fp16-rounded weights).
// AFP 1: plain split. AFP 2: BN(g_bnsum/g_bnsq[0..K)) + GELU, then split.
// MODE 0: all cols -> C1h (fp16). MODE 1: cols<128 -> C1h (fp16, stride 128);
//         cols>=128 -> C2 (fp32) + bias.
template<int BN, int MODE, int AFP>
__global__ __launch_bounds__(256) void k_gemm_mma(
    const float* __restrict__ A,
    const __half* __restrict__ Bh_,
    __half* __restrict__ C1h, float* __restrict__ C2,
    const float* __restrict__ bias,
    const float* __restrict__ bnG, const float* __restrict__ bnB,
    int M, int K) {
    constexpr int BM = 64;
    constexpr int BK = 32;
    constexpr int SA = 40;
    constexpr int THREADS = 256;
    constexpr int WM = 2, WN = 4;
    constexpr int WNW = BN / WN;
    constexpr int NT = WNW / 8;
    constexpr int NP = NT / 2;
    constexpr int AHALF = BM * SA;
    constexpr int BHALF = BN * SA;
    constexpr int PERBUF = 2 * AHALF + BHALF;
    extern __shared__ __half smh[];
    const uint32_t su = (uint32_t)__cvta_generic_to_shared(smh);
    __shared__ float sS[C1C], sBsh[C1C];

    const int tid = threadIdx.x;
    const int w = tid >> 5, lane = tid & 31;
    const int mw = (w % WM) * 32;
    const int nw = (w / WM) * WNW;
    const int m0 = blockIdx.x * BM;
    const int g = lane >> 3, l8 = lane & 7;

    if (AFP == 2) {
        if (tid < K) {
            float inv = 1.0f / (float)M;
            float mu = g_bnsum[tid] * inv;
            float var = g_bnsq[tid] * inv - mu * mu;
            float sc = bnG[tid] * rsqrtf(var + 1e-5f);
            sS[tid] = sc;
            sBsh[tid] = bnB[tid] - mu * sc;
        }
        __syncthreads();
    }

    float acc[2][NT][4];
    #pragma unroll
    for (int i = 0; i < 2; i++)
        #pragma unroll
        for (int j = 0; j < NT; j++)
            #pragma unroll
            for (int q = 0; q < 4; q++) acc[i][j][q] = 0.0f;

    const int arow = tid >> 2;
    const int akk = (tid & 3) * 8;
    const int agm = m0 + arow;
    const float* abase = A + (size_t)(agm < M ? agm : 0) * K + akk;
    float4 ra0, ra1;

    auto ldgA = [&](int chunk) {
        const float* s = abase + chunk * BK;
        ra0 = *(const float4*)s;
        ra1 = *(const float4*)(s + 4);
    };
    auto stsA = [&](int buf, int kc) {
        float v[8] = {ra0.x, ra0.y, ra0.z, ra0.w, ra1.x, ra1.y, ra1.z, ra1.w};
        if (AFP == 2) {
            #pragma unroll
            for (int i = 0; i < 8; i++) {
                int kcol = kc + akk + i;
                v[i] = gelu_f(fmaf(v[i], sS[kcol], sBsh[kcol]));
            }
        }
        __half hh[8], hl[8];
        #pragma unroll
        for (int i = 0; i < 8; i++) {
            hh[i] = __float2half_rn(v[i]);
            hl[i] = __float2half_rn(v[i] - __half2float(hh[i]));
        }
        uint4 uh, ul;
        uh.x = hpack(hh[0], hh[1]); uh.y = hpack(hh[2], hh[3]);
        uh.z = hpack(hh[4], hh[5]); uh.w = hpack(hh[6], hh[7]);
        ul.x = hpack(hl[0], hl[1]); ul.y = hpack(hl[2], hl[3]);
        ul.z = hpack(hl[4], hl[5]); ul.w = hpack(hl[6], hl[7]);
        __half* dst = smh + buf * PERBUF + arow * SA + akk;
        *(uint4*)dst = uh;
        *(uint4*)(dst + AHALF) = ul;
    };
    auto cpB = [&](int chunk, int buf) {
        const int kc = chunk * BK;
        const uint32_t b0 = su + buf * PERBUF * 2;
        #pragma unroll
        for (int it = 0; it < (BN * 4 + THREADS - 1) / THREADS; it++) {
            int slot = tid + it * THREADS;
            if (slot < BN * 4) {
                int row = slot >> 2, kk = slot & 3;
                const __half* sp = Bh_ + (size_t)row * K + kc + kk * 8;
                uint32_t dst = b0 + (uint32_t)(2 * AHALF + row * SA + kk * 8) * 2;
                cp16(dst, sp, 16);
            }
        }
        CP_COMMIT();
    };

    const int nchunks = K / BK;
    ldgA(0);
    stsA(0, 0);
    cpB(0, 0);
    for (int c = 0; c < nchunks; c++) {
        const int buf = c & 1;
        const bool more = (c + 1 < nchunks);
        CP_WAIT0();
        __syncthreads();
        if (more) { ldgA(c + 1); cpB(c + 1, buf ^ 1); }
        const uint32_t b0 = su + buf * PERBUF * 2;
        const uint32_t cAh = b0, cAl = b0 + AHALF * 2;
        const uint32_t cBh = b0 + 2 * AHALF * 2;
        #pragma unroll
        for (int ks = 0; ks < 2; ks++) {
            const int kb = ks * 16;
            uint32_t ah[2][4], al[2][4];
            #pragma unroll
            for (int mt = 0; mt < 2; mt++) {
                int r = mw + mt * 16 + l8 + (g & 1) * 8;
                int col = kb + (g >> 1) * 8;
                uint32_t off = (uint32_t)(r * SA + col) * 2;
                ldsm4(ah[mt], cAh + off);
                ldsm4(al[mt], cAl + off);
            }
            uint32_t bh[NP][4];
            #pragma unroll
            for (int p = 0; p < NP; p++) {
                int r = nw + p * 16 + l8 + (g >> 1) * 8;
                int col = kb + (g & 1) * 8;
                uint32_t off = (uint32_t)(r * SA + col) * 2;
                ldsm4(bh[p], cBh + off);
            }
            // sweep 1: Ah * B
            #pragma unroll
            for (int p = 0; p < NP; p++)
                #pragma unroll
                for (int sub = 0; sub < 2; sub++)
                    #pragma unroll
                    for (int mt = 0; mt < 2; mt++)
                        mma16816(acc[mt][p * 2 + sub], ah[mt],
                                 bh[p][2 * sub], bh[p][2 * sub + 1]);
            // sweep 2: Al * B
            #pragma unroll
            for (int p = 0; p < NP; p++)
                #pragma unroll
                for (int sub = 0; sub < 2; sub++)
                    #pragma unroll
                    for (int mt = 0; mt < 2; mt++)
                        mma16816(acc[mt][p * 2 + sub], al[mt],
                                 bh[p][2 * sub], bh[p][2 * sub + 1]);
        }
        if (more) stsA(buf ^ 1, (c + 1) * BK);
    }

    const int gid = lane >> 2, qid = lane & 3;
    #pragma unroll
    for (int mt = 0; mt < 2; mt++) {
        int r0 = m0 + mw + mt * 16 + gid;
        #pragma unroll
        for (int nt = 0; nt < NT; nt++) {
            int col = nw + nt * 8 + qid * 2;
            #pragma unroll
            for (int half = 0; half < 2; half++) {
                int r = r0 + half * 8;
                if (r >= M) continue;
                float v0 = acc[mt][nt][half * 2 + 0];
                float v1 = acc[mt][nt][half * 2 + 1];
                if (MODE == 0) {
                    *(__half2*)&C1h[(size_t)r * BN + col] = __floats2half2_rn(v0, v1);
                } else {
                    if (col < 128) {
                        *(__half2*)&C1h[(size_t)r * 128 + col] = __floats2half2_rn(v0, v1);
                    } else {
                        int c2 = col - 128;
                        v0 += bias[c2]; v1 += bias[c2 + 1];
                        *(float2*)&C2[(size_t)r * (BN - 128) + c2] = make_float2(v0, v1);
                    }
                }
            }
        }
    }
}

// ---------------- aggregation (fp16 gather, fp32 accumulate) + BN stats ----------------
__global__ void k_agg128(const __half* __restrict__ h, float* __restrict__ out, int n) {
    __shared__ float s_sum[C1C], s_sq[C1C];
    int tid = threadIdx.x, lane = tid & 31, wid = tid >> 5;
    if (tid < C1C) { s_sum[tid] = 0.f; s_sq[tid] = 0.f; }
    __syncthreads();
    const uint2* hv = (const uint2*)h;
    float4 lsum = make_float4(0.f, 0.f, 0.f, 0.f);
    float4 lsq  = make_float4(0.f, 0.f, 0.f, 0.f);
    int base = (blockIdx.x * 8 + wid) * 8;
    #pragma unroll 1
    for (int g = 0; g < 8; g++) {
        int w = base + g;
        if (w >= n) break;
        float di = g_dinv[w];
        float s = di * di;
        uint2 raw = hv[(size_t)w * 32 + lane];
        __half2 p0 = *(__half2*)&raw.x;
        __half2 p1 = *(__half2*)&raw.y;
        float4 acc;
        acc.x = __low2float(p0) * s;  acc.y = __high2float(p0) * s;
        acc.z = __low2float(p1) * s;  acc.w = __high2float(p1) * s;
        int beg = g_rowptr[w], end = g_rowptr[w + 1];
        int e = beg;
        for (; e + 3 < end; e += 4) {
            int s0 = g_src[e], s1 = g_src[e + 1], s2 = g_src[e + 2], s3 = g_src[e + 3];
            float w0 = g_norm[e], w1 = g_norm[e + 1], w2 = g_norm[e + 2], w3 = g_norm[e + 3];
            uint2 r0 = hv[(size_t)s0 * 32 + lane];
            uint2 r1 = hv[(size_t)s1 * 32 + lane];
            uint2 r2 = hv[(size_t)s2 * 32 + lane];
            uint2 r3 = hv[(size_t)s3 * 32 + lane];
            __half2 a0 = *(__half2*)&r0.x, b0 = *(__half2*)&r0.y;
            __half2 a1 = *(__half2*)&r1.x, b1 = *(__half2*)&r1.y;
            __half2 a2 = *(__half2*)&r2.x, b2 = *(__half2*)&r2.y;
            __half2 a3 = *(__half2*)&r3.x, b3 = *(__half2*)&r3.y;
            acc.x += w0 * __low2float(a0) + w1 * __low2float(a1)
                   + w2 * __low2float(a2) + w3 * __low2float(a3);
            acc.y += w0 * __high2float(a0) + w1 * __high2float(a1)
                   + w2 * __high2float(a2) + w3 * __high2float(a3);
            acc.z += w0 * __low2float(b0) + w1 * __low2float(b1)
                   + w2 * __low2float(b2) + w3 * __low2float(b3);
            acc.w += w0 * __high2float(b0) + w1 * __high2float(b1)
                   + w2 * __high2float(b2) + w3 * __high2float(b3);
        }
        for (; e < end; e++) {
            int src = g_src[e];
            float wt = g_norm[e];
            uint2 r0 = hv[(size_t)src * 32 + lane];
            __half2 a0 = *(__half2*)&r0.x, b0 = *(__half2*)&r0.y;
            acc.x += wt * __low2float(a0);  acc.y += wt * __high2float(a0);
            acc.z += wt * __low2float(b0);  acc.w += wt * __high2float(b0);
        }
        ((float4*)out)[(size_t)w * 32 + lane] = acc;
        lsum.x += acc.x; lsum.y += acc.y; lsum.z += acc.z; lsum.w += acc.w;
        lsq.x += acc.x * acc.x; lsq.y += acc.y * acc.y;
        lsq.z += acc.z * acc.z; lsq.w += acc.w * acc.w;
    }
    int c = lane * 4;
    atomicAdd(&s_sum[c + 0], lsum.x); atomicAdd(&s_sum[c + 1], lsum.y);
    atomicAdd(&s_sum[c + 2], lsum.z); atomicAdd(&s_sum[c + 3], lsum.w);
    atomicAdd(&s_sq[c + 0], lsq.x);  atomicAdd(&s_sq[c + 1], lsq.y);
    atomicAdd(&s_sq[c + 2], lsq.z);  atomicAdd(&s_sq[c + 3], lsq.w);
    __syncthreads();
    if (tid < C1C) {
        atomicAdd(&g_bnsum[tid], s_sum[tid]);
        atomicAdd(&g_bnsq[tid], s_sq[tid]);
    }
}

__global__ void k_agg64(const __half* __restrict__ h, float* __restrict__ out, int n) {
    __shared__ float s_sum[C2C], s_sq[C2C];
    int tid = threadIdx.x, lane = tid & 31, wid = tid >> 5;
    if (tid < C2C) { s_sum[tid] = 0.f; s_sq[tid] = 0.f; }
    __syncthreads();
    const __half2* hv = (const __half2*)h;
    float2 lsum = make_float2(0.f, 0.f);
    float2 lsq  = make_float2(0.f, 0.f);
    int base = (blockIdx.x * 8 + wid) * 8;
    #pragma unroll 1
    for (int g = 0; g < 8; g++) {
        int w = base + g;
        if (w >= n) break;
        float di = g_dinv[w];
        float s = di * di;
        __half2 a = hv[(size_t)w * 32 + lane];
        float2 acc;
        acc.x = __low2float(a) * s; acc.y = __high2float(a) * s;
        int beg = g_rowptr[w], end = g_rowptr[w + 1];
        int e = beg;
        for (; e + 3 < end; e += 4) {
            int s0 = g_src[e], s1 = g_src[e + 1], s2 = g_src[e + 2], s3 = g_src[e + 3];
            float w0 = g_norm[e], w1 = g_norm[e + 1], w2 = g_norm[e + 2], w3 = g_norm[e + 3];
            __half2 v0 = hv[(size_t)s0 * 32 + lane];
            __half2 v1 = hv[(size_t)s1 * 32 + lane];
            __half2 v2 = hv[(size_t)s2 * 32 + lane];
            __half2 v3 = hv[(size_t)s3 * 32 + lane];
            acc.x += w0 * __low2float(v0) + w1 * __low2float(v1)
                   + w2 * __low2float(v2) + w3 * __low2float(v3);
            acc.y += w0 * __high2float(v0) + w1 * __high2float(v1)
                   + w2 * __high2float(v2) + w3 * __high2float(v3);
        }
        for (; e < end; e++) {
            int src = g_src[e];
            float wt = g_norm[e];
            __half2 v = hv[(size_t)src * 32 + lane];
            acc.x += wt * __low2float(v); acc.y += wt * __high2float(v);
        }
        ((float2*)out)[(size_t)w * 32 + lane] = acc;
        lsum.x += acc.x; lsum.y += acc.y;
        lsq.x += acc.x * acc.x; lsq.y += acc.y * acc.y;
    }
    int c = lane * 2;
    atomicAdd(&s_sum[c + 0], lsum.x); atomicAdd(&s_sum[c + 1], lsum.y);
    atomicAdd(&s_sq[c + 0], lsq.x);  atomicAdd(&s_sq[c + 1], lsq.y);
    __syncthreads();
    if (tid < C2C) {
        atomicAdd(&g_bnsum[C1C + tid], s_sum[tid]);
        atomicAdd(&g_bnsq[C1C + tid], s_sq[tid]);
    }
}

// ---------------- final BN2 + skip ----------------
__global__ void k_bn2(const float* __restrict__ a, float* __restrict__ o,
                      const float* __restrict__ gamma, const float* __restrict__ beta,
                      int n, const float* __restrict__ skip) {
    int i = blockIdx.x * blockDim.x + threadIdx.x;
    if (i >= n * C2C) return;
    int c = i & (C2C - 1);
    float inv_n = 1.0f / (float)n;
    float mu = g_bnsum[C1C + c] * inv_n;
    float var = g_bnsq[C1C + c] * inv_n - mu * mu;
    float v = (a[i] - mu) * rsqrtf(var + 1e-5f) * gamma[c] + beta[c];
    o[i] = v + skip[i];
}

// ---------------- launcher ----------------
extern "C" void kernel_launch(void* const* d_in, const int* in_sizes, int n_in,
                              void* d_out, int out_size) {
    const float* x   = (const float*)d_in[0];
    const int*   ei  = (const int*)d_in[1];
    const float* ew  = (const float*)d_in[2];
    const float* W1  = (const float*)d_in[3];
    const float* W2  = (const float*)d_in[5];
    const float* g1  = (const float*)d_in[7];
    const float* be1 = (const float*)d_in[8];
    const float* g2  = (const float*)d_in[9];
    const float* be2 = (const float*)d_in[10];
    const float* Ws  = (const float*)d_in[11];
    const float* bs  = (const float*)d_in[12];
    float* out = (float*)d_out;

    int E = in_sizes[2];
    int n = in_sizes[0] / CIN;
    const int* rowp = ei;
    const int* colp = ei + E;

    float *p_agg1, *p_skip, *p_agg2;
    cudaGetSymbolAddress((void**)&p_agg1, g_agg1);
    cudaGetSymbolAddress((void**)&p_skip, g_skip);
    cudaGetSymbolAddress((void**)&p_agg2, g_agg2);
    __half *p_h1f, *p_h2f, *p_wfh, *p_w2th;
    cudaGetSymbolAddress((void**)&p_h1f,  g_h1f);
    cudaGetSymbolAddress((void**)&p_h2f,  g_h2f);
    cudaGetSymbolAddress((void**)&p_wfh,  g_wfh);
    cudaGetSymbolAddress((void**)&p_w2th, g_w2th);

    // smem: 2 stages * (2*64 + BN) rows * 40 halves * 2B
    const int SMEMF = 2 * (2 * 64 + 192) * 40 * 2;  // 51200
    const int SMEM2 = 2 * (2 * 64 + 64) * 40 * 2;   // 30720
    cudaFuncSetAttribute((const void*)k_gemm_mma<192, 1, 1>,
                         cudaFuncAttributeMaxDynamicSharedMemorySize, SMEMF);
    cudaFuncSetAttribute((const void*)k_gemm_mma<64, 0, 2>,
                         cudaFuncAttributeMaxDynamicSharedMemorySize, SMEM2);

    int nb = (n + 255) / 256;
    int eb = (E + 255) / 256;
    int sblk = (n + 1023) / 1024;
    int mtiles = (n + 63) / 64;
    int aggb = (n + 63) / 64;

    // Side stream + fork/join (created fresh per call; never destroyed —
    // kernel_launch runs only a handful of times; no device memory involved).
    cudaStream_t sB;
    cudaStreamCreate(&sB);
    cudaEvent_t eFork, eJoin;
    cudaEventCreateWithFlags(&eFork, cudaEventDisableTiming);
    cudaEventCreateWithFlags(&eJoin, cudaEventDisableTiming);

    cudaEventRecord(eFork, 0);
    cudaStreamWaitEvent(sB, eFork, 0);

    // 1: main weight prep; 2-3: side CSR start
    k_split_wf<<<(192 * CIN + 255) / 256, 256>>>(W1, Ws, p_wfh);
    k_init<<<nb, 256, 0, sB>>>(n);
    k_hist<<<eb, 256, 0, sB>>>(colp, ew, E);

    // 4: fused GEMM1+skip (2-term split) — ncu capture slot
    k_gemm_mma<192, 1, 1><<<mtiles, 256, SMEMF>>>(x, p_wfh,
                                                  p_h1f, p_skip, bs,
                                                  nullptr, nullptr, n, CIN);

    // side: finish CSR + W2 prep (overlaps GEMM)
    k_scan_part<<<sblk, 1024, 0, sB>>>(n);
    k_scan_top<<<1, 64, 0, sB>>>(sblk, n);
    k_scan_add<<<sblk, 1024, 0, sB>>>(n);
    k_fill<<<eb, 256, 0, sB>>>(rowp, colp, ew, E);
    k_split_wt<<<(C1C * C2C + 255) / 256, 256, 0, sB>>>(W2, p_w2th, C1C, C2C);

    // join before aggregation
    cudaEventRecord(eJoin, sB);
    cudaStreamWaitEvent(0, eJoin, 0);

    // serial tail
    k_agg128<<<aggb, 256>>>(p_h1f, p_agg1, n);
    k_gemm_mma<64, 0, 2><<<mtiles, 256, SMEM2>>>(p_agg1, p_w2th,
                                                 p_h2f, nullptr, nullptr,
                                                 g1, be1, n, C1C);
    k_agg64<<<aggb, 256>>>(p_h2f, p_agg2, n);
    k_bn2<<<(n * C2C + 255) / 256, 256>>>(p_agg2, out, g2, be2, n, p_skip);

    (void)n_in; (void)out_size;
}

// round 14
// speedup vs baseline: 1.4492x; 1.0049x over previous
#include <cuda_runtime.h>
#include <cuda_fp16.h>
#include <math.h>
#include <stdint.h>

// ---------------- problem constants ----------------
#define NMAX 50000
#define EMAX 800000
#define CIN  256
#define C1C  128
#define C2C  64

// ---------------- device scratch ----------------
__device__ float g_deg[NMAX];
__device__ float g_dinv[NMAX];
__device__ int   g_cnt[NMAX];
__device__ int   g_fill[NMAX];
__device__ int   g_rowptr[NMAX + 1];
__device__ int   g_bsum[64];
__device__ int   g_src[EMAX];
__device__ float g_norm[EMAX];
__device__ float g_agg1[NMAX * C1C];
__device__ float g_skip[NMAX * C2C];
__device__ float g_agg2[NMAX * C2C];
__device__ float g_bnsum[C1C + C2C];
__device__ float g_bnsq[C1C + C2C];

// fp16 intermediates
__device__ __align__(256) __half g_h1f[NMAX * C1C];
__device__ __align__(256) __half g_h2f[NMAX * C2C];
// fp16 weights (plain rn)
__device__ __align__(256) __half g_wfh[192 * CIN];   // [W1^T ; Ws^T]
__device__ __align__(256) __half g_w2th[C2C * C1C];

__device__ __forceinline__ float gelu_f(float v) {
    return 0.5f * v * (1.0f + erff(v * 0.70710678118654752440f));
}

// ---------------- init ----------------
__global__ void k_init(int n) {
    int i = blockIdx.x * blockDim.x + threadIdx.x;
    if (i < n) { g_cnt[i] = 0; g_fill[i] = 0; g_deg[i] = 1.0f; }
    if (i < C1C + C2C) { g_bnsum[i] = 0.0f; g_bnsq[i] = 0.0f; }
}

// ---------------- histogram ----------------
__global__ void k_hist(const int* __restrict__ col, const float* __restrict__ ew, int e) {
    int i = blockIdx.x * blockDim.x + threadIdx.x;
    if (i < e) {
        int c = col[i];
        atomicAdd(&g_cnt[c], 1);
        atomicAdd(&g_deg[c], ew[i]);
    }
}

// ---------------- scan part (+ fused dinv) ----------------
__global__ void k_scan_part(int n) {
    __shared__ int warp_sums[32];
    int tid = threadIdx.x;
    int lane = tid & 31, wid = tid >> 5;
    int i = blockIdx.x * 1024 + tid;
    int v = (i < n) ? g_cnt[i] : 0;
    int x = v;
    #pragma unroll
    for (int o = 1; o < 32; o <<= 1) {
        int y = __shfl_up_sync(0xFFFFFFFFu, x, o);
        if (lane >= o) x += y;
    }
    if (lane == 31) warp_sums[wid] = x;
    __syncthreads();
    if (wid == 0) {
        int w = warp_sums[lane];
        #pragma unroll
        for (int o = 1; o < 32; o <<= 1) {
            int y = __shfl_up_sync(0xFFFFFFFFu, w, o);
            if (lane >= o) w += y;
        }
        warp_sums[lane] = w;
    }
    __syncthreads();
    int inc = x + (wid > 0 ? warp_sums[wid - 1] : 0);
    if (i < n) {
        g_rowptr[i] = inc - v;
        float d = g_deg[i];
        g_dinv[i] = (d > 0.0f) ? rsqrtf(d) : 0.0f;
    }
    if (tid == 1023) g_bsum[blockIdx.x] = inc;
}

__global__ void k_scan_top(int nblk, int n) {
    int tid = threadIdx.x;
    int lane = tid & 31, wid = tid >> 5;
    __shared__ int w0_total;
    int v = (tid < nblk) ? g_bsum[tid] : 0;
    int x = v;
    #pragma unroll
    for (int o = 1; o < 32; o <<= 1) {
        int y = __shfl_up_sync(0xFFFFFFFFu, x, o);
        if (lane >= o) x += y;
    }
    if (wid == 0 && lane == 31) w0_total = x;
    __syncthreads();
    int incl = x + (wid == 1 ? w0_total : 0);
    if (tid < nblk) g_bsum[tid] = incl - v;
    if (tid == nblk - 1) g_rowptr[n] = incl;
}

__global__ void k_scan_add(int n) {
    int i = blockIdx.x * 1024 + threadIdx.x;
    if (i < n) g_rowptr[i] += g_bsum[blockIdx.x];
}

// ---------------- fill CSR ----------------
__global__ void k_fill(const int* __restrict__ row, const int* __restrict__ col,
                       const float* __restrict__ ew, int e) {
    int i = blockIdx.x * blockDim.x + threadIdx.x;
    if (i < e) {
        int c = col[i], r = row[i];
        int pos = g_rowptr[c] + atomicAdd(&g_fill[c], 1);
        g_src[pos] = r;
        g_norm[pos] = g_dinv[r] * ew[i] * g_dinv[c];
    }
}

// ---------------- fused W1+Ws transpose (fp16 rn) ----------------
__global__ void k_split_wf(const float* __restrict__ W1, const float* __restrict__ Ws,
                           __half* __restrict__ Th) {
    int i = blockIdx.x * blockDim.x + threadIdx.x;
    if (i >= 192 * CIN) return;
    int nn = i / CIN, k = i % CIN;
    float v = (nn < C1C) ? W1[(size_t)k * C1C + nn] : Ws[(size_t)k * C2C + (nn - C1C)];
    Th[i] = __float2half_rn(v);
}

// ---------------- transpose W2 (fp16 rn) ----------------
__global__ void k_split_wt(const float* __restrict__ W, __half* __restrict__ Th,
                           int K, int N) {
    int i = blockIdx.x * blockDim.x + threadIdx.x;
    if (i >= K * N) return;
    int k = i / N, nn = i % N;
    Th[(size_t)nn * K + k] = __float2half_rn(W[i]);
}

// ---------------- mma.sync GEMM, BK=64, 2-term split ----------------
__device__ __forceinline__ void ldsm4(uint32_t* r, uint32_t addr) {
    asm volatile("ldmatrix.sync.aligned.m8n8.x4.shared.b16 {%0,%1,%2,%3}, [%4];"
                 : "=r"(r[0]), "=r"(r[1]), "=r"(r[2]), "=r"(r[3]) : "r"(addr));
}
__device__ __forceinline__ void mma16816(float* d, const uint32_t* a,
                                         uint32_t b0, uint32_t b1) {
    asm volatile(
        "mma.sync.aligned.m16n8k16.row.col.f32.f16.f16.f32 "
        "{%0,%1,%2,%3}, {%4,%5,%6,%7}, {%8,%9}, {%0,%1,%2,%3};"
        : "+f"(d[0]), "+f"(d[1]), "+f"(d[2]), "+f"(d[3])
        : "r"(a[0]), "r"(a[1]), "r"(a[2]), "r"(a[3]), "r"(b0), "r"(b1));
}
__device__ __forceinline__ void cp16(uint32_t dst, const void* src, int srcsize) {
    asm volatile("cp.async.cg.shared.global [%0], [%1], 16, %2;"
                 :: "r"(dst), "l"(src), "r"(srcsize) : "memory");
}
#define CP_COMMIT() asm volatile("cp.async.commit_group;" ::: "memory")
#define CP_WAIT0()  asm volatile("cp.async.wait_group 0;" ::: "memory")

__device__ __forceinline__ uint32_t hpack(__half a, __half b) {
    return (uint32_t)__half_as_ushort(a) | ((uint32_t)__half_as_ushort(b) << 16);
}

// A fp32 [M,K] split hi/lo fp16 in-kernel; B fp16 [BN,K].
// D = Ah*B + Al*B. AFP 1: plain. AFP 2: BN+GELU on A.
// MODE 0: all cols -> C1h fp16. MODE 1: col<128 -> C1h; col>=128 -> C2 fp32 +bias.
// BK=64: 4 ks-iterations per chunk; one barrier per chunk (race-free per R10).
template<int BN, int MODE, int AFP>
__global__ __launch_bounds__(256) void k_gemm_mma(
    const float* __restrict__ A,
    const __half* __restrict__ Bh_,
    __half* __restrict__ C1h, float* __restrict__ C2,
    const float* __restrict__ bias,
    const float* __restrict__ bnG, const float* __restrict__ bnB,
    int M, int K) {
    constexpr int BM = 64;
    constexpr int BK = 64;
    constexpr int SA = 72;               // 64 halves + 8 pad (conflict-free)
    constexpr int THREADS = 256;
    constexpr int WM = 2, WN = 4;
    constexpr int WNW = BN / WN;
    constexpr int NT = WNW / 8;
    constexpr int NP = NT / 2;
    constexpr int AHALF = BM * SA;
    constexpr int BHALF = BN * SA;
    constexpr int PERBUF = 2 * AHALF + BHALF;
    extern __shared__ __half smh[];
    const uint32_t su = (uint32_t)__cvta_generic_to_shared(smh);
    __shared__ float sS[C1C], sBsh[C1C];

    const int tid = threadIdx.x;
    const int w = tid >> 5, lane = tid & 31;
    const int mw = (w % WM) * 32;
    const int nw = (w / WM) * WNW;
    const int m0 = blockIdx.x * BM;
    const int g = lane >> 3, l8 = lane & 7;

    if (AFP == 2) {
        if (tid < K) {
            float inv = 1.0f / (float)M;
            float mu = g_bnsum[tid] * inv;
            float var = g_bnsq[tid] * inv - mu * mu;
            float sc = bnG[tid] * rsqrtf(var + 1e-5f);
            sS[tid] = sc;
            sBsh[tid] = bnB[tid] - mu * sc;
        }
        __syncthreads();
    }

    float acc[2][NT][4];
    #pragma unroll
    for (int i = 0; i < 2; i++)
        #pragma unroll
        for (int j = 0; j < NT; j++)
            #pragma unroll
            for (int q = 0; q < 4; q++) acc[i][j][q] = 0.0f;

    // A staging: 64 rows x 8 k-groups (8 floats) = 512 slots, 2 per thread.
    float4 ra[2][2];
    auto ldgA = [&](int chunk) {
        #pragma unroll
        for (int it = 0; it < 2; it++) {
            int slot = tid + it * 256;
            int row = slot >> 3;
            int kk = (slot & 7) * 8;
            int gm = m0 + row;
            const float* s = A + (size_t)(gm < M ? gm : 0) * K + chunk * BK + kk;
            ra[it][0] = *(const float4*)s;
            ra[it][1] = *(const float4*)(s + 4);
        }
    };
    auto stsA = [&](int buf, int kc) {
        #pragma unroll
        for (int it = 0; it < 2; it++) {
            int slot = tid + it * 256;
            int row = slot >> 3;
            int kk = (slot & 7) * 8;
            float v[8] = {ra[it][0].x, ra[it][0].y, ra[it][0].z, ra[it][0].w,
                          ra[it][1].x, ra[it][1].y, ra[it][1].z, ra[it][1].w};
            if (AFP == 2) {
                #pragma unroll
                for (int i = 0; i < 8; i++) {
                    int kcol = kc + kk + i;
                    v[i] = gelu_f(fmaf(v[i], sS[kcol], sBsh[kcol]));
                }
            }
            __half hh[8], hl[8];
            #pragma unroll
            for (int i = 0; i < 8; i++) {
                hh[i] = __float2half_rn(v[i]);
                hl[i] = __float2half_rn(v[i] - __half2float(hh[i]));
            }
            uint4 uh, ul;
            uh.x = hpack(hh[0], hh[1]); uh.y = hpack(hh[2], hh[3]);
            uh.z = hpack(hh[4], hh[5]); uh.w = hpack(hh[6], hh[7]);
            ul.x = hpack(hl[0], hl[1]); ul.y = hpack(hl[2], hl[3]);
            ul.z = hpack(hl[4], hl[5]); ul.w = hpack(hl[6], hl[7]);
            __half* dst = smh + buf * PERBUF + row * SA + kk;
            *(uint4*)dst = uh;
            *(uint4*)(dst + AHALF) = ul;
        }
    };
    auto cpB = [&](int chunk, int buf) {
        const int kc = chunk * BK;
        const uint32_t b0 = su + buf * PERBUF * 2;
        #pragma unroll
        for (int it = 0; it < (BN * 8 + THREADS - 1) / THREADS; it++) {
            int slot = tid + it * THREADS;
            if (slot < BN * 8) {
                int row = slot >> 3, kk = slot & 7;
                const __half* sp = Bh_ + (size_t)row * K + kc + kk * 8;
                uint32_t dst = b0 + (uint32_t)(2 * AHALF + row * SA + kk * 8) * 2;
                cp16(dst, sp, 16);
            }
        }
        CP_COMMIT();
    };

    const int nchunks = K / BK;
    ldgA(0);
    stsA(0, 0);
    cpB(0, 0);
    for (int c = 0; c < nchunks; c++) {
        const int buf = c & 1;
        const bool more = (c + 1 < nchunks);
        CP_WAIT0();
        __syncthreads();
        if (more) { ldgA(c + 1); cpB(c + 1, buf ^ 1); }
        const uint32_t b0 = su + buf * PERBUF * 2;
        const uint32_t cAh = b0, cAl = b0 + AHALF * 2;
        const uint32_t cBh = b0 + 2 * AHALF * 2;
        #pragma unroll
        for (int ks = 0; ks < 4; ks++) {
            const int kb = ks * 16;
            uint32_t ah[2][4], al[2][4];
            #pragma unroll
            for (int mt = 0; mt < 2; mt++) {
                int r = mw + mt * 16 + l8 + (g & 1) * 8;
                int col = kb + (g >> 1) * 8;
                uint32_t off = (uint32_t)(r * SA + col) * 2;
                ldsm4(ah[mt], cAh + off);
                ldsm4(al[mt], cAl + off);
            }
            uint32_t bh[NP][4];
            #pragma unroll
            for (int p = 0; p < NP; p++) {
                int r = nw + p * 16 + l8 + (g >> 1) * 8;
                int col = kb + (g & 1) * 8;
                uint32_t off = (uint32_t)(r * SA + col) * 2;
                ldsm4(bh[p], cBh + off);
            }
            #pragma unroll
            for (int p = 0; p < NP; p++)
                #pragma unroll
                for (int sub = 0; sub < 2; sub++)
                    #pragma unroll
                    for (int mt = 0; mt < 2; mt++)
                        mma16816(acc[mt][p * 2 + sub], ah[mt],
                                 bh[p][2 * sub], bh[p][2 * sub + 1]);
            #pragma unroll
            for (int p = 0; p < NP; p++)
                #pragma unroll
                for (int sub = 0; sub < 2; sub++)
                    #pragma unroll
                    for (int mt = 0; mt < 2; mt++)
                        mma16816(acc[mt][p * 2 + sub], al[mt],
                                 bh[p][2 * sub], bh[p][2 * sub + 1]);
        }
        if (more) stsA(buf ^ 1, (c + 1) * BK);
    }

    const int gid = lane >> 2, qid = lane & 3;
    #pragma unroll
    for (int mt = 0; mt < 2; mt++) {
        int r0 = m0 + mw + mt * 16 + gid;
        #pragma unroll
        for (int nt = 0; nt < NT; nt++) {
            int col = nw + nt * 8 + qid * 2;
            #pragma unroll
            for (int half = 0; half < 2; half++) {
                int r = r0 + half * 8;
                if (r >= M) continue;
                float v0 = acc[mt][nt][half * 2 + 0];
                float v1 = acc[mt][nt][half * 2 + 1];
                if (MODE == 0) {
                    *(__half2*)&C1h[(size_t)r * BN + col] = __floats2half2_rn(v0, v1);
                } else {
                    if (col < 128) {
                        *(__half2*)&C1h[(size_t)r * 128 + col] = __floats2half2_rn(v0, v1);
                    } else {
                        int c2 = col - 128;
                        v0 += bias[c2]; v1 += bias[c2 + 1];
                        *(float2*)&C2[(size_t)r * (BN - 128) + c2] = make_float2(v0, v1);
                    }
                }
            }
        }
    }
}

// ---------------- aggregation (fp16 gather, fp32 accumulate) + BN stats ----------------
__global__ void k_agg128(const __half* __restrict__ h, float* __restrict__ out, int n) {
    __shared__ float s_sum[C1C], s_sq[C1C];
    int tid = threadIdx.x, lane = tid & 31, wid = tid >> 5;
    if (tid < C1C) { s_sum[tid] = 0.f; s_sq[tid] = 0.f; }
    __syncthreads();
    const uint2* hv = (const uint2*)h;
    float4 lsum = make_float4(0.f, 0.f, 0.f, 0.f);
    float4 lsq  = make_float4(0.f, 0.f, 0.f, 0.f);
    int base = (blockIdx.x * 8 + wid) * 8;
    #pragma unroll 1
    for (int g = 0; g < 8; g++) {
        int w = base + g;
        if (w >= n) break;
        float di = g_dinv[w];
        float s = di * di;
        uint2 raw = hv[(size_t)w * 32 + lane];
        __half2 p0 = *(__half2*)&raw.x;
        __half2 p1 = *(__half2*)&raw.y;
        float4 acc;
        acc.x = __low2float(p0) * s;  acc.y = __high2float(p0) * s;
        acc.z = __low2float(p1) * s;  acc.w = __high2float(p1) * s;
        int beg = g_rowptr[w], end = g_rowptr[w + 1];
        int e = beg;
        for (; e + 3 < end; e += 4) {
            int s0 = g_src[e], s1 = g_src[e + 1], s2 = g_src[e + 2], s3 = g_src[e + 3];
            float w0 = g_norm[e], w1 = g_norm[e + 1], w2 = g_norm[e + 2], w3 = g_norm[e + 3];
            uint2 r0 = hv[(size_t)s0 * 32 + lane];
            uint2 r1 = hv[(size_t)s1 * 32 + lane];
            uint2 r2 = hv[(size_t)s2 * 32 + lane];
            uint2 r3 = hv[(size_t)s3 * 32 + lane];
            __half2 a0 = *(__half2*)&r0.x, b0 = *(__half2*)&r0.y;
            __half2 a1 = *(__half2*)&r1.x, b1 = *(__half2*)&r1.y;
            __half2 a2 = *(__half2*)&r2.x, b2 = *(__half2*)&r2.y;
            __half2 a3 = *(__half2*)&r3.x, b3 = *(__half2*)&r3.y;
            acc.x += w0 * __low2float(a0) + w1 * __low2float(a1)
                   + w2 * __low2float(a2) + w3 * __low2float(a3);
            acc.y += w0 * __high2float(a0) + w1 * __high2float(a1)
                   + w2 * __high2float(a2) + w3 * __high2float(a3);
            acc.z += w0 * __low2float(b0) + w1 * __low2float(b1)
                   + w2 * __low2float(b2) + w3 * __low2float(b3);
            acc.w += w0 * __high2float(b0) + w1 * __high2float(b1)
                   + w2 * __high2float(b2) + w3 * __high2float(b3);
        }
        for (; e < end; e++) {
            int src = g_src[e];
            float wt = g_norm[e];
            uint2 r0 = hv[(size_t)src * 32 + lane];
            __half2 a0 = *(__half2*)&r0.x, b0 = *(__half2*)&r0.y;
            acc.x += wt * __low2float(a0);  acc.y += wt * __high2float(a0);
            acc.z += wt * __low2float(b0);  acc.w += wt * __high2float(b0);
        }
        ((float4*)out)[(size_t)w * 32 + lane] = acc;
        lsum.x += acc.x; lsum.y += acc.y; lsum.z += acc.z; lsum.w += acc.w;
        lsq.x += acc.x * acc.x; lsq.y += acc.y * acc.y;
        lsq.z += acc.z * acc.z; lsq.w += acc.w * acc.w;
    }
    int c = lane * 4;
    atomicAdd(&s_sum[c + 0], lsum.x); atomicAdd(&s_sum[c + 1], lsum.y);
    atomicAdd(&s_sum[c + 2], lsum.z); atomicAdd(&s_sum[c + 3], lsum.w);
    atomicAdd(&s_sq[c + 0], lsq.x);  atomicAdd(&s_sq[c + 1], lsq.y);
    atomicAdd(&s_sq[c + 2], lsq.z);  atomicAdd(&s_sq[c + 3], lsq.w);
    __syncthreads();
    if (tid < C1C) {
        atomicAdd(&g_bnsum[tid], s_sum[tid]);
        atomicAdd(&g_bnsq[tid], s_sq[tid]);
    }
}

__global__ void k_agg64(const __half* __restrict__ h, float* __restrict__ out, int n) {
    __shared__ float s_sum[C2C], s_sq[C2C];
    int tid = threadIdx.x, lane = tid & 31, wid = tid >> 5;
    if (tid < C2C) { s_sum[tid] = 0.f; s_sq[tid] = 0.f; }
    __syncthreads();
    const __half2* hv = (const __half2*)h;
    float2 lsum = make_float2(0.f, 0.f);
    float2 lsq  = make_float2(0.f, 0.f);
    int base = (blockIdx.x * 8 + wid) * 8;
    #pragma unroll 1
    for (int g = 0; g < 8; g++) {
        int w = base + g;
        if (w >= n) break;
        float di = g_dinv[w];
        float s = di * di;
        __half2 a = hv[(size_t)w * 32 + lane];
        float2 acc;
        acc.x = __low2float(a) * s; acc.y = __high2float(a) * s;
        int beg = g_rowptr[w], end = g_rowptr[w + 1];
        int e = beg;
        for (; e + 3 < end; e += 4) {
            int s0 = g_src[e], s1 = g_src[e + 1], s2 = g_src[e + 2], s3 = g_src[e + 3];
            float w0 = g_norm[e], w1 = g_norm[e + 1], w2 = g_norm[e + 2], w3 = g_norm[e + 3];
            __half2 v0 = hv[(size_t)s0 * 32 + lane];
            __half2 v1 = hv[(size_t)s1 * 32 + lane];
            __half2 v2 = hv[(size_t)s2 * 32 + lane];
            __half2 v3 = hv[(size_t)s3 * 32 + lane];
            acc.x += w0 * __low2float(v0) + w1 * __low2float(v1)
                   + w2 * __low2float(v2) + w3 * __low2float(v3);
            acc.y += w0 * __high2float(v0) + w1 * __high2float(v1)
                   + w2 * __high2float(v2) + w3 * __high2float(v3);
        }
        for (; e < end; e++) {
            int src = g_src[e];
            float wt = g_norm[e];
            __half2 v = hv[(size_t)src * 32 + lane];
            acc.x += wt * __low2float(v); acc.y += wt * __high2float(v);
        }
        ((float2*)out)[(size_t)w * 32 + lane] = acc;
        lsum.x += acc.x; lsum.y += acc.y;
        lsq.x += acc.x * acc.x; lsq.y += acc.y * acc.y;
    }
    int c = lane * 2;
    atomicAdd(&s_sum[c + 0], lsum.x); atomicAdd(&s_sum[c + 1], lsum.y);
    atomicAdd(&s_sq[c + 0], lsq.x);  atomicAdd(&s_sq[c + 1], lsq.y);
    __syncthreads();
    if (tid < C2C) {
        atomicAdd(&g_bnsum[C1C + tid], s_sum[tid]);
        atomicAdd(&g_bnsq[C1C + tid], s_sq[tid]);
    }
}

// ---------------- final BN2 + skip ----------------
__global__ void k_bn2(const float* __restrict__ a, float* __restrict__ o,
                      const float* __restrict__ gamma, const float* __restrict__ beta,
                      int n, const float* __restrict__ skip) {
    int i = blockIdx.x * blockDim.x + threadIdx.x;
    if (i >= n * C2C) return;
    int c = i & (C2C - 1);
    float inv_n = 1.0f / (float)n;
    float mu = g_bnsum[C1C + c] * inv_n;
    float var = g_bnsq[C1C + c] * inv_n - mu * mu;
    float v = (a[i] - mu) * rsqrtf(var + 1e-5f) * gamma[c] + beta[c];
    o[i] = v + skip[i];
}

// ---------------- launcher ----------------
extern "C" void kernel_launch(void* const* d_in, const int* in_sizes, int n_in,
                              void* d_out, int out_size) {
    const float* x   = (const float*)d_in[0];
    const int*   ei  = (const int*)d_in[1];
    const float* ew  = (const float*)d_in[2];
    const float* W1  = (const float*)d_in[3];
    const float* W2  = (const float*)d_in[5];
    const float* g1  = (const float*)d_in[7];
    const float* be1 = (const float*)d_in[8];
    const float* g2  = (const float*)d_in[9];
    const float* be2 = (const float*)d_in[10];
    const float* Ws  = (const float*)d_in[11];
    const float* bs  = (const float*)d_in[12];
    float* out = (float*)d_out;

    int E = in_sizes[2];
    int n = in_sizes[0] / CIN;
    const int* rowp = ei;
    const int* colp = ei + E;

    float *p_agg1, *p_skip, *p_agg2;
    cudaGetSymbolAddress((void**)&p_agg1, g_agg1);
    cudaGetSymbolAddress((void**)&p_skip, g_skip);
    cudaGetSymbolAddress((void**)&p_agg2, g_agg2);
    __half *p_h1f, *p_h2f, *p_wfh, *p_w2th;
    cudaGetSymbolAddress((void**)&p_h1f,  g_h1f);
    cudaGetSymbolAddress((void**)&p_h2f,  g_h2f);
    cudaGetSymbolAddress((void**)&p_wfh,  g_wfh);
    cudaGetSymbolAddress((void**)&p_w2th, g_w2th);

    // smem: 2 stages * (2*64 + BN) rows * 72 halves * 2B
    const int SMEMF = 2 * (2 * 64 + 192) * 72 * 2;  // 92160
    const int SMEM2 = 2 * (2 * 64 + 64) * 72 * 2;   // 55296
    cudaFuncSetAttribute((const void*)k_gemm_mma<192, 1, 1>,
                         cudaFuncAttributeMaxDynamicSharedMemorySize, SMEMF);
    cudaFuncSetAttribute((const void*)k_gemm_mma<64, 0, 2>,
                         cudaFuncAttributeMaxDynamicSharedMemorySize, SMEM2);

    int nb = (n + 255) / 256;
    int eb = (E + 255) / 256;
    int sblk = (n + 1023) / 1024;
    int mtiles = (n + 63) / 64;
    int aggb = (n + 63) / 64;

    // Side stream + fork/join (created fresh per call; never destroyed).
    cudaStream_t sB;
    cudaStreamCreate(&sB);
    cudaEvent_t eFork, eJoin;
    cudaEventCreateWithFlags(&eFork, cudaEventDisableTiming);
    cudaEventCreateWithFlags(&eJoin, cudaEventDisableTiming);

    cudaEventRecord(eFork, 0);
    cudaStreamWaitEvent(sB, eFork, 0);

    // 1: main weight prep; 2-3: side CSR start
    k_split_wf<<<(192 * CIN + 255) / 256, 256>>>(W1, Ws, p_wfh);
    k_init<<<nb, 256, 0, sB>>>(n);
    k_hist<<<eb, 256, 0, sB>>>(colp, ew, E);

    // 4: fused GEMM1+skip (BK=64, 2-term) — ncu capture slot
    k_gemm_mma<192, 1, 1><<<mtiles, 256, SMEMF>>>(x, p_wfh,
                                                  p_h1f, p_skip, bs,
                                                  nullptr, nullptr, n, CIN);

    // side: finish CSR + W2 prep (overlaps GEMM)
    k_scan_part<<<sblk, 1024, 0, sB>>>(n);
    k_scan_top<<<1, 64, 0, sB>>>(sblk, n);
    k_scan_add<<<sblk, 1024, 0, sB>>>(n);
    k_fill<<<eb, 256, 0, sB>>>(rowp, colp, ew, E);
    k_split_wt<<<(C1C * C2C + 255) / 256, 256, 0, sB>>>(W2, p_w2th, C1C, C2C);

    // join before aggregation
    cudaEventRecord(eJoin, sB);
    cudaStreamWaitEvent(0, eJoin, 0);

    // serial tail
    k_agg128<<<aggb, 256>>>(p_h1f, p_agg1, n);
    k_gemm_mma<64, 0, 2><<<mtiles, 256, SMEM2>>>(p_agg1, p_w2th,
                                                 p_h2f, nullptr, nullptr,
                                                 g1, be1, n, C1C);
    k_agg64<<<aggb, 256>>>(p_h2f, p_agg2, n);
    k_bn2<<<(n * C2C + 255) / 256, 256>>>(p_agg2, out, g2, be2, n, p_skip);

    (void)n_in; (void)out_size;
}

// round 15
// speedup vs baseline: 1.6088x; 1.1102x over previous
#include <cuda_runtime.h>
#include <cuda_fp16.h>
#include <math.h>
#include <stdint.h>

// ---------------- problem constants ----------------
#define NMAX 50000
#define EMAX 800000
#define CIN  256
#define C1C  128
#define C2C  64

// ---------------- device scratch ----------------
__device__ float g_deg[NMAX];
__device__ float g_dinv[NMAX];
__device__ int   g_cnt[NMAX];
__device__ int   g_fill[NMAX];
__device__ int   g_rowptr[NMAX + 1];
__device__ int   g_bsum[64];
__device__ int   g_src[EMAX];
__device__ float g_norm[EMAX];
__device__ float g_agg1[NMAX * C1C];
__device__ float g_skip[NMAX * C2C];
__device__ float g_agg2[NMAX * C2C];
__device__ float g_bnsum[C1C + C2C];
__device__ float g_bnsq[C1C + C2C];

// fp16 intermediates
__device__ __align__(256) __half g_h1f[NMAX * C1C];
__device__ __align__(256) __half g_h2f[NMAX * C2C];
// fp16 weights
__device__ __align__(256) __half g_wfh[192 * CIN];   // [W1^T ; Ws^T]
__device__ __align__(256) __half g_w2th[C2C * C1C];

__device__ __forceinline__ float gelu_f(float v) {
    return 0.5f * v * (1.0f + erff(v * 0.70710678118654752440f));
}

// ---------------- init ----------------
__global__ void k_init(int n) {
    int i = blockIdx.x * blockDim.x + threadIdx.x;
    if (i < n) { g_cnt[i] = 0; g_fill[i] = 0; g_deg[i] = 1.0f; }
    if (i < C1C + C2C) { g_bnsum[i] = 0.0f; g_bnsq[i] = 0.0f; }
}

// ---------------- histogram ----------------
__global__ void k_hist(const int* __restrict__ col, const float* __restrict__ ew, int e) {
    int i = blockIdx.x * blockDim.x + threadIdx.x;
    if (i < e) {
        int c = col[i];
        atomicAdd(&g_cnt[c], 1);
        atomicAdd(&g_deg[c], ew[i]);
    }
}

// ---------------- scan part (+ fused dinv) ----------------
__global__ void k_scan_part(int n) {
    __shared__ int warp_sums[32];
    int tid = threadIdx.x;
    int lane = tid & 31, wid = tid >> 5;
    int i = blockIdx.x * 1024 + tid;
    int v = (i < n) ? g_cnt[i] : 0;
    int x = v;
    #pragma unroll
    for (int o = 1; o < 32; o <<= 1) {
        int y = __shfl_up_sync(0xFFFFFFFFu, x, o);
        if (lane >= o) x += y;
    }
    if (lane == 31) warp_sums[wid] = x;
    __syncthreads();
    if (wid == 0) {
        int w = warp_sums[lane];
        #pragma unroll
        for (int o = 1; o < 32; o <<= 1) {
            int y = __shfl_up_sync(0xFFFFFFFFu, w, o);
            if (lane >= o) w += y;
        }
        warp_sums[lane] = w;
    }
    __syncthreads();
    int inc = x + (wid > 0 ? warp_sums[wid - 1] : 0);
    if (i < n) {
        g_rowptr[i] = inc - v;
        float d = g_deg[i];
        g_dinv[i] = (d > 0.0f) ? rsqrtf(d) : 0.0f;
    }
    if (tid == 1023) g_bsum[blockIdx.x] = inc;
}

__global__ void k_scan_top(int nblk, int n) {
    int tid = threadIdx.x;
    int lane = tid & 31, wid = tid >> 5;
    __shared__ int w0_total;
    int v = (tid < nblk) ? g_bsum[tid] : 0;
    int x = v;
    #pragma unroll
    for (int o = 1; o < 32; o <<= 1) {
        int y = __shfl_up_sync(0xFFFFFFFFu, x, o);
        if (lane >= o) x += y;
    }
    if (wid == 0 && lane == 31) w0_total = x;
    __syncthreads();
    int incl = x + (wid == 1 ? w0_total : 0);
    if (tid < nblk) g_bsum[tid] = incl - v;
    if (tid == nblk - 1) g_rowptr[n] = incl;
}

__global__ void k_scan_add(int n) {
    int i = blockIdx.x * 1024 + threadIdx.x;
    if (i < n) g_rowptr[i] += g_bsum[blockIdx.x];
}

// ---------------- fill CSR ----------------
__global__ void k_fill(const int* __restrict__ row, const int* __restrict__ col,
                       const float* __restrict__ ew, int e) {
    int i = blockIdx.x * blockDim.x + threadIdx.x;
    if (i < e) {
        int c = col[i], r = row[i];
        int pos = g_rowptr[c] + atomicAdd(&g_fill[c], 1);
        g_src[pos] = r;
        g_norm[pos] = g_dinv[r] * ew[i] * g_dinv[c];
    }
}

// ---------------- fused W1+Ws transpose (fp16 rn) ----------------
__global__ void k_split_wf(const float* __restrict__ W1, const float* __restrict__ Ws,
                           __half* __restrict__ Th) {
    int i = blockIdx.x * blockDim.x + threadIdx.x;
    if (i >= 192 * CIN) return;
    int nn = i / CIN, k = i % CIN;
    float v = (nn < C1C) ? W1[(size_t)k * C1C + nn] : Ws[(size_t)k * C2C + (nn - C1C)];
    Th[i] = __float2half_rn(v);
}

// ---------------- transpose W2 (fp16 rn) ----------------
__global__ void k_split_wt(const float* __restrict__ W, __half* __restrict__ Th,
                           int K, int N) {
    int i = blockIdx.x * blockDim.x + threadIdx.x;
    if (i >= K * N) return;
    int k = i / N, nn = i % N;
    Th[(size_t)nn * K + k] = __float2half_rn(W[i]);
}

// ---------------- mma.sync GEMM, BK=64, single-term fp16 ----------------
__device__ __forceinline__ void ldsm4(uint32_t* r, uint32_t addr) {
    asm volatile("ldmatrix.sync.aligned.m8n8.x4.shared.b16 {%0,%1,%2,%3}, [%4];"
                 : "=r"(r[0]), "=r"(r[1]), "=r"(r[2]), "=r"(r[3]) : "r"(addr));
}
__device__ __forceinline__ void mma16816(float* d, const uint32_t* a,
                                         uint32_t b0, uint32_t b1) {
    asm volatile(
        "mma.sync.aligned.m16n8k16.row.col.f32.f16.f16.f32 "
        "{%0,%1,%2,%3}, {%4,%5,%6,%7}, {%8,%9}, {%0,%1,%2,%3};"
        : "+f"(d[0]), "+f"(d[1]), "+f"(d[2]), "+f"(d[3])
        : "r"(a[0]), "r"(a[1]), "r"(a[2]), "r"(a[3]), "r"(b0), "r"(b1));
}
__device__ __forceinline__ void cp16(uint32_t dst, const void* src, int srcsize) {
    asm volatile("cp.async.cg.shared.global [%0], [%1], 16, %2;"
                 :: "r"(dst), "l"(src), "r"(srcsize) : "memory");
}
#define CP_COMMIT() asm volatile("cp.async.commit_group;" ::: "memory")
#define CP_WAIT0()  asm volatile("cp.async.wait_group 0;" ::: "memory")

__device__ __forceinline__ uint32_t hpack(__half a, __half b) {
    return (uint32_t)__half_as_ushort(a) | ((uint32_t)__half_as_ushort(b) << 16);
}

// A fp32 [M,K] converted to fp16-rn in-kernel; B fp16 [BN,K]. D = A16 * B.
// AFP 1: plain convert. AFP 2: BN(g_bnsum/g_bnsq[0..K)) + GELU, then convert.
// MODE 0: all cols -> C1h fp16. MODE 1: col<128 -> C1h; col>=128 -> C2 fp32 +bias.
template<int BN, int MODE, int AFP>
__global__ __launch_bounds__(256) void k_gemm_mma(
    const float* __restrict__ A,
    const __half* __restrict__ Bh_,
    __half* __restrict__ C1h, float* __restrict__ C2,
    const float* __restrict__ bias,
    const float* __restrict__ bnG, const float* __restrict__ bnB,
    int M, int K) {
    constexpr int BM = 64;
    constexpr int BK = 64;
    constexpr int SA = 72;
    constexpr int THREADS = 256;
    constexpr int WM = 2, WN = 4;
    constexpr int WNW = BN / WN;
    constexpr int NT = WNW / 8;
    constexpr int NP = NT / 2;
    constexpr int AHALF = BM * SA;
    constexpr int BHALF = BN * SA;
    constexpr int PERBUF = AHALF + BHALF;
    extern __shared__ __half smh[];
    const uint32_t su = (uint32_t)__cvta_generic_to_shared(smh);
    __shared__ float sS[C1C], sBsh[C1C];

    const int tid = threadIdx.x;
    const int w = tid >> 5, lane = tid & 31;
    const int mw = (w % WM) * 32;
    const int nw = (w / WM) * WNW;
    const int m0 = blockIdx.x * BM;
    const int g = lane >> 3, l8 = lane & 7;

    if (AFP == 2) {
        if (tid < K) {
            float inv = 1.0f / (float)M;
            float mu = g_bnsum[tid] * inv;
            float var = g_bnsq[tid] * inv - mu * mu;
            float sc = bnG[tid] * rsqrtf(var + 1e-5f);
            sS[tid] = sc;
            sBsh[tid] = bnB[tid] - mu * sc;
        }
        __syncthreads();
    }

    float acc[2][NT][4];
    #pragma unroll
    for (int i = 0; i < 2; i++)
        #pragma unroll
        for (int j = 0; j < NT; j++)
            #pragma unroll
            for (int q = 0; q < 4; q++) acc[i][j][q] = 0.0f;

    // A staging: 64 rows x 8 k-groups (8 floats) = 512 slots, 2 per thread.
    float4 ra[2][2];
    auto ldgA = [&](int chunk) {
        #pragma unroll
        for (int it = 0; it < 2; it++) {
            int slot = tid + it * 256;
            int row = slot >> 3;
            int kk = (slot & 7) * 8;
            int gm = m0 + row;
            const float* s = A + (size_t)(gm < M ? gm : 0) * K + chunk * BK + kk;
            ra[it][0] = *(const float4*)s;
            ra[it][1] = *(const float4*)(s + 4);
        }
    };
    auto stsA = [&](int buf, int kc) {
        #pragma unroll
        for (int it = 0; it < 2; it++) {
            int slot = tid + it * 256;
            int row = slot >> 3;
            int kk = (slot & 7) * 8;
            float v[8] = {ra[it][0].x, ra[it][0].y, ra[it][0].z, ra[it][0].w,
                          ra[it][1].x, ra[it][1].y, ra[it][1].z, ra[it][1].w};
            if (AFP == 2) {
                #pragma unroll
                for (int i = 0; i < 8; i++) {
                    int kcol = kc + kk + i;
                    v[i] = gelu_f(fmaf(v[i], sS[kcol], sBsh[kcol]));
                }
            }
            __half hh[8];
            #pragma unroll
            for (int i = 0; i < 8; i++) hh[i] = __float2half_rn(v[i]);
            uint4 uh;
            uh.x = hpack(hh[0], hh[1]); uh.y = hpack(hh[2], hh[3]);
            uh.z = hpack(hh[4], hh[5]); uh.w = hpack(hh[6], hh[7]);
            *(uint4*)(smh + buf * PERBUF + row * SA + kk) = uh;
        }
    };
    auto cpB = [&](int chunk, int buf) {
        const int kc = chunk * BK;
        const uint32_t b0 = su + buf * PERBUF * 2;
        #pragma unroll
        for (int it = 0; it < (BN * 8 + THREADS - 1) / THREADS; it++) {
            int slot = tid + it * THREADS;
            if (slot < BN * 8) {
                int row = slot >> 3, kk = slot & 7;
                const __half* sp = Bh_ + (size_t)row * K + kc + kk * 8;
                uint32_t dst = b0 + (uint32_t)(AHALF + row * SA + kk * 8) * 2;
                cp16(dst, sp, 16);
            }
        }
        CP_COMMIT();
    };

    const int nchunks = K / BK;
    ldgA(0);
    stsA(0, 0);
    cpB(0, 0);
    for (int c = 0; c < nchunks; c++) {
        const int buf = c & 1;
        const bool more = (c + 1 < nchunks);
        CP_WAIT0();
        __syncthreads();
        if (more) { ldgA(c + 1); cpB(c + 1, buf ^ 1); }
        const uint32_t b0 = su + buf * PERBUF * 2;
        const uint32_t cAh = b0;
        const uint32_t cBh = b0 + AHALF * 2;
        #pragma unroll
        for (int ks = 0; ks < 4; ks++) {
            const int kb = ks * 16;
            uint32_t ah[2][4];
            #pragma unroll
            for (int mt = 0; mt < 2; mt++) {
                int r = mw + mt * 16 + l8 + (g & 1) * 8;
                int col = kb + (g >> 1) * 8;
                ldsm4(ah[mt], cAh + (uint32_t)(r * SA + col) * 2);
            }
            uint32_t bh[NP][4];
            #pragma unroll
            for (int p = 0; p < NP; p++) {
                int r = nw + p * 16 + l8 + (g >> 1) * 8;
                int col = kb + (g & 1) * 8;
                ldsm4(bh[p], cBh + (uint32_t)(r * SA + col) * 2);
            }
            #pragma unroll
            for (int p = 0; p < NP; p++)
                #pragma unroll
                for (int sub = 0; sub < 2; sub++)
                    #pragma unroll
                    for (int mt = 0; mt < 2; mt++)
                        mma16816(acc[mt][p * 2 + sub], ah[mt],
                                 bh[p][2 * sub], bh[p][2 * sub + 1]);
        }
        if (more) stsA(buf ^ 1, (c + 1) * BK);
    }

    const int gid = lane >> 2, qid = lane & 3;
    #pragma unroll
    for (int mt = 0; mt < 2; mt++) {
        int r0 = m0 + mw + mt * 16 + gid;
        #pragma unroll
        for (int nt = 0; nt < NT; nt++) {
            int col = nw + nt * 8 + qid * 2;
            #pragma unroll
            for (int half = 0; half < 2; half++) {
                int r = r0 + half * 8;
                if (r >= M) continue;
                float v0 = acc[mt][nt][half * 2 + 0];
                float v1 = acc[mt][nt][half * 2 + 1];
                if (MODE == 0) {
                    *(__half2*)&C1h[(size_t)r * BN + col] = __floats2half2_rn(v0, v1);
                } else {
                    if (col < 128) {
                        *(__half2*)&C1h[(size_t)r * 128 + col] = __floats2half2_rn(v0, v1);
                    } else {
                        int c2 = col - 128;
                        v0 += bias[c2]; v1 += bias[c2 + 1];
                        *(float2*)&C2[(size_t)r * (BN - 128) + c2] = make_float2(v0, v1);
                    }
                }
            }
        }
    }
}

// ---------------- aggregation: unroll-8 gather, 4 nodes/warp, + BN stats ----------------
__global__ void k_agg128(const __half* __restrict__ h, float* __restrict__ out, int n) {
    __shared__ float s_sum[C1C], s_sq[C1C];
    int tid = threadIdx.x, lane = tid & 31, wid = tid >> 5;
    if (tid < C1C) { s_sum[tid] = 0.f; s_sq[tid] = 0.f; }
    __syncthreads();
    const uint2* hv = (const uint2*)h;
    float4 lsum = make_float4(0.f, 0.f, 0.f, 0.f);
    float4 lsq  = make_float4(0.f, 0.f, 0.f, 0.f);
    int base = (blockIdx.x * 8 + wid) * 4;
    #pragma unroll 1
    for (int g = 0; g < 4; g++) {
        int w = base + g;
        if (w >= n) break;
        float di = g_dinv[w];
        float s = di * di;
        uint2 raw = hv[(size_t)w * 32 + lane];
        __half2 p0 = *(__half2*)&raw.x;
        __half2 p1 = *(__half2*)&raw.y;
        float4 acc;
        acc.x = __low2float(p0) * s;  acc.y = __high2float(p0) * s;
        acc.z = __low2float(p1) * s;  acc.w = __high2float(p1) * s;
        int beg = g_rowptr[w], end = g_rowptr[w + 1];
        int e = beg;
        for (; e + 7 < end; e += 8) {
            int   si[8];
            float wi[8];
            #pragma unroll
            for (int q = 0; q < 8; q++) { si[q] = g_src[e + q]; wi[q] = g_norm[e + q]; }
            uint2 rr[8];
            #pragma unroll
            for (int q = 0; q < 8; q++) rr[q] = hv[(size_t)si[q] * 32 + lane];
            #pragma unroll
            for (int q = 0; q < 8; q++) {
                __half2 a0 = *(__half2*)&rr[q].x, b0 = *(__half2*)&rr[q].y;
                acc.x += wi[q] * __low2float(a0);  acc.y += wi[q] * __high2float(a0);
                acc.z += wi[q] * __low2float(b0);  acc.w += wi[q] * __high2float(b0);
            }
        }
        for (; e < end; e++) {
            int src = g_src[e];
            float wt = g_norm[e];
            uint2 r0 = hv[(size_t)src * 32 + lane];
            __half2 a0 = *(__half2*)&r0.x, b0 = *(__half2*)&r0.y;
            acc.x += wt * __low2float(a0);  acc.y += wt * __high2float(a0);
            acc.z += wt * __low2float(b0);  acc.w += wt * __high2float(b0);
        }
        ((float4*)out)[(size_t)w * 32 + lane] = acc;
        lsum.x += acc.x; lsum.y += acc.y; lsum.z += acc.z; lsum.w += acc.w;
        lsq.x += acc.x * acc.x; lsq.y += acc.y * acc.y;
        lsq.z += acc.z * acc.z; lsq.w += acc.w * acc.w;
    }
    int c = lane * 4;
    atomicAdd(&s_sum[c + 0], lsum.x); atomicAdd(&s_sum[c + 1], lsum.y);
    atomicAdd(&s_sum[c + 2], lsum.z); atomicAdd(&s_sum[c + 3], lsum.w);
    atomicAdd(&s_sq[c + 0], lsq.x);  atomicAdd(&s_sq[c + 1], lsq.y);
    atomicAdd(&s_sq[c + 2], lsq.z);  atomicAdd(&s_sq[c + 3], lsq.w);
    __syncthreads();
    if (tid < C1C) {
        atomicAdd(&g_bnsum[tid], s_sum[tid]);
        atomicAdd(&g_bnsq[tid], s_sq[tid]);
    }
}

__global__ void k_agg64(const __half* __restrict__ h, float* __restrict__ out, int n) {
    __shared__ float s_sum[C2C], s_sq[C2C];
    int tid = threadIdx.x, lane = tid & 31, wid = tid >> 5;
    if (tid < C2C) { s_sum[tid] = 0.f; s_sq[tid] = 0.f; }
    __syncthreads();
    const __half2* hv = (const __half2*)h;
    float2 lsum = make_float2(0.f, 0.f);
    float2 lsq  = make_float2(0.f, 0.f);
    int base = (blockIdx.x * 8 + wid) * 4;
    #pragma unroll 1
    for (int g = 0; g < 4; g++) {
        int w = base + g;
        if (w >= n) break;
        float di = g_dinv[w];
        float s = di * di;
        __half2 a = hv[(size_t)w * 32 + lane];
        float2 acc;
        acc.x = __low2float(a) * s; acc.y = __high2float(a) * s;
        int beg = g_rowptr[w], end = g_rowptr[w + 1];
        int e = beg;
        for (; e + 7 < end; e += 8) {
            int   si[8];
            float wi[8];
            #pragma unroll
            for (int q = 0; q < 8; q++) { si[q] = g_src[e + q]; wi[q] = g_norm[e + q]; }
            __half2 vv[8];
            #pragma unroll
            for (int q = 0; q < 8; q++) vv[q] = hv[(size_t)si[q] * 32 + lane];
            #pragma unroll
            for (int q = 0; q < 8; q++) {
                acc.x += wi[q] * __low2float(vv[q]);
                acc.y += wi[q] * __high2float(vv[q]);
            }
        }
        for (; e < end; e++) {
            int src = g_src[e];
            float wt = g_norm[e];
            __half2 v = hv[(size_t)src * 32 + lane];
            acc.x += wt * __low2float(v); acc.y += wt * __high2float(v);
        }
        ((float2*)out)[(size_t)w * 32 + lane] = acc;
        lsum.x += acc.x; lsum.y += acc.y;
        lsq.x += acc.x * acc.x; lsq.y += acc.y * acc.y;
    }
    int c = lane * 2;
    atomicAdd(&s_sum[c + 0], lsum.x); atomicAdd(&s_sum[c + 1], lsum.y);
    atomicAdd(&s_sq[c + 0], lsq.x);  atomicAdd(&s_sq[c + 1], lsq.y);
    __syncthreads();
    if (tid < C2C) {
        atomicAdd(&g_bnsum[C1C + tid], s_sum[tid]);
        atomicAdd(&g_bnsq[C1C + tid], s_sq[tid]);
    }
}

// ---------------- final BN2 + skip (float4) ----------------
__global__ void k_bn2(const float* __restrict__ a, float* __restrict__ o,
                      const float* __restrict__ gamma, const float* __restrict__ beta,
                      int n, const float* __restrict__ skip) {
    int i4 = blockIdx.x * blockDim.x + threadIdx.x;
    if (i4 >= n * C2C / 4) return;
    int c = (i4 * 4) & (C2C - 1);
    float inv_n = 1.0f / (float)n;
    float4 va = ((const float4*)a)[i4];
    float4 vs = ((const float4*)skip)[i4];
    float4 r;
    #pragma unroll
    for (int q = 0; q < 4; q++) {
        float mu = g_bnsum[C1C + c + q] * inv_n;
        float var = g_bnsq[C1C + c + q] * inv_n - mu * mu;
        float sc = gamma[c + q] * rsqrtf(var + 1e-5f);
        float sh = beta[c + q] - mu * sc;
        float av = (&va.x)[q];
        (&r.x)[q] = fmaf(av, sc, sh) + (&vs.x)[q];
    }
    ((float4*)o)[i4] = r;
}

// ---------------- launcher ----------------
extern "C" void kernel_launch(void* const* d_in, const int* in_sizes, int n_in,
                              void* d_out, int out_size) {
    const float* x   = (const float*)d_in[0];
    const int*   ei  = (const int*)d_in[1];
    const float* ew  = (const float*)d_in[2];
    const float* W1  = (const float*)d_in[3];
    const float* W2  = (const float*)d_in[5];
    const float* g1  = (const float*)d_in[7];
    const float* be1 = (const float*)d_in[8];
    const float* g2  = (const float*)d_in[9];
    const float* be2 = (const float*)d_in[10];
    const float* Ws  = (const float*)d_in[11];
    const float* bs  = (const float*)d_in[12];
    float* out = (float*)d_out;

    int E = in_sizes[2];
    int n = in_sizes[0] / CIN;
    const int* rowp = ei;
    const int* colp = ei + E;

    float *p_agg1, *p_skip, *p_agg2;
    cudaGetSymbolAddress((void**)&p_agg1, g_agg1);
    cudaGetSymbolAddress((void**)&p_skip, g_skip);
    cudaGetSymbolAddress((void**)&p_agg2, g_agg2);
    __half *p_h1f, *p_h2f, *p_wfh, *p_w2th;
    cudaGetSymbolAddress((void**)&p_h1f,  g_h1f);
    cudaGetSymbolAddress((void**)&p_h2f,  g_h2f);
    cudaGetSymbolAddress((void**)&p_wfh,  g_wfh);
    cudaGetSymbolAddress((void**)&p_w2th, g_w2th);

    // smem: 2 stages * (64 + BN) rows * 72 halves * 2B
    const int SMEMF = 2 * (64 + 192) * 72 * 2;  // 73728
    const int SMEM2 = 2 * (64 + 64) * 72 * 2;   // 36864
    cudaFuncSetAttribute((const void*)k_gemm_mma<192, 1, 1>,
                         cudaFuncAttributeMaxDynamicSharedMemorySize, SMEMF);
    cudaFuncSetAttribute((const void*)k_gemm_mma<64, 0, 2>,
                         cudaFuncAttributeMaxDynamicSharedMemorySize, SMEM2);

    int nb = (n + 255) / 256;
    int eb = (E + 255) / 256;
    int sblk = (n + 1023) / 1024;
    int mtiles = (n + 63) / 64;
    int aggb = (n + 31) / 32;   // 4 nodes per warp, 8 warps per block

    // Side stream + fork/join (created fresh per call; never destroyed).
    cudaStream_t sB;
    cudaStreamCreate(&sB);
    cudaEvent_t eFork, eJoin;
    cudaEventCreateWithFlags(&eFork, cudaEventDisableTiming);
    cudaEventCreateWithFlags(&eJoin, cudaEventDisableTiming);

    cudaEventRecord(eFork, 0);
    cudaStreamWaitEvent(sB, eFork, 0);

    // 1: main weight prep; 2-3: side CSR start
    k_split_wf<<<(192 * CIN + 255) / 256, 256>>>(W1, Ws, p_wfh);
    k_init<<<nb, 256, 0, sB>>>(n);
    k_hist<<<eb, 256, 0, sB>>>(colp, ew, E);

    // 4: fused GEMM1+skip (single-term fp16) — ncu capture slot
    k_gemm_mma<192, 1, 1><<<mtiles, 256, SMEMF>>>(x, p_wfh,
                                                  p_h1f, p_skip, bs,
                                                  nullptr, nullptr, n, CIN);

    // side: finish CSR + W2 prep (overlaps GEMM)
    k_scan_part<<<sblk, 1024, 0, sB>>>(n);
    k_scan_top<<<1, 64, 0, sB>>>(sblk, n);
    k_scan_add<<<sblk, 1024, 0, sB>>>(n);
    k_fill<<<eb, 256, 0, sB>>>(rowp, colp, ew, E);
    k_split_wt<<<(C1C * C2C + 255) / 256, 256, 0, sB>>>(W2, p_w2th, C1C, C2C);

    // join before aggregation
    cudaEventRecord(eJoin, sB);
    cudaStreamWaitEvent(0, eJoin, 0);

    // serial tail
    k_agg128<<<aggb, 256>>>(p_h1f, p_agg1, n);
    k_gemm_mma<64, 0, 2><<<mtiles, 256, SMEM2>>>(p_agg1, p_w2th,
                                                 p_h2f, nullptr, nullptr,
                                                 g1, be1, n, C1C);
    k_agg64<<<aggb, 256>>>(p_h2f, p_agg2, n);
    k_bn2<<<(n * C2C / 4 + 255) / 256, 256>>>(p_agg2, out, g2, be2, n, p_skip);

    (void)n_in; (void)out_size;
}

// round 16
// speedup vs baseline: 1.6682x; 1.0369x over previous
#include <cuda_runtime.h>
#include <cuda_fp16.h>
#include <math.h>
#include <stdint.h>

// ---------------- problem constants ----------------
#define NMAX 50000
#define EMAX 800000
#define CIN  256
#define C1C  128
#define C2C  64

// ---------------- device scratch ----------------
__device__ float g_deg[NMAX];
__device__ float g_dinv[NMAX];
__device__ int   g_cnt[NMAX];
__device__ int   g_fill[NMAX];
__device__ int   g_rowptr[NMAX + 1];
__device__ int   g_bsum[64];
__device__ int2  g_edge[EMAX];          // packed {src, norm-as-int}
__device__ float g_skip[NMAX * C2C];
__device__ float g_agg2[NMAX * C2C];
__device__ float g_bnsum[C1C + C2C];
__device__ float g_bnsq[C1C + C2C];

// fp16 intermediates
__device__ __align__(256) __half g_h1f[NMAX * C1C];
__device__ __align__(256) __half g_agg1h[NMAX * C1C];
__device__ __align__(256) __half g_h2f[NMAX * C2C];
// fp16 weights
__device__ __align__(256) __half g_wfh[192 * CIN];   // [W1^T ; Ws^T]
__device__ __align__(256) __half g_w2th[C2C * C1C];

__device__ __forceinline__ float gelu_f(float v) {
    return 0.5f * v * (1.0f + erff(v * 0.70710678118654752440f));
}

// ---------------- init ----------------
__global__ void k_init(int n) {
    int i = blockIdx.x * blockDim.x + threadIdx.x;
    if (i < n) { g_cnt[i] = 0; g_fill[i] = 0; g_deg[i] = 1.0f; }
    if (i < C1C + C2C) { g_bnsum[i] = 0.0f; g_bnsq[i] = 0.0f; }
}

// ---------------- histogram ----------------
__global__ void k_hist(const int* __restrict__ col, const float* __restrict__ ew, int e) {
    int i = blockIdx.x * blockDim.x + threadIdx.x;
    if (i < e) {
        int c = col[i];
        atomicAdd(&g_cnt[c], 1);
        atomicAdd(&g_deg[c], ew[i]);
    }
}

// ---------------- scan part (+ fused dinv) ----------------
__global__ void k_scan_part(int n) {
    __shared__ int warp_sums[32];
    int tid = threadIdx.x;
    int lane = tid & 31, wid = tid >> 5;
    int i = blockIdx.x * 1024 + tid;
    int v = (i < n) ? g_cnt[i] : 0;
    int x = v;
    #pragma unroll
    for (int o = 1; o < 32; o <<= 1) {
        int y = __shfl_up_sync(0xFFFFFFFFu, x, o);
        if (lane >= o) x += y;
    }
    if (lane == 31) warp_sums[wid] = x;
    __syncthreads();
    if (wid == 0) {
        int w = warp_sums[lane];
        #pragma unroll
        for (int o = 1; o < 32; o <<= 1) {
            int y = __shfl_up_sync(0xFFFFFFFFu, w, o);
            if (lane >= o) w += y;
        }
        warp_sums[lane] = w;
    }
    __syncthreads();
    int inc = x + (wid > 0 ? warp_sums[wid - 1] : 0);
    if (i < n) {
        g_rowptr[i] = inc - v;
        float d = g_deg[i];
        g_dinv[i] = (d > 0.0f) ? rsqrtf(d) : 0.0f;
    }
    if (tid == 1023) g_bsum[blockIdx.x] = inc;
}

__global__ void k_scan_top(int nblk, int n) {
    int tid = threadIdx.x;
    int lane = tid & 31, wid = tid >> 5;
    __shared__ int w0_total;
    int v = (tid < nblk) ? g_bsum[tid] : 0;
    int x = v;
    #pragma unroll
    for (int o = 1; o < 32; o <<= 1) {
        int y = __shfl_up_sync(0xFFFFFFFFu, x, o);
        if (lane >= o) x += y;
    }
    if (wid == 0 && lane == 31) w0_total = x;
    __syncthreads();
    int incl = x + (wid == 1 ? w0_total : 0);
    if (tid < nblk) g_bsum[tid] = incl - v;
    if (tid == nblk - 1) g_rowptr[n] = incl;
}

__global__ void k_scan_add(int n) {
    int i = blockIdx.x * 1024 + threadIdx.x;
    if (i < n) g_rowptr[i] += g_bsum[blockIdx.x];
}

// ---------------- fill CSR (packed edge) ----------------
__global__ void k_fill(const int* __restrict__ row, const int* __restrict__ col,
                       const float* __restrict__ ew, int e) {
    int i = blockIdx.x * blockDim.x + threadIdx.x;
    if (i < e) {
        int c = col[i], r = row[i];
        int pos = g_rowptr[c] + atomicAdd(&g_fill[c], 1);
        float nm = g_dinv[r] * ew[i] * g_dinv[c];
        g_edge[pos] = make_int2(r, __float_as_int(nm));
    }
}

// ---------------- fused W1+Ws transpose (fp16 rn) ----------------
__global__ void k_split_wf(const float* __restrict__ W1, const float* __restrict__ Ws,
                           __half* __restrict__ Th) {
    int i = blockIdx.x * blockDim.x + threadIdx.x;
    if (i >= 192 * CIN) return;
    int nn = i / CIN, k = i % CIN;
    float v = (nn < C1C) ? W1[(size_t)k * C1C + nn] : Ws[(size_t)k * C2C + (nn - C1C)];
    Th[i] = __float2half_rn(v);
}

// ---------------- transpose W2 (fp16 rn) ----------------
__global__ void k_split_wt(const float* __restrict__ W, __half* __restrict__ Th,
                           int K, int N) {
    int i = blockIdx.x * blockDim.x + threadIdx.x;
    if (i >= K * N) return;
    int k = i / N, nn = i % N;
    Th[(size_t)nn * K + k] = __float2half_rn(W[i]);
}

// ---------------- mma.sync GEMM, BK=64, single-term fp16 ----------------
__device__ __forceinline__ void ldsm4(uint32_t* r, uint32_t addr) {
    asm volatile("ldmatrix.sync.aligned.m8n8.x4.shared.b16 {%0,%1,%2,%3}, [%4];"
                 : "=r"(r[0]), "=r"(r[1]), "=r"(r[2]), "=r"(r[3]) : "r"(addr));
}
__device__ __forceinline__ void mma16816(float* d, const uint32_t* a,
                                         uint32_t b0, uint32_t b1) {
    asm volatile(
        "mma.sync.aligned.m16n8k16.row.col.f32.f16.f16.f32 "
        "{%0,%1,%2,%3}, {%4,%5,%6,%7}, {%8,%9}, {%0,%1,%2,%3};"
        : "+f"(d[0]), "+f"(d[1]), "+f"(d[2]), "+f"(d[3])
        : "r"(a[0]), "r"(a[1]), "r"(a[2]), "r"(a[3]), "r"(b0), "r"(b1));
}
__device__ __forceinline__ void cp16(uint32_t dst, const void* src, int srcsize) {
    asm volatile("cp.async.cg.shared.global [%0], [%1], 16, %2;"
                 :: "r"(dst), "l"(src), "r"(srcsize) : "memory");
}
#define CP_COMMIT() asm volatile("cp.async.commit_group;" ::: "memory")
#define CP_WAIT0()  asm volatile("cp.async.wait_group 0;" ::: "memory")

__device__ __forceinline__ uint32_t hpack(__half a, __half b) {
    return (uint32_t)__half_as_ushort(a) | ((uint32_t)__half_as_ushort(b) << 16);
}

// AFP 1: A fp32 [M,K], convert fp16-rn in-kernel.
// AFP 2: A fp16 [M,K] (agg1h); BN(g_bnsum/g_bnsq[0..K)) + GELU, then convert.
// MODE 0: all cols -> C1h fp16. MODE 1: col<128 -> C1h; col>=128 -> C2 fp32 +bias.
template<int BN, int MODE, int AFP>
__global__ __launch_bounds__(256) void k_gemm_mma(
    const void* __restrict__ Avoid,
    const __half* __restrict__ Bh_,
    __half* __restrict__ C1h, float* __restrict__ C2,
    const float* __restrict__ bias,
    const float* __restrict__ bnG, const float* __restrict__ bnB,
    int M, int K) {
    constexpr int BM = 64;
    constexpr int BK = 64;
    constexpr int SA = 72;
    constexpr int THREADS = 256;
    constexpr int WM = 2, WN = 4;
    constexpr int WNW = BN / WN;
    constexpr int NT = WNW / 8;
    constexpr int NP = NT / 2;
    constexpr int AHALF = BM * SA;
    constexpr int BHALF = BN * SA;
    constexpr int PERBUF = AHALF + BHALF;
    extern __shared__ __half smh[];
    const uint32_t su = (uint32_t)__cvta_generic_to_shared(smh);
    __shared__ float sS[C1C], sBsh[C1C];

    const float* Af  = (const float*)Avoid;
    const __half* A16 = (const __half*)Avoid;

    const int tid = threadIdx.x;
    const int w = tid >> 5, lane = tid & 31;
    const int mw = (w % WM) * 32;
    const int nw = (w / WM) * WNW;
    const int m0 = blockIdx.x * BM;
    const int g = lane >> 3, l8 = lane & 7;

    if (AFP == 2) {
        if (tid < K) {
            float inv = 1.0f / (float)M;
            float mu = g_bnsum[tid] * inv;
            float var = g_bnsq[tid] * inv - mu * mu;
            float sc = bnG[tid] * rsqrtf(var + 1e-5f);
            sS[tid] = sc;
            sBsh[tid] = bnB[tid] - mu * sc;
        }
        __syncthreads();
    }

    float acc[2][NT][4];
    #pragma unroll
    for (int i = 0; i < 2; i++)
        #pragma unroll
        for (int j = 0; j < NT; j++)
            #pragma unroll
            for (int q = 0; q < 4; q++) acc[i][j][q] = 0.0f;

    // A staging: 64 rows x 8 k-groups (8 elems) = 512 slots, 2 per thread.
    float4 ra[2][2];   // AFP==1
    uint4  rh[2];      // AFP==2
    auto ldgA = [&](int chunk) {
        #pragma unroll
        for (int it = 0; it < 2; it++) {
            int slot = tid + it * 256;
            int row = slot >> 3;
            int kk = (slot & 7) * 8;
            int gm = m0 + row;
            if (AFP == 1) {
                const float* s = Af + (size_t)(gm < M ? gm : 0) * K + chunk * BK + kk;
                ra[it][0] = *(const float4*)s;
                ra[it][1] = *(const float4*)(s + 4);
            } else {
                const __half* s = A16 + (size_t)(gm < M ? gm : 0) * K + chunk * BK + kk;
                rh[it] = *(const uint4*)s;
            }
        }
    };
    auto stsA = [&](int buf, int kc) {
        #pragma unroll
        for (int it = 0; it < 2; it++) {
            int slot = tid + it * 256;
            int row = slot >> 3;
            int kk = (slot & 7) * 8;
            float v[8];
            if (AFP == 1) {
                v[0] = ra[it][0].x; v[1] = ra[it][0].y; v[2] = ra[it][0].z; v[3] = ra[it][0].w;
                v[4] = ra[it][1].x; v[5] = ra[it][1].y; v[6] = ra[it][1].z; v[7] = ra[it][1].w;
            } else {
                const uint32_t* u = &rh[it].x;
                #pragma unroll
                for (int p = 0; p < 4; p++) {
                    __half2 hp = *(__half2*)&u[p];
                    v[2 * p]     = __low2float(hp);
                    v[2 * p + 1] = __high2float(hp);
                }
                #pragma unroll
                for (int i = 0; i < 8; i++) {
                    int kcol = kc + kk + i;
                    v[i] = gelu_f(fmaf(v[i], sS[kcol], sBsh[kcol]));
                }
            }
            __half hh[8];
            #pragma unroll
            for (int i = 0; i < 8; i++) hh[i] = __float2half_rn(v[i]);
            uint4 uh;
            uh.x = hpack(hh[0], hh[1]); uh.y = hpack(hh[2], hh[3]);
            uh.z = hpack(hh[4], hh[5]); uh.w = hpack(hh[6], hh[7]);
            *(uint4*)(smh + buf * PERBUF + row * SA + kk) = uh;
        }
    };
    auto cpB = [&](int chunk, int buf) {
        const int kc = chunk * BK;
        const uint32_t b0 = su + buf * PERBUF * 2;
        #pragma unroll
        for (int it = 0; it < (BN * 8 + THREADS - 1) / THREADS; it++) {
            int slot = tid + it * THREADS;
            if (slot < BN * 8) {
                int row = slot >> 3, kk = slot & 7;
                const __half* sp = Bh_ + (size_t)row * K + kc + kk * 8;
                uint32_t dst = b0 + (uint32_t)(AHALF + row * SA + kk * 8) * 2;
                cp16(dst, sp, 16);
            }
        }
        CP_COMMIT();
    };

    const int nchunks = K / BK;
    ldgA(0);
    stsA(0, 0);
    cpB(0, 0);
    for (int c = 0; c < nchunks; c++) {
        const int buf = c & 1;
        const bool more = (c + 1 < nchunks);
        CP_WAIT0();
        __syncthreads();
        if (more) { ldgA(c + 1); cpB(c + 1, buf ^ 1); }
        const uint32_t b0 = su + buf * PERBUF * 2;
        const uint32_t cAh = b0;
        const uint32_t cBh = b0 + AHALF * 2;
        #pragma unroll
        for (int ks = 0; ks < 4; ks++) {
            const int kb = ks * 16;
            uint32_t ah[2][4];
            #pragma unroll
            for (int mt = 0; mt < 2; mt++) {
                int r = mw + mt * 16 + l8 + (g & 1) * 8;
                int col = kb + (g >> 1) * 8;
                ldsm4(ah[mt], cAh + (uint32_t)(r * SA + col) * 2);
            }
            uint32_t bh[NP][4];
            #pragma unroll
            for (int p = 0; p < NP; p++) {
                int r = nw + p * 16 + l8 + (g >> 1) * 8;
                int col = kb + (g & 1) * 8;
                ldsm4(bh[p], cBh + (uint32_t)(r * SA + col) * 2);
            }
            #pragma unroll
            for (int p = 0; p < NP; p++)
                #pragma unroll
                for (int sub = 0; sub < 2; sub++)
                    #pragma unroll
                    for (int mt = 0; mt < 2; mt++)
                        mma16816(acc[mt][p * 2 + sub], ah[mt],
                                 bh[p][2 * sub], bh[p][2 * sub + 1]);
        }
        if (more) stsA(buf ^ 1, (c + 1) * BK);
    }

    const int gid = lane >> 2, qid = lane & 3;
    #pragma unroll
    for (int mt = 0; mt < 2; mt++) {
        int r0 = m0 + mw + mt * 16 + gid;
        #pragma unroll
        for (int nt = 0; nt < NT; nt++) {
            int col = nw + nt * 8 + qid * 2;
            #pragma unroll
            for (int half = 0; half < 2; half++) {
                int r = r0 + half * 8;
                if (r >= M) continue;
                float v0 = acc[mt][nt][half * 2 + 0];
                float v1 = acc[mt][nt][half * 2 + 1];
                if (MODE == 0) {
                    *(__half2*)&C1h[(size_t)r * BN + col] = __floats2half2_rn(v0, v1);
                } else {
                    if (col < 128) {
                        *(__half2*)&C1h[(size_t)r * 128 + col] = __floats2half2_rn(v0, v1);
                    } else {
                        int c2 = col - 128;
                        v0 += bias[c2]; v1 += bias[c2 + 1];
                        *(float2*)&C2[(size_t)r * (BN - 128) + c2] = make_float2(v0, v1);
                    }
                }
            }
        }
    }
}

// ---------------- aggregation: packed edges, shfl indices, 4 nodes/warp ----------------
// agg128: gathers fp16 h1f, accumulates fp32, writes agg1 as fp16 + fp32 BN stats.
__global__ void k_agg128(const __half* __restrict__ h, __half* __restrict__ outh, int n) {
    __shared__ float s_sum[C1C], s_sq[C1C];
    int tid = threadIdx.x, lane = tid & 31, wid = tid >> 5;
    if (tid < C1C) { s_sum[tid] = 0.f; s_sq[tid] = 0.f; }
    __syncthreads();
    const uint2* hv = (const uint2*)h;
    float4 lsum = make_float4(0.f, 0.f, 0.f, 0.f);
    float4 lsq  = make_float4(0.f, 0.f, 0.f, 0.f);
    int base = (blockIdx.x * 8 + wid) * 4;
    #pragma unroll 1
    for (int g = 0; g < 4; g++) {
        int w = base + g;
        if (w >= n) break;
        float di = g_dinv[w];
        float s = di * di;
        uint2 raw = hv[(size_t)w * 32 + lane];
        __half2 p0 = *(__half2*)&raw.x;
        __half2 p1 = *(__half2*)&raw.y;
        float4 acc;
        acc.x = __low2float(p0) * s;  acc.y = __high2float(p0) * s;
        acc.z = __low2float(p1) * s;  acc.w = __high2float(p1) * s;
        int beg = g_rowptr[w], end = g_rowptr[w + 1];
        int e = beg;
        for (; e + 7 < end; e += 8) {
            int2 ed = g_edge[e + (lane & 7)];   // one 64B segment, lanes 8-31 replay
            uint2 rr[8];
            float wi[8];
            #pragma unroll
            for (int q = 0; q < 8; q++) {
                int   sq = __shfl_sync(0xFFFFFFFFu, ed.x, q);
                int   wq = __shfl_sync(0xFFFFFFFFu, ed.y, q);
                wi[q] = __int_as_float(wq);
                rr[q] = hv[(size_t)sq * 32 + lane];
            }
            #pragma unroll
            for (int q = 0; q < 8; q++) {
                __half2 a0 = *(__half2*)&rr[q].x, b0 = *(__half2*)&rr[q].y;
                acc.x += wi[q] * __low2float(a0);  acc.y += wi[q] * __high2float(a0);
                acc.z += wi[q] * __low2float(b0);  acc.w += wi[q] * __high2float(b0);
            }
        }
        for (; e < end; e++) {
            int2 ed = g_edge[e];
            float wt = __int_as_float(ed.y);
            uint2 r0 = hv[(size_t)ed.x * 32 + lane];
            __half2 a0 = *(__half2*)&r0.x, b0 = *(__half2*)&r0.y;
            acc.x += wt * __low2float(a0);  acc.y += wt * __high2float(a0);
            acc.z += wt * __low2float(b0);  acc.w += wt * __high2float(b0);
        }
        uint2 packed;
        *(__half2*)&packed.x = __floats2half2_rn(acc.x, acc.y);
        *(__half2*)&packed.y = __floats2half2_rn(acc.z, acc.w);
        ((uint2*)outh)[(size_t)w * 32 + lane] = packed;
        lsum.x += acc.x; lsum.y += acc.y; lsum.z += acc.z; lsum.w += acc.w;
        lsq.x += acc.x * acc.x; lsq.y += acc.y * acc.y;
        lsq.z += acc.z * acc.z; lsq.w += acc.w * acc.w;
    }
    int c = lane * 4;
    atomicAdd(&s_sum[c + 0], lsum.x); atomicAdd(&s_sum[c + 1], lsum.y);
    atomicAdd(&s_sum[c + 2], lsum.z); atomicAdd(&s_sum[c + 3], lsum.w);
    atomicAdd(&s_sq[c + 0], lsq.x);  atomicAdd(&s_sq[c + 1], lsq.y);
    atomicAdd(&s_sq[c + 2], lsq.z);  atomicAdd(&s_sq[c + 3], lsq.w);
    __syncthreads();
    if (tid < C1C) {
        atomicAdd(&g_bnsum[tid], s_sum[tid]);
        atomicAdd(&g_bnsq[tid], s_sq[tid]);
    }
}

__global__ void k_agg64(const __half* __restrict__ h, float* __restrict__ out, int n) {
    __shared__ float s_sum[C2C], s_sq[C2C];
    int tid = threadIdx.x, lane = tid & 31, wid = tid >> 5;
    if (tid < C2C) { s_sum[tid] = 0.f; s_sq[tid] = 0.f; }
    __syncthreads();
    const __half2* hv = (const __half2*)h;
    float2 lsum = make_float2(0.f, 0.f);
    float2 lsq  = make_float2(0.f, 0.f);
    int base = (blockIdx.x * 8 + wid) * 4;
    #pragma unroll 1
    for (int g = 0; g < 4; g++) {
        int w = base + g;
        if (w >= n) break;
        float di = g_dinv[w];
        float s = di * di;
        __half2 a = hv[(size_t)w * 32 + lane];
        float2 acc;
        acc.x = __low2float(a) * s; acc.y = __high2float(a) * s;
        int beg = g_rowptr[w], end = g_rowptr[w + 1];
        int e = beg;
        for (; e + 7 < end; e += 8) {
            int2 ed = g_edge[e + (lane & 7)];
            __half2 vv[8];
            float wi[8];
            #pragma unroll
            for (int q = 0; q < 8; q++) {
                int sq = __shfl_sync(0xFFFFFFFFu, ed.x, q);
                int wq = __shfl_sync(0xFFFFFFFFu, ed.y, q);
                wi[q] = __int_as_float(wq);
                vv[q] = hv[(size_t)sq * 32 + lane];
            }
            #pragma unroll
            for (int q = 0; q < 8; q++) {
                acc.x += wi[q] * __low2float(vv[q]);
                acc.y += wi[q] * __high2float(vv[q]);
            }
        }
        for (; e < end; e++) {
            int2 ed = g_edge[e];
            float wt = __int_as_float(ed.y);
            __half2 v = hv[(size_t)ed.x * 32 + lane];
            acc.x += wt * __low2float(v); acc.y += wt * __high2float(v);
        }
        ((float2*)out)[(size_t)w * 32 + lane] = acc;
        lsum.x += acc.x; lsum.y += acc.y;
        lsq.x += acc.x * acc.x; lsq.y += acc.y * acc.y;
    }
    int c = lane * 2;
    atomicAdd(&s_sum[c + 0], lsum.x); atomicAdd(&s_sum[c + 1], lsum.y);
    atomicAdd(&s_sq[c + 0], lsq.x);  atomicAdd(&s_sq[c + 1], lsq.y);
    __syncthreads();
    if (tid < C2C) {
        atomicAdd(&g_bnsum[C1C + tid], s_sum[tid]);
        atomicAdd(&g_bnsq[C1C + tid], s_sq[tid]);
    }
}

// ---------------- final BN2 + skip (float4) ----------------
__global__ void k_bn2(const float* __restrict__ a, float* __restrict__ o,
                      const float* __restrict__ gamma, const float* __restrict__ beta,
                      int n, const float* __restrict__ skip) {
    int i4 = blockIdx.x * blockDim.x + threadIdx.x;
    if (i4 >= n * C2C / 4) return;
    int c = (i4 * 4) & (C2C - 1);
    float inv_n = 1.0f / (float)n;
    float4 va = ((const float4*)a)[i4];
    float4 vs = ((const float4*)skip)[i4];
    float4 r;
    #pragma unroll
    for (int q = 0; q < 4; q++) {
        float mu = g_bnsum[C1C + c + q] * inv_n;
        float var = g_bnsq[C1C + c + q] * inv_n - mu * mu;
        float sc = gamma[c + q] * rsqrtf(var + 1e-5f);
        float sh = beta[c + q] - mu * sc;
        (&r.x)[q] = fmaf((&va.x)[q], sc, sh) + (&vs.x)[q];
    }
    ((float4*)o)[i4] = r;
}

// ---------------- launcher ----------------
extern "C" void kernel_launch(void* const* d_in, const int* in_sizes, int n_in,
                              void* d_out, int out_size) {
    const float* x   = (const float*)d_in[0];
    const int*   ei  = (const int*)d_in[1];
    const float* ew  = (const float*)d_in[2];
    const float* W1  = (const float*)d_in[3];
    const float* W2  = (const float*)d_in[5];
    const float* g1  = (const float*)d_in[7];
    const float* be1 = (const float*)d_in[8];
    const float* g2  = (const float*)d_in[9];
    const float* be2 = (const float*)d_in[10];
    const float* Ws  = (const float*)d_in[11];
    const float* bs  = (const float*)d_in[12];
    float* out = (float*)d_out;

    int E = in_sizes[2];
    int n = in_sizes[0] / CIN;
    const int* rowp = ei;
    const int* colp = ei + E;

    float *p_skip, *p_agg2;
    cudaGetSymbolAddress((void**)&p_skip, g_skip);
    cudaGetSymbolAddress((void**)&p_agg2, g_agg2);
    __half *p_h1f, *p_agg1h, *p_h2f, *p_wfh, *p_w2th;
    cudaGetSymbolAddress((void**)&p_h1f,   g_h1f);
    cudaGetSymbolAddress((void**)&p_agg1h, g_agg1h);
    cudaGetSymbolAddress((void**)&p_h2f,   g_h2f);
    cudaGetSymbolAddress((void**)&p_wfh,   g_wfh);
    cudaGetSymbolAddress((void**)&p_w2th,  g_w2th);

    const int SMEMF = 2 * (64 + 192) * 72 * 2;  // 73728
    const int SMEM2 = 2 * (64 + 64) * 72 * 2;   // 36864
    cudaFuncSetAttribute((const void*)k_gemm_mma<192, 1, 1>,
                         cudaFuncAttributeMaxDynamicSharedMemorySize, SMEMF);
    cudaFuncSetAttribute((const void*)k_gemm_mma<64, 0, 2>,
                         cudaFuncAttributeMaxDynamicSharedMemorySize, SMEM2);

    int nb = (n + 255) / 256;
    int eb = (E + 255) / 256;
    int sblk = (n + 1023) / 1024;
    int mtiles = (n + 63) / 64;
    int aggb = (n + 31) / 32;   // 4 nodes/warp, 8 warps/block

    // Side stream + fork/join (created fresh per call; never destroyed).
    cudaStream_t sB;
    cudaStreamCreate(&sB);
    cudaEvent_t eFork, eJoin;
    cudaEventCreateWithFlags(&eFork, cudaEventDisableTiming);
    cudaEventCreateWithFlags(&eJoin, cudaEventDisableTiming);

    cudaEventRecord(eFork, 0);
    cudaStreamWaitEvent(sB, eFork, 0);

    // 1: main weight prep; 2-3: side CSR start
    k_split_wf<<<(192 * CIN + 255) / 256, 256>>>(W1, Ws, p_wfh);
    k_init<<<nb, 256, 0, sB>>>(n);
    k_hist<<<eb, 256, 0, sB>>>(colp, ew, E);

    // 4: fused GEMM1+skip — ncu capture slot
    k_gemm_mma<192, 1, 1><<<mtiles, 256, SMEMF>>>(x, p_wfh,
                                                  p_h1f, p_skip, bs,
                                                  nullptr, nullptr, n, CIN);

    // side: finish CSR + W2 prep (overlaps GEMM)
    k_scan_part<<<sblk, 1024, 0, sB>>>(n);
    k_scan_top<<<1, 64, 0, sB>>>(sblk, n);
    k_scan_add<<<sblk, 1024, 0, sB>>>(n);
    k_fill<<<eb, 256, 0, sB>>>(rowp, colp, ew, E);
    k_split_wt<<<(C1C * C2C + 255) / 256, 256, 0, sB>>>(W2, p_w2th, C1C, C2C);

    // join before aggregation
    cudaEventRecord(eJoin, sB);
    cudaStreamWaitEvent(0, eJoin, 0);

    // serial tail
    k_agg128<<<aggb, 256>>>(p_h1f, p_agg1h, n);
    k_gemm_mma<64, 0, 2><<<mtiles, 256, SMEM2>>>(p_agg1h, p_w2th,
                                                 p_h2f, nullptr, nullptr,
                                                 g1, be1, n, C1C);
    k_agg64<<<aggb, 256>>>(p_h2f, p_agg2, n);
    k_bn2<<<(n * C2C / 4 + 255) / 256, 256>>>(p_agg2, out, g2, be2, n, p_skip);

    (void)n_in; (void)out_size;
}